// round 1
// baseline (speedup 1.0000x reference)
#include <cuda_runtime.h>
#include <math.h>

// Shapes (fixed by the problem)
#define B 64
#define L 128
#define D 200
#define MP 20
#define ATT 50
#define OUTC 83   // 21 + 20 + 21 + 21

// ---------------------------------------------------------------------------
// Scratch (device globals; no allocations allowed)
// ---------------------------------------------------------------------------
__device__ float g_e_lt[B * L * ATT];   // tanh(lt @ w2)               [b,l,a]
__device__ float g_e_rt[B * L * ATT];   // tanh(rt @ w1) * diag        [b,r,a]
__device__ float g_nl[B * L];           // sqrt(max(|lt_l|^2, EPS))    [b,l]

// ---------------------------------------------------------------------------
// Kernel 1: attention projections + lt row norms
// grid (L, B), 128 threads
// ---------------------------------------------------------------------------
__global__ __launch_bounds__(128) void k_proj(
    const float* __restrict__ lt, const float* __restrict__ rt,
    const float* __restrict__ w1, const float* __restrict__ w2,
    const float* __restrict__ diag)
{
    const int i = blockIdx.x, b = blockIdx.y;
    const int t = threadIdx.x;
    __shared__ float s_lt[D], s_rt[D], s_red[4];

    const float* ltrow = lt + ((size_t)b * L + i) * D;
    const float* rtrow = rt + ((size_t)b * L + i) * D;
    for (int d = t; d < D; d += 128) { s_lt[d] = ltrow[d]; s_rt[d] = rtrow[d]; }
    __syncthreads();

    // norm of lt row
    float ps = 0.f;
    for (int d = t; d < D; d += 128) ps = fmaf(s_lt[d], s_lt[d], ps);
    #pragma unroll
    for (int o = 16; o > 0; o >>= 1) ps += __shfl_xor_sync(0xffffffffu, ps, o);
    if ((t & 31) == 0) s_red[t >> 5] = ps;
    __syncthreads();
    if (t == 0) {
        float s = s_red[0] + s_red[1] + s_red[2] + s_red[3];
        g_nl[b * L + i] = sqrtf(fmaxf(s, 1e-6f));
    }

    if (t < ATT) {
        float acc = 0.f;
        #pragma unroll 8
        for (int d = 0; d < D; d++) acc = fmaf(s_lt[d], w2[d * ATT + t], acc);
        g_e_lt[((size_t)b * L + i) * ATT + t] = tanhf(acc);
    } else if (t >= 64 && t < 64 + ATT) {
        const int a = t - 64;
        float acc = 0.f;
        #pragma unroll 8
        for (int d = 0; d < D; d++) acc = fmaf(s_rt[d], w1[d * ATT + a], acc);
        g_e_rt[((size_t)b * L + i) * ATT + a] = tanhf(acc) * diag[a];
    }
}

// ---------------------------------------------------------------------------
// Kernel 2: maxpool match.  out[b,l,21+m] = tanh(max_k sum_d lt[l,d] w[m,d] rt[k,d])
// One block per (m, b): 128x128 GEMM tile, K = 200, fp32 packed FFMA2.
// A-tile (lt*w_m) stored duplicated ((v,v) pairs) -> broadcast LDS.128 reads.
// B-tile columns assigned strided (col = 32j + 2tx + e) -> conflict-free LDS.64.
// Column order is irrelevant because we reduce max over k.
// ---------------------------------------------------------------------------
__global__ __launch_bounds__(256, 2) void k_maxpool(
    const float* __restrict__ lt, const float* __restrict__ rt,
    const float* __restrict__ wmp, float* __restrict__ out)
{
    const int m = blockIdx.x;   // 0..19
    const int b = blockIdx.y;   // 0..63

    __shared__ float Asd[2][8][260];   // duplicated A rows (256 used + pad)
    __shared__ float Bs[2][8][132];    // B rows (128 used + pad)
    __shared__ float red[128][17];

    const float* ltb = lt + (size_t)b * L * D;
    const float* rtb = rt + (size_t)b * L * D;
    const float* wr  = wmp + m * D;

    const int tid = threadIdx.x;
    const int ty = tid >> 4;          // 0..15 (row group)
    const int tx = tid & 15;          // 0..15 (col group)
    const int lr = tid >> 1;          // load row 0..127
    const int lc = (tid & 1) * 4;     // load col 0 or 4

    unsigned long long acc[8][4];
    #pragma unroll
    for (int i = 0; i < 8; i++)
        #pragma unroll
        for (int j = 0; j < 4; j++) acc[i][j] = 0ull;

    float4 ra, rb;   // staged global loads
    float  w0, w1v, w2v, w3v;

    auto ld_regs = [&](int k0) {
        ra = *reinterpret_cast<const float4*>(ltb + lr * D + k0 + lc);
        rb = *reinterpret_cast<const float4*>(rtb + lr * D + k0 + lc);
        w0 = wr[k0 + lc + 0]; w1v = wr[k0 + lc + 1];
        w2v = wr[k0 + lc + 2]; w3v = wr[k0 + lc + 3];
    };
    auto st_smem = [&](int bf) {
        float ax = ra.x * w0, ay = ra.y * w1v, az = ra.z * w2v, aw = ra.w * w3v;
        *reinterpret_cast<float2*>(&Asd[bf][lc + 0][2 * lr]) = make_float2(ax, ax);
        *reinterpret_cast<float2*>(&Asd[bf][lc + 1][2 * lr]) = make_float2(ay, ay);
        *reinterpret_cast<float2*>(&Asd[bf][lc + 2][2 * lr]) = make_float2(az, az);
        *reinterpret_cast<float2*>(&Asd[bf][lc + 3][2 * lr]) = make_float2(aw, aw);
        Bs[bf][lc + 0][lr] = rb.x; Bs[bf][lc + 1][lr] = rb.y;
        Bs[bf][lc + 2][lr] = rb.z; Bs[bf][lc + 3][lr] = rb.w;
    };
    auto compute = [&](int bf) {
        #pragma unroll
        for (int kk = 0; kk < 8; kk++) {
            unsigned long long a2[8], b2[4];
            #pragma unroll
            for (int q = 0; q < 4; q++) {
                ulonglong2 v = *reinterpret_cast<const ulonglong2*>(
                    &Asd[bf][kk][2 * (ty * 8 + 2 * q)]);
                a2[2 * q] = v.x; a2[2 * q + 1] = v.y;
            }
            #pragma unroll
            for (int j = 0; j < 4; j++)
                b2[j] = *reinterpret_cast<const unsigned long long*>(
                    &Bs[bf][kk][32 * j + 2 * tx]);
            #pragma unroll
            for (int i = 0; i < 8; i++)
                #pragma unroll
                for (int j = 0; j < 4; j++)
                    asm("fma.rn.f32x2 %0, %1, %2, %0;"
                        : "+l"(acc[i][j]) : "l"(a2[i]), "l"(b2[j]));
        }
    };

    ld_regs(0);
    st_smem(0);
    __syncthreads();

    #pragma unroll 1
    for (int kt = 1; kt < 25; kt++) {      // 25 K-tiles of 8 (K = 200)
        ld_regs(kt * 8);
        compute((kt - 1) & 1);
        st_smem(kt & 1);
        __syncthreads();
    }
    compute(0);   // tile 24 lives in buffer 24&1 == 0

    // epilogue: per-thread max over its 8 k-columns per row, reduce over tx
    float rmax[8];
    #pragma unroll
    for (int i = 0; i < 8; i++) {
        float mx = -3.4e38f;
        #pragma unroll
        for (int j = 0; j < 4; j++) {
            unsigned long long v = acc[i][j];
            float lo = __uint_as_float((unsigned)(v & 0xffffffffull));
            float hi = __uint_as_float((unsigned)(v >> 32));
            mx = fmaxf(mx, fmaxf(lo, hi));
        }
        rmax[i] = mx;
    }
    __syncthreads();
    #pragma unroll
    for (int i = 0; i < 8; i++) red[ty * 8 + i][tx] = rmax[i];
    __syncthreads();
    if (tid < 128) {
        float v = red[tid][0];
        #pragma unroll
        for (int x = 1; x < 16; x++) v = fmaxf(v, red[tid][x]);
        out[((size_t)(b * L + tid)) * OUTC + 21 + m] = tanhf(v);
    }
}

// ---------------------------------------------------------------------------
// Kernel 3: per-(b,row) fused full + attentive + max-attentive match.
// grid (L, B), 256 threads.
// ---------------------------------------------------------------------------
__global__ __launch_bounds__(256) void k_rows(
    const float* __restrict__ lt, const float* __restrict__ rt,
    const float* __restrict__ fw, const float* __restrict__ bw,
    const float* __restrict__ w_full, const float* __restrict__ w_att,
    const float* __restrict__ w_maxatt, float* __restrict__ out)
{
    const int i = blockIdx.x, b = blockIdx.y;
    const int t = threadIdx.x;
    const int row = b * L + i;
    const int w = t >> 5, lane = t & 31;

    __shared__ float s_rt[D], s_lti[D], s_h[D], s_att[D], s_gat[D];
    __shared__ float s_ert[ATT];
    __shared__ float s_elt[L * ATT];     // 25.6 KB
    __shared__ float s_tile[16][D];      // 12.8 KB streaming lt tile
    __shared__ float s_nl[L];
    __shared__ float s_z[L], s_p[L], s_rel[L];
    __shared__ float s_red[8];
    __shared__ int   s_ired[8];
    __shared__ int   s_pos;
    __shared__ float s_scal;

    const float* ltb = lt + (size_t)b * L * D;
    float* outrow = out + (size_t)row * OUTC;

    // ---- cooperative loads ----
    for (int d = t; d < D; d += 256) {
        s_lti[d] = lt[(size_t)row * D + d];
        s_rt[d]  = rt[(size_t)row * D + d];
        s_h[d]   = (d < 100) ? fw[b * 100 + d] : bw[b * 100 + d - 100];
    }
    if (t < ATT) s_ert[t] = g_e_rt[(size_t)row * ATT + t];
    for (int idx = t; idx < L * ATT; idx += 256) s_elt[idx] = g_e_lt[(size_t)b * L * ATT + idx];
    if (t < L) s_nl[t] = g_nl[b * L + t];
    __syncthreads();

    // ---- full match: cols 0..20 (uses lt row i and h) ----
    if (w < 7) {
        #pragma unroll
        for (int q = 0; q < 3; q++) {
            const int idx = w * 3 + q;
            float acc = 0.f;
            if (idx == 0) {
                for (int d = lane; d < D; d += 32) acc = fmaf(s_lti[d], s_h[d], acc);
            } else {
                const float* wr = w_full + (idx - 1) * D;
                for (int d = lane; d < D; d += 32) acc = fmaf(s_lti[d] * wr[d], s_h[d], acc);
            }
            #pragma unroll
            for (int o = 16; o > 0; o >>= 1) acc += __shfl_xor_sync(0xffffffffu, acc, o);
            if (lane == 0) outrow[idx] = tanhf(acc);
        }
    }

    // ---- attention logits z[l] = e_rt_i . e_lt[l] ----
    if (t < L) {
        float acc = 0.f;
        const float* e = &s_elt[t * ATT];
        #pragma unroll 10
        for (int a = 0; a < ATT; a++) acc = fmaf(s_ert[a], e[a], acc);
        s_z[t] = acc;
    }
    __syncthreads();

    // ---- softmax over l (first 128 lanes carry data) ----
    float z = (t < L) ? s_z[t] : -3.4e38f;
    float zm = z;
    #pragma unroll
    for (int o = 16; o > 0; o >>= 1) zm = fmaxf(zm, __shfl_xor_sync(0xffffffffu, zm, o));
    if (lane == 0) s_red[w] = zm;
    __syncthreads();
    zm = s_red[0];
    #pragma unroll
    for (int q = 1; q < 8; q++) zm = fmaxf(zm, s_red[q]);
    float p = (t < L) ? expf(z - zm) : 0.f;
    float sm = p;
    #pragma unroll
    for (int o = 16; o > 0; o >>= 1) sm += __shfl_xor_sync(0xffffffffu, sm, o);
    if (lane == 0) s_red[w] = sm;
    __syncthreads();
    if (t == 0) {
        float tot = 0.f;
        #pragma unroll
        for (int q = 0; q < 8; q++) tot += s_red[q];
        s_scal = 1.0f / tot;
    }
    __syncthreads();
    if (t < L) s_p[t] = p * s_scal;

    // ---- stream lt tiles: cosine dots (max-attentive) + attn-weighted sum ----
    float acc_att = 0.f;   // valid for t < 200 (dim t)
    for (int T = 0; T < 8; T++) {
        const int l0 = T * 16;
        __syncthreads();   // protect s_tile (and ensure s_p visible at T=0)
        for (int idx = t; idx < 16 * D; idx += 256) {
            const int r = idx / D, d = idx - r * D;
            s_tile[r][d] = ltb[(size_t)(l0 + r) * D + d];
        }
        __syncthreads();
        // dots: 8 warps x 2 rows
        #pragma unroll
        for (int q = 0; q < 2; q++) {
            const int r = w * 2 + q;
            float a = 0.f;
            for (int d = lane; d < D; d += 32) a = fmaf(s_rt[d], s_tile[r][d], a);
            #pragma unroll
            for (int o = 16; o > 0; o >>= 1) a += __shfl_xor_sync(0xffffffffu, a, o);
            if (lane == 0) s_rel[l0 + r] = a / s_nl[l0 + r];
        }
        // attn-weighted accumulation over these 16 rows
        if (t < D) {
            #pragma unroll
            for (int r = 0; r < 16; r++) acc_att = fmaf(s_p[l0 + r], s_tile[r][t], acc_att);
        }
    }
    if (t < D) s_att[t] = acc_att;
    __syncthreads();

    // ---- argmax over rel (first-index tie-break, like jnp.argmax) ----
    if (t < L) {
        float v = s_rel[t]; int idx = t;
        #pragma unroll
        for (int o = 16; o > 0; o >>= 1) {
            float ov = __shfl_xor_sync(0xffffffffu, v, o);
            int   oi = __shfl_xor_sync(0xffffffffu, idx, o);
            if (ov > v || (ov == v && oi < idx)) { v = ov; idx = oi; }
        }
        if (lane == 0) { s_red[w] = v; s_ired[w] = idx; }
    }
    __syncthreads();
    if (t == 0) {
        float v = s_red[0]; int idx = s_ired[0];
        #pragma unroll
        for (int q = 1; q < 4; q++)
            if (s_red[q] > v || (s_red[q] == v && s_ired[q] < idx)) { v = s_red[q]; idx = s_ired[q]; }
        s_pos = idx;
    }
    __syncthreads();
    for (int d = t; d < D; d += 256) s_gat[d] = ltb[(size_t)s_pos * D + d];
    __syncthreads();

    // ---- attentive mp (cols 41..61) and max-attentive mp (cols 62..82) ----
    if (w < 7) {
        #pragma unroll
        for (int q = 0; q < 3; q++) {
            const int idx = w * 3 + q;
            float a1 = 0.f, a2 = 0.f;
            if (idx == 0) {
                for (int d = lane; d < D; d += 32) {
                    a1 = fmaf(s_att[d], s_rt[d], a1);
                    a2 = fmaf(s_rt[d], s_gat[d], a2);
                }
            } else {
                const float* wa = w_att    + (idx - 1) * D;
                const float* wm = w_maxatt + (idx - 1) * D;
                for (int d = lane; d < D; d += 32) {
                    a1 = fmaf(s_att[d] * wa[d], s_rt[d], a1);
                    a2 = fmaf(s_rt[d] * wm[d], s_gat[d], a2);
                }
            }
            #pragma unroll
            for (int o = 16; o > 0; o >>= 1) {
                a1 += __shfl_xor_sync(0xffffffffu, a1, o);
                a2 += __shfl_xor_sync(0xffffffffu, a2, o);
            }
            if (lane == 0) {
                outrow[41 + idx] = tanhf(a1);
                outrow[62 + idx] = tanhf(a2);
            }
        }
    }
}

// ---------------------------------------------------------------------------
extern "C" void kernel_launch(void* const* d_in, const int* in_sizes, int n_in,
                              void* d_out, int out_size)
{
    const float* reps_lt   = (const float*)d_in[0];
    const float* reps_rt   = (const float*)d_in[1];
    const float* fw_h_rt   = (const float*)d_in[2];
    const float* bw_h_rt   = (const float*)d_in[3];
    const float* w_full    = (const float*)d_in[4];
    const float* w_maxpool = (const float*)d_in[5];
    const float* w_att     = (const float*)d_in[6];
    const float* w_maxatt  = (const float*)d_in[7];
    const float* attn_w1   = (const float*)d_in[8];
    const float* attn_w2   = (const float*)d_in[9];
    const float* diag_w    = (const float*)d_in[10];
    float* out = (float*)d_out;

    dim3 g1(L, B);  k_proj<<<g1, 128>>>(reps_lt, reps_rt, attn_w1, attn_w2, diag_w);
    dim3 g2(MP, B); k_maxpool<<<g2, 256>>>(reps_lt, reps_rt, w_maxpool, out);
    dim3 g3(L, B);  k_rows<<<g3, 256>>>(reps_lt, reps_rt, fw_h_rt, bw_h_rt,
                                        w_full, w_att, w_maxatt, out);
}

// round 2
// speedup vs baseline: 1.4426x; 1.4426x over previous
#include <cuda_runtime.h>
#include <math.h>
#include <float.h>

// Shapes (fixed by the problem)
#define B 64
#define L 128
#define D 200
#define MP 20
#define ATT 50
#define OUTC 83   // 21 + 20 + 21 + 21

// ---------------------------------------------------------------------------
// Scratch (device globals; no allocations allowed)
// ---------------------------------------------------------------------------
__device__ float g_e_lt[B * L * ATT];   // tanh(lt @ w2)               [b,l,a]
__device__ float g_e_rt[B * L * ATT];   // tanh(rt @ w1) * diag        [b,r,a]
__device__ float g_nl[B * L];           // sqrt(max(|lt_l|^2, EPS))    [b,l]

// ---------------------------------------------------------------------------
// Kernel 1: attention projections + lt row norms.
// grid (8, B): 16 rows per block, 256 threads, dynamic smem (~107 KB).
// w1/w2 stored TRANSPOSED ([a][d], row stride 202) so the k-loop reads float2.
// ---------------------------------------------------------------------------
__global__ __launch_bounds__(256) void k_proj(
    const float* __restrict__ lt, const float* __restrict__ rt,
    const float* __restrict__ w1, const float* __restrict__ w2,
    const float* __restrict__ diag)
{
    extern __shared__ float sm[];
    float* sLT = sm;            // [16][202]
    float* sRT = sm + 3232;     // [16][202]
    float* sW1 = sm + 6464;     // [50][202] transposed
    float* sW2 = sm + 16564;    // [50][202] transposed
    // total 26664 floats = 106656 B

    const int tile = blockIdx.x, b = blockIdx.y;
    const int t = threadIdx.x;
    const int r = t >> 4, c = t & 15;
    const int row0 = b * L + tile * 16;

    for (int idx = t; idx < 1600; idx += 256) {
        const int rr = idx / 100, q = idx - rr * 100;
        *(float2*)&sLT[rr * 202 + 2 * q] =
            *(const float2*)&lt[(size_t)(row0 + rr) * D + 2 * q];
        *(float2*)&sRT[rr * 202 + 2 * q] =
            *(const float2*)&rt[(size_t)(row0 + rr) * D + 2 * q];
    }
    for (int idx = t; idx < 10000; idx += 256) {
        const int d = idx / 50, a = idx - d * 50;
        sW1[a * 202 + d] = w1[idx];
        sW2[a * 202 + d] = w2[idx];
    }
    __syncthreads();

    float accL[4] = {0.f, 0.f, 0.f, 0.f};
    float accR[4] = {0.f, 0.f, 0.f, 0.f};
    float nacc = 0.f;
    const bool q3 = (c < 2);

    #pragma unroll 4
    for (int d = 0; d < 200; d += 2) {
        const float2 xl = *(const float2*)&sLT[r * 202 + d];
        const float2 xr = *(const float2*)&sRT[r * 202 + d];
        if (c == 0) nacc = fmaf(xl.x, xl.x, fmaf(xl.y, xl.y, nacc));
        #pragma unroll
        for (int q = 0; q < 3; q++) {
            const int a = c + 16 * q;
            const float2 wl = *(const float2*)&sW2[a * 202 + d];
            const float2 wr = *(const float2*)&sW1[a * 202 + d];
            accL[q] = fmaf(xl.x, wl.x, fmaf(xl.y, wl.y, accL[q]));
            accR[q] = fmaf(xr.x, wr.x, fmaf(xr.y, wr.y, accR[q]));
        }
        if (q3) {
            const int a = c + 48;
            const float2 wl = *(const float2*)&sW2[a * 202 + d];
            const float2 wr = *(const float2*)&sW1[a * 202 + d];
            accL[3] = fmaf(xl.x, wl.x, fmaf(xl.y, wl.y, accL[3]));
            accR[3] = fmaf(xr.x, wr.x, fmaf(xr.y, wr.y, accR[3]));
        }
    }

    const int row = row0 + r;
    #pragma unroll
    for (int q = 0; q < 3; q++) {
        const int a = c + 16 * q;
        g_e_lt[(size_t)row * ATT + a] = tanhf(accL[q]);
        g_e_rt[(size_t)row * ATT + a] = tanhf(accR[q]) * diag[a];
    }
    if (q3) {
        const int a = c + 48;
        g_e_lt[(size_t)row * ATT + a] = tanhf(accL[3]);
        g_e_rt[(size_t)row * ATT + a] = tanhf(accR[3]) * diag[a];
    }
    if (c == 0) g_nl[row] = sqrtf(fmaxf(nacc, 1e-6f));
}

// ---------------------------------------------------------------------------
// Kernel 2: maxpool match (unchanged structure; B cols remapped so B-tile
// register loads are 2x LDS.128 instead of 4x LDS.64).
// column of acc[i][j] lane e  <->  k = 8*tx + 2*j + e  (legal: max over k)
// ---------------------------------------------------------------------------
__global__ __launch_bounds__(256, 2) void k_maxpool(
    const float* __restrict__ lt, const float* __restrict__ rt,
    const float* __restrict__ wmp, float* __restrict__ out)
{
    const int m = blockIdx.x;   // 0..19
    const int b = blockIdx.y;   // 0..63

    __shared__ float Asd[2][8][260];   // duplicated A rows (256 used + pad)
    __shared__ float Bs[2][8][132];    // B rows (128 used + pad)
    __shared__ float red[128][17];

    const float* ltb = lt + (size_t)b * L * D;
    const float* rtb = rt + (size_t)b * L * D;
    const float* wr  = wmp + m * D;

    const int tid = threadIdx.x;
    const int ty = tid >> 4;          // 0..15 (row group)
    const int tx = tid & 15;          // 0..15 (col group)
    const int lr = tid >> 1;          // load row 0..127
    const int lc = (tid & 1) * 4;     // load col 0 or 4

    unsigned long long acc[8][4];
    #pragma unroll
    for (int i = 0; i < 8; i++)
        #pragma unroll
        for (int j = 0; j < 4; j++) acc[i][j] = 0ull;

    float4 ra, rb;
    float  w0, w1v, w2v, w3v;

    auto ld_regs = [&](int k0) {
        ra = *reinterpret_cast<const float4*>(ltb + lr * D + k0 + lc);
        rb = *reinterpret_cast<const float4*>(rtb + lr * D + k0 + lc);
        w0 = wr[k0 + lc + 0]; w1v = wr[k0 + lc + 1];
        w2v = wr[k0 + lc + 2]; w3v = wr[k0 + lc + 3];
    };
    auto st_smem = [&](int bf) {
        float ax = ra.x * w0, ay = ra.y * w1v, az = ra.z * w2v, aw = ra.w * w3v;
        *reinterpret_cast<float2*>(&Asd[bf][lc + 0][2 * lr]) = make_float2(ax, ax);
        *reinterpret_cast<float2*>(&Asd[bf][lc + 1][2 * lr]) = make_float2(ay, ay);
        *reinterpret_cast<float2*>(&Asd[bf][lc + 2][2 * lr]) = make_float2(az, az);
        *reinterpret_cast<float2*>(&Asd[bf][lc + 3][2 * lr]) = make_float2(aw, aw);
        Bs[bf][lc + 0][lr] = rb.x; Bs[bf][lc + 1][lr] = rb.y;
        Bs[bf][lc + 2][lr] = rb.z; Bs[bf][lc + 3][lr] = rb.w;
    };
    auto compute = [&](int bf) {
        #pragma unroll
        for (int kk = 0; kk < 8; kk++) {
            unsigned long long a2[8], b2[4];
            #pragma unroll
            for (int q = 0; q < 4; q++) {
                ulonglong2 v = *reinterpret_cast<const ulonglong2*>(
                    &Asd[bf][kk][2 * (ty * 8 + 2 * q)]);
                a2[2 * q] = v.x; a2[2 * q + 1] = v.y;
            }
            {
                ulonglong2 v0 = *reinterpret_cast<const ulonglong2*>(&Bs[bf][kk][8 * tx]);
                ulonglong2 v1 = *reinterpret_cast<const ulonglong2*>(&Bs[bf][kk][8 * tx + 4]);
                b2[0] = v0.x; b2[1] = v0.y; b2[2] = v1.x; b2[3] = v1.y;
            }
            #pragma unroll
            for (int i = 0; i < 8; i++)
                #pragma unroll
                for (int j = 0; j < 4; j++)
                    asm("fma.rn.f32x2 %0, %1, %2, %0;"
                        : "+l"(acc[i][j]) : "l"(a2[i]), "l"(b2[j]));
        }
    };

    ld_regs(0);
    st_smem(0);
    __syncthreads();

    #pragma unroll 1
    for (int kt = 1; kt < 25; kt++) {
        ld_regs(kt * 8);
        compute((kt - 1) & 1);
        st_smem(kt & 1);
        __syncthreads();
    }
    compute(0);

    float rmax[8];
    #pragma unroll
    for (int i = 0; i < 8; i++) {
        float mx = -3.4e38f;
        #pragma unroll
        for (int j = 0; j < 4; j++) {
            unsigned long long v = acc[i][j];
            float lo = __uint_as_float((unsigned)(v & 0xffffffffull));
            float hi = __uint_as_float((unsigned)(v >> 32));
            mx = fmaxf(mx, fmaxf(lo, hi));
        }
        rmax[i] = mx;
    }
    __syncthreads();
    #pragma unroll
    for (int i = 0; i < 8; i++) red[ty * 8 + i][tx] = rmax[i];
    __syncthreads();
    if (tid < 128) {
        float v = red[tid][0];
        #pragma unroll
        for (int x = 1; x < 16; x++) v = fmaxf(v, red[tid][x]);
        out[((size_t)(b * L + tid)) * OUTC + 21 + m] = tanhf(v);
    }
}

// ---------------------------------------------------------------------------
// Kernel 3: fused full + attentive + max-attentive match.
// grid (8, B): each block handles 16 output rows, 512 threads,
// whole lt[b] + e_lt[b] + all mp weights resident in ~218 KB dynamic smem.
//   S = rt_tile @ lt^T  -> argmax_l S/nl  (cosine-relevancy argmax)
//   Z = e_rt_tile @ e_lt^T -> softmax -> P ; att = P @ lt
//   epilogue: 1008 length-200 weighted dots.
// ---------------------------------------------------------------------------
__global__ __launch_bounds__(512) void k_match(
    const float* __restrict__ lt, const float* __restrict__ rt,
    const float* __restrict__ fw, const float* __restrict__ bw,
    const float* __restrict__ w_full, const float* __restrict__ w_att,
    const float* __restrict__ w_maxatt, float* __restrict__ out)
{
    extern __shared__ float sm[];
    float* sLT  = sm;            // [128][202]
    float* sRT  = sm + 25856;    // [16][202]
    float* sAT  = sm + 29088;    // [16][202]
    float* sEL  = sm + 32320;    // [128][51]
    float* sER  = sm + 38848;    // [16][51]
    float* sH   = sm + 39664;    // [204]
    float* sW   = sm + 39868;    // [60][201]  rows: 0..19 full, 20..39 att, 40..59 maxatt
    float* sONE = sm + 51928;    // [204]
    float* sZP  = sm + 52132;    // [16][132]  (S, then Z, then P)
    float* sNL  = sm + 54244;    // [128]
    float* sCOS = sm + 54372;    // [16]
    int*   sPOS = (int*)(sm + 54388);  // [16]
    // total 54404 floats = 217616 B

    const int tile = blockIdx.x, b = blockIdx.y;
    const int t = threadIdx.x;
    const int lane = t & 31, w = t >> 5;     // 16 warps
    const int r0g = tile * 16;               // first local row (global index)
    const float* ltb = lt + (size_t)b * L * D;
    const float* rtb = rt + (size_t)b * L * D;

    // ------------------------- fills -------------------------
    for (int idx = t; idx < 12800; idx += 512) {            // lt: 128 rows, float2
        const int rr = idx / 100, q = idx - rr * 100;
        *(float2*)&sLT[rr * 202 + 2 * q] = *(const float2*)&ltb[(size_t)rr * D + 2 * q];
    }
    for (int idx = t; idx < 1600; idx += 512) {             // rt tile
        const int rr = idx / 100, q = idx - rr * 100;
        *(float2*)&sRT[rr * 202 + 2 * q] =
            *(const float2*)&rtb[(size_t)(r0g + rr) * D + 2 * q];
    }
    for (int idx = t; idx < 6400; idx += 512) {             // e_lt (coalesced src)
        const int l = idx / 50, k = idx - l * 50;
        sEL[l * 51 + k] = g_e_lt[(size_t)b * L * ATT + idx];
    }
    for (int idx = t; idx < 800; idx += 512) {              // e_rt tile
        const int j = idx / 50, k = idx - j * 50;
        sER[j * 51 + k] = g_e_rt[(size_t)(b * L + r0g) * ATT + idx];
    }
    for (int idx = t; idx < 12000; idx += 512) {            // 3 mp weight matrices
        const int mrow = idx / 200, d = idx - mrow * 200;
        float v;
        if (mrow < 20)      v = w_full[idx];
        else if (mrow < 40) v = w_att[idx - 4000];
        else                v = w_maxatt[idx - 8000];
        sW[mrow * 201 + d] = v;
    }
    if (t < 204) { sH[t] = (t < 100) ? fw[b * 100 + t]
                         : (t < 200) ? bw[b * 100 + t - 100] : 0.f; }
    if (t >= 256 && t < 460) sONE[t - 256] = 1.0f;
    if (t < 128) sNL[t] = g_nl[b * L + t];
    __syncthreads();

    // ------------------------- S = rt_tile @ lt^T -------------------------
    {
        const int r0 = t >> 6, l0 = t & 63;   // outputs (r0/r0+8) x (l0/l0+64)
        const float* a0 = &sRT[r0 * 202];
        const float* a1 = &sRT[(r0 + 8) * 202];
        const float* b0 = &sLT[l0 * 202];
        const float* b1 = &sLT[(l0 + 64) * 202];
        float c00 = 0.f, c01 = 0.f, c10 = 0.f, c11 = 0.f;
        #pragma unroll 4
        for (int d = 0; d < 200; d += 2) {
            const float2 x0 = *(const float2*)&a0[d];
            const float2 x1 = *(const float2*)&a1[d];
            const float2 y0 = *(const float2*)&b0[d];
            const float2 y1 = *(const float2*)&b1[d];
            c00 = fmaf(x0.x, y0.x, fmaf(x0.y, y0.y, c00));
            c01 = fmaf(x0.x, y1.x, fmaf(x0.y, y1.y, c01));
            c10 = fmaf(x1.x, y0.x, fmaf(x1.y, y0.y, c10));
            c11 = fmaf(x1.x, y1.x, fmaf(x1.y, y1.y, c11));
        }
        sZP[r0 * 132 + l0]            = c00;
        sZP[r0 * 132 + l0 + 64]       = c01;
        sZP[(r0 + 8) * 132 + l0]      = c10;
        sZP[(r0 + 8) * 132 + l0 + 64] = c11;
    }
    __syncthreads();

    // --------------- argmax_l  S[r][l]/nl[l]  (warp w -> row w) ---------------
    {
        float bv = -FLT_MAX; int bi = 0;
        #pragma unroll
        for (int q = 0; q < 4; q++) {
            const int l = lane + 32 * q;
            const float v = sZP[w * 132 + l] / sNL[l];
            if (v > bv) { bv = v; bi = l; }
        }
        #pragma unroll
        for (int o = 16; o > 0; o >>= 1) {
            const float ov = __shfl_xor_sync(0xffffffffu, bv, o);
            const int   oi = __shfl_xor_sync(0xffffffffu, bi, o);
            if (ov > bv || (ov == bv && oi < bi)) { bv = ov; bi = oi; }
        }
        if (lane == 0) { sPOS[w] = bi; sCOS[w] = sZP[w * 132 + bi]; }
    }
    __syncthreads();

    // ------------------------- Z = e_rt_tile @ e_lt^T -------------------------
    {
        const int r0 = t >> 6, l0 = t & 63;
        const float* a0 = &sER[r0 * 51];
        const float* a1 = &sER[(r0 + 8) * 51];
        const float* b0 = &sEL[l0 * 51];
        const float* b1 = &sEL[(l0 + 64) * 51];
        float c00 = 0.f, c01 = 0.f, c10 = 0.f, c11 = 0.f;
        #pragma unroll 5
        for (int k = 0; k < 50; k++) {
            const float x0 = a0[k], x1 = a1[k], y0 = b0[k], y1 = b1[k];
            c00 = fmaf(x0, y0, c00); c01 = fmaf(x0, y1, c01);
            c10 = fmaf(x1, y0, c10); c11 = fmaf(x1, y1, c11);
        }
        sZP[r0 * 132 + l0]            = c00;
        sZP[r0 * 132 + l0 + 64]       = c01;
        sZP[(r0 + 8) * 132 + l0]      = c10;
        sZP[(r0 + 8) * 132 + l0 + 64] = c11;
    }
    __syncthreads();

    // ------------------------- softmax over l (warp w -> row w) ---------------
    {
        float zv[4];
        float zm = -FLT_MAX;
        #pragma unroll
        for (int q = 0; q < 4; q++) {
            zv[q] = sZP[w * 132 + lane + 32 * q];
            zm = fmaxf(zm, zv[q]);
        }
        #pragma unroll
        for (int o = 16; o > 0; o >>= 1)
            zm = fmaxf(zm, __shfl_xor_sync(0xffffffffu, zm, o));
        float s = 0.f;
        #pragma unroll
        for (int q = 0; q < 4; q++) { zv[q] = expf(zv[q] - zm); s += zv[q]; }
        #pragma unroll
        for (int o = 16; o > 0; o >>= 1)
            s += __shfl_xor_sync(0xffffffffu, s, o);
        const float inv = 1.0f / s;
        #pragma unroll
        for (int q = 0; q < 4; q++)
            sZP[w * 132 + lane + 32 * q] = zv[q] * inv;
    }
    __syncthreads();

    // ------------------------- att = P @ lt -------------------------
    {
        const int rg = t >> 6, c = t & 63;
        const bool q3 = (c < 8);
        float a0q[4] = {0.f, 0.f, 0.f, 0.f};
        float a1q[4] = {0.f, 0.f, 0.f, 0.f};
        #pragma unroll 2
        for (int l = 0; l < 128; l++) {
            const float p0 = sZP[rg * 132 + l];
            const float p1 = sZP[(rg + 8) * 132 + l];
            const float* row = &sLT[l * 202 + c];
            const float v0 = row[0], v1 = row[64], v2 = row[128];
            a0q[0] = fmaf(p0, v0, a0q[0]); a1q[0] = fmaf(p1, v0, a1q[0]);
            a0q[1] = fmaf(p0, v1, a0q[1]); a1q[1] = fmaf(p1, v1, a1q[1]);
            a0q[2] = fmaf(p0, v2, a0q[2]); a1q[2] = fmaf(p1, v2, a1q[2]);
            if (q3) {
                const float v3 = row[192];
                a0q[3] = fmaf(p0, v3, a0q[3]); a1q[3] = fmaf(p1, v3, a1q[3]);
            }
        }
        sAT[rg * 202 + c]        = a0q[0]; sAT[(rg + 8) * 202 + c]        = a1q[0];
        sAT[rg * 202 + c + 64]   = a0q[1]; sAT[(rg + 8) * 202 + c + 64]   = a1q[1];
        sAT[rg * 202 + c + 128]  = a0q[2]; sAT[(rg + 8) * 202 + c + 128]  = a1q[2];
        if (q3) { sAT[rg * 202 + c + 192] = a0q[3];
                  sAT[(rg + 8) * 202 + c + 192] = a1q[3]; }
    }
    __syncthreads();

    // ------------------------- epilogue: 1008 weighted dots -------------------
    for (int id = t; id < 16 * 63; id += 512) {
        const int j = id / 63, c = id - j * 63;
        const float* px; const float* py; const float* pw;
        int col; bool direct = false; float dval = 0.f;
        if (c == 0)       { col = 0;      px = &sLT[(r0g + j) * 202]; py = sH; pw = sONE; }
        else if (c < 21)  { col = c;      px = &sLT[(r0g + j) * 202]; py = sH; pw = &sW[(c - 1) * 201]; }
        else if (c == 21) { col = 41;     px = &sAT[j * 202]; py = &sRT[j * 202]; pw = sONE; }
        else if (c < 42)  { col = 20 + c; px = &sAT[j * 202]; py = &sRT[j * 202]; pw = &sW[(c - 2) * 201]; }
        else if (c == 42) { col = 62; direct = true; dval = sCOS[j];
                            px = sONE; py = sONE; pw = sONE; }
        else              { col = 20 + c; px = &sRT[j * 202]; py = &sLT[sPOS[j] * 202]; pw = &sW[(c - 3) * 201]; }
        float acc = 0.f;
        #pragma unroll 4
        for (int d = 0; d < 200; d++) acc = fmaf(px[d] * pw[d], py[d], acc);
        const float res = tanhf(direct ? dval : acc);
        out[((size_t)(b * L + r0g + j)) * OUTC + col] = res;
    }
}

// ---------------------------------------------------------------------------
extern "C" void kernel_launch(void* const* d_in, const int* in_sizes, int n_in,
                              void* d_out, int out_size)
{
    const float* reps_lt   = (const float*)d_in[0];
    const float* reps_rt   = (const float*)d_in[1];
    const float* fw_h_rt   = (const float*)d_in[2];
    const float* bw_h_rt   = (const float*)d_in[3];
    const float* w_full    = (const float*)d_in[4];
    const float* w_maxpool = (const float*)d_in[5];
    const float* w_att     = (const float*)d_in[6];
    const float* w_maxatt  = (const float*)d_in[7];
    const float* attn_w1   = (const float*)d_in[8];
    const float* attn_w2   = (const float*)d_in[9];
    const float* diag_w    = (const float*)d_in[10];
    float* out = (float*)d_out;

    const int smem_proj  = 26664 * 4;   // 106656 B
    const int smem_match = 54404 * 4;   // 217616 B
    cudaFuncSetAttribute(k_proj,  cudaFuncAttributeMaxDynamicSharedMemorySize, smem_proj);
    cudaFuncSetAttribute(k_match, cudaFuncAttributeMaxDynamicSharedMemorySize, smem_match);

    dim3 g1(8, B);  k_proj<<<g1, 256, smem_proj>>>(reps_lt, reps_rt, attn_w1, attn_w2, diag_w);
    dim3 g2(MP, B); k_maxpool<<<g2, 256>>>(reps_lt, reps_rt, w_maxpool, out);
    dim3 g3(8, B);  k_match<<<g3, 512, smem_match>>>(reps_lt, reps_rt, fw_h_rt, bw_h_rt,
                                                     w_full, w_att, w_maxatt, out);
}

// round 4
// speedup vs baseline: 1.5271x; 1.0585x over previous
#include <cuda_runtime.h>
#include <math.h>
#include <float.h>

// Shapes (fixed by the problem)
#define B 64
#define L 128
#define D 200
#define MP 20
#define ATT 50
#define OUTC 83   // 21 + 20 + 21 + 21

// ---------------------------------------------------------------------------
// Scratch (device globals; no allocations allowed)
// ---------------------------------------------------------------------------
__device__ float g_e_lt[B * L * ATT];   // tanh(lt @ w2)               [b,l,a]
__device__ float g_e_rt[B * L * ATT];   // tanh(rt @ w1) * diag        [b,r,a]
__device__ float g_nl[B * L];           // sqrt(max(|lt_l|^2, EPS))    [b,l]

// ---------------------------------------------------------------------------
// Kernel 1: attention projections + lt row norms.
// grid (8, B), 128 threads, 26 KB smem -> high occupancy.
// Thread = one attention column (50 lt-side + 50 rt-side), 16 rows in regs,
// weights read via coalesced L1-hit LDG, FFMA2 paired over d.
// ---------------------------------------------------------------------------
__global__ __launch_bounds__(128) void k_proj(
    const float* __restrict__ lt, const float* __restrict__ rt,
    const float* __restrict__ w1, const float* __restrict__ w2,
    const float* __restrict__ diag)
{
    __shared__ float sX[32][202];   // rows 0-15: lt tile, rows 16-31: rt tile
    __shared__ float sD[64];

    const int tile = blockIdx.x, b = blockIdx.y;
    const int t = threadIdx.x;
    const int row0 = b * L + tile * 16;

    for (int idx = t; idx < 3200; idx += 128) {
        const int r = idx / 100, q = idx - r * 100;
        const int gr = row0 + (r & 15);
        const float* src = (r < 16) ? lt : rt;
        *(float2*)&sX[r][2 * q] = *(const float2*)&src[(size_t)gr * D + 2 * q];
    }
    if (t < ATT) sD[t] = diag[t];
    __syncthreads();

    if (t < 100) {
        const bool isLt = (t < 50);
        const int a = isLt ? t : t - 50;
        const float* wsrc = isLt ? w2 : w1;
        const int rbase = isLt ? 0 : 16;

        unsigned long long acc2[16];
        #pragma unroll
        for (int r = 0; r < 16; r++) acc2[r] = 0ull;

        #pragma unroll 2
        for (int d = 0; d < 200; d += 2) {
            const float wlo = wsrc[d * ATT + a];
            const float whi = wsrc[(d + 1) * ATT + a];
            unsigned long long w2r;
            asm("mov.b64 %0, {%1, %2};" : "=l"(w2r) : "f"(wlo), "f"(whi));
            #pragma unroll
            for (int r = 0; r < 16; r++) {
                const unsigned long long x2 =
                    *(const unsigned long long*)&sX[rbase + r][d];
                asm("fma.rn.f32x2 %0, %1, %2, %0;"
                    : "+l"(acc2[r]) : "l"(x2), "l"(w2r));
            }
        }
        #pragma unroll
        for (int r = 0; r < 16; r++) {
            float lo, hi;
            asm("mov.b64 {%0, %1}, %2;" : "=f"(lo), "=f"(hi) : "l"(acc2[r]));
            const float v = tanhf(lo + hi);
            if (isLt) g_e_lt[(size_t)(row0 + r) * ATT + a] = v;
            else      g_e_rt[(size_t)(row0 + r) * ATT + a] = v * sD[a];
        }
    } else if (t < 116) {
        const int r = t - 100;
        float ss = 0.f;
        #pragma unroll 4
        for (int d = 0; d < 200; d += 2) {
            const float2 x = *(const float2*)&sX[r][d];
            ss = fmaf(x.x, x.x, fmaf(x.y, x.y, ss));
        }
        g_nl[row0 + r] = sqrtf(fmaxf(ss, 1e-6f));
    }
}

// ---------------------------------------------------------------------------
// Kernel 2: maxpool match (unchanged from round 2 — near its FFMA2 floor).
// ---------------------------------------------------------------------------
__global__ __launch_bounds__(256, 2) void k_maxpool(
    const float* __restrict__ lt, const float* __restrict__ rt,
    const float* __restrict__ wmp, float* __restrict__ out)
{
    const int m = blockIdx.x;   // 0..19
    const int b = blockIdx.y;   // 0..63

    __shared__ float Asd[2][8][260];
    __shared__ float Bs[2][8][132];
    __shared__ float red[128][17];

    const float* ltb = lt + (size_t)b * L * D;
    const float* rtb = rt + (size_t)b * L * D;
    const float* wr  = wmp + m * D;

    const int tid = threadIdx.x;
    const int ty = tid >> 4;
    const int tx = tid & 15;
    const int lr = tid >> 1;
    const int lc = (tid & 1) * 4;

    unsigned long long acc[8][4];
    #pragma unroll
    for (int i = 0; i < 8; i++)
        #pragma unroll
        for (int j = 0; j < 4; j++) acc[i][j] = 0ull;

    float4 ra, rb;
    float  w0, w1v, w2v, w3v;

    auto ld_regs = [&](int k0) {
        ra = *reinterpret_cast<const float4*>(ltb + lr * D + k0 + lc);
        rb = *reinterpret_cast<const float4*>(rtb + lr * D + k0 + lc);
        w0 = wr[k0 + lc + 0]; w1v = wr[k0 + lc + 1];
        w2v = wr[k0 + lc + 2]; w3v = wr[k0 + lc + 3];
    };
    auto st_smem = [&](int bf) {
        float ax = ra.x * w0, ay = ra.y * w1v, az = ra.z * w2v, aw = ra.w * w3v;
        *reinterpret_cast<float2*>(&Asd[bf][lc + 0][2 * lr]) = make_float2(ax, ax);
        *reinterpret_cast<float2*>(&Asd[bf][lc + 1][2 * lr]) = make_float2(ay, ay);
        *reinterpret_cast<float2*>(&Asd[bf][lc + 2][2 * lr]) = make_float2(az, az);
        *reinterpret_cast<float2*>(&Asd[bf][lc + 3][2 * lr]) = make_float2(aw, aw);
        Bs[bf][lc + 0][lr] = rb.x; Bs[bf][lc + 1][lr] = rb.y;
        Bs[bf][lc + 2][lr] = rb.z; Bs[bf][lc + 3][lr] = rb.w;
    };
    auto compute = [&](int bf) {
        #pragma unroll
        for (int kk = 0; kk < 8; kk++) {
            unsigned long long a2[8], b2[4];
            #pragma unroll
            for (int q = 0; q < 4; q++) {
                ulonglong2 v = *reinterpret_cast<const ulonglong2*>(
                    &Asd[bf][kk][2 * (ty * 8 + 2 * q)]);
                a2[2 * q] = v.x; a2[2 * q + 1] = v.y;
            }
            {
                ulonglong2 v0 = *reinterpret_cast<const ulonglong2*>(&Bs[bf][kk][8 * tx]);
                ulonglong2 v1 = *reinterpret_cast<const ulonglong2*>(&Bs[bf][kk][8 * tx + 4]);
                b2[0] = v0.x; b2[1] = v0.y; b2[2] = v1.x; b2[3] = v1.y;
            }
            #pragma unroll
            for (int i = 0; i < 8; i++)
                #pragma unroll
                for (int j = 0; j < 4; j++)
                    asm("fma.rn.f32x2 %0, %1, %2, %0;"
                        : "+l"(acc[i][j]) : "l"(a2[i]), "l"(b2[j]));
        }
    };

    ld_regs(0);
    st_smem(0);
    __syncthreads();

    #pragma unroll 1
    for (int kt = 1; kt < 25; kt++) {
        ld_regs(kt * 8);
        compute((kt - 1) & 1);
        st_smem(kt & 1);
        __syncthreads();
    }
    compute(0);

    float rmax[8];
    #pragma unroll
    for (int i = 0; i < 8; i++) {
        float mx = -3.4e38f;
        #pragma unroll
        for (int j = 0; j < 4; j++) {
            unsigned long long v = acc[i][j];
            float lo = __uint_as_float((unsigned)(v & 0xffffffffull));
            float hi = __uint_as_float((unsigned)(v >> 32));
            mx = fmaxf(mx, fmaxf(lo, hi));
        }
        rmax[i] = mx;
    }
    __syncthreads();
    #pragma unroll
    for (int i = 0; i < 8; i++) red[ty * 8 + i][tx] = rmax[i];
    __syncthreads();
    if (tid < 128) {
        float v = red[tid][0];
        #pragma unroll
        for (int x = 1; x < 16; x++) v = fmaxf(v, red[tid][x]);
        out[((size_t)(b * L + tid)) * OUTC + 21 + m] = tanhf(v);
    }
}

// ---------------------------------------------------------------------------
// Kernel 3: fused full + attentive + max-attentive match.
// grid (8, B), 512 threads, ~222 KB dynamic smem.
// New epilogue: per warp j, g = U (.) V in registers, out = tanh(g @ W^T).
// ---------------------------------------------------------------------------
__global__ __launch_bounds__(512) void k_match(
    const float* __restrict__ lt, const float* __restrict__ rt,
    const float* __restrict__ fw, const float* __restrict__ bw,
    const float* __restrict__ w_full, const float* __restrict__ w_att,
    const float* __restrict__ w_maxatt, float* __restrict__ out)
{
    extern __shared__ float sm[];
    float* sLT  = sm;            // [128][202]
    float* sRT  = sm + 25856;    // [16][202]
    float* sAT  = sm + 29088;    // [16][202]
    float* sEL  = sm + 32320;    // [128][51]
    float* sER  = sm + 38848;    // [16][51]
    float* sH   = sm + 39664;    // [204]
    float* sW   = sm + 39868;    // [60][224] zero-padded d>=200
    float* sZP  = sm + 53308;    // [16][132]
    float* sNL  = sm + 55420;    // [128]
    int*   sPOS = (int*)(sm + 55548);  // [16]
    // total 55564 floats = 222256 B

    const int tile = blockIdx.x, b = blockIdx.y;
    const int t = threadIdx.x;
    const int lane = t & 31, w = t >> 5;     // 16 warps
    const int r0g = tile * 16;
    const float* ltb = lt + (size_t)b * L * D;
    const float* rtb = rt + (size_t)b * L * D;

    // ------------------------- fills -------------------------
    for (int idx = t; idx < 12800; idx += 512) {
        const int rr = idx / 100, q = idx - rr * 100;
        *(float2*)&sLT[rr * 202 + 2 * q] = *(const float2*)&ltb[(size_t)rr * D + 2 * q];
    }
    for (int idx = t; idx < 1600; idx += 512) {
        const int rr = idx / 100, q = idx - rr * 100;
        *(float2*)&sRT[rr * 202 + 2 * q] =
            *(const float2*)&rtb[(size_t)(r0g + rr) * D + 2 * q];
    }
    for (int idx = t; idx < 6400; idx += 512) {
        const int l = idx / 50, k = idx - l * 50;
        sEL[l * 51 + k] = g_e_lt[(size_t)b * L * ATT + idx];
    }
    for (int idx = t; idx < 800; idx += 512) {
        const int j = idx / 50, k = idx - j * 50;
        sER[j * 51 + k] = g_e_rt[(size_t)(b * L + r0g) * ATT + idx];
    }
    for (int idx = t; idx < 60 * 224; idx += 512) {
        const int mrow = idx / 224, d = idx - mrow * 224;
        float v = 0.f;
        if (d < 200) {
            if (mrow < 20)      v = w_full[mrow * 200 + d];
            else if (mrow < 40) v = w_att[(mrow - 20) * 200 + d];
            else                v = w_maxatt[(mrow - 40) * 200 + d];
        }
        sW[mrow * 224 + d] = v;
    }
    if (t < 204) { sH[t] = (t < 100) ? fw[b * 100 + t]
                         : (t < 200) ? bw[b * 100 + t - 100] : 0.f; }
    if (t < 128) sNL[t] = g_nl[b * L + t];
    __syncthreads();

    // ------------------------- S = rt_tile @ lt^T -------------------------
    {
        const int r0 = t >> 6, l0 = t & 63;
        const float* a0 = &sRT[r0 * 202];
        const float* a1 = &sRT[(r0 + 8) * 202];
        const float* b0 = &sLT[l0 * 202];
        const float* b1 = &sLT[(l0 + 64) * 202];
        float c00 = 0.f, c01 = 0.f, c10 = 0.f, c11 = 0.f;
        #pragma unroll 4
        for (int d = 0; d < 200; d += 2) {
            const float2 x0 = *(const float2*)&a0[d];
            const float2 x1 = *(const float2*)&a1[d];
            const float2 y0 = *(const float2*)&b0[d];
            const float2 y1 = *(const float2*)&b1[d];
            c00 = fmaf(x0.x, y0.x, fmaf(x0.y, y0.y, c00));
            c01 = fmaf(x0.x, y1.x, fmaf(x0.y, y1.y, c01));
            c10 = fmaf(x1.x, y0.x, fmaf(x1.y, y0.y, c10));
            c11 = fmaf(x1.x, y1.x, fmaf(x1.y, y1.y, c11));
        }
        sZP[r0 * 132 + l0]            = c00;
        sZP[r0 * 132 + l0 + 64]       = c01;
        sZP[(r0 + 8) * 132 + l0]      = c10;
        sZP[(r0 + 8) * 132 + l0 + 64] = c11;
    }
    __syncthreads();

    // --------------- argmax_l  S[r][l]/nl[l]  (warp w -> row w) ---------------
    {
        float bv = -FLT_MAX; int bi = 0;
        #pragma unroll
        for (int q = 0; q < 4; q++) {
            const int l = lane + 32 * q;
            const float v = sZP[w * 132 + l] / sNL[l];
            if (v > bv) { bv = v; bi = l; }
        }
        #pragma unroll
        for (int o = 16; o > 0; o >>= 1) {
            const float ov = __shfl_xor_sync(0xffffffffu, bv, o);
            const int   oi = __shfl_xor_sync(0xffffffffu, bi, o);
            if (ov > bv || (ov == bv && oi < bi)) { bv = ov; bi = oi; }
        }
        if (lane == 0) sPOS[w] = bi;
    }
    __syncthreads();

    // ------------------------- Z = e_rt_tile @ e_lt^T -------------------------
    {
        const int r0 = t >> 6, l0 = t & 63;
        const float* a0 = &sER[r0 * 51];
        const float* a1 = &sER[(r0 + 8) * 51];
        const float* b0 = &sEL[l0 * 51];
        const float* b1 = &sEL[(l0 + 64) * 51];
        float c00 = 0.f, c01 = 0.f, c10 = 0.f, c11 = 0.f;
        #pragma unroll 5
        for (int k = 0; k < 50; k++) {
            const float x0 = a0[k], x1 = a1[k], y0 = b0[k], y1 = b1[k];
            c00 = fmaf(x0, y0, c00); c01 = fmaf(x0, y1, c01);
            c10 = fmaf(x1, y0, c10); c11 = fmaf(x1, y1, c11);
        }
        sZP[r0 * 132 + l0]            = c00;
        sZP[r0 * 132 + l0 + 64]       = c01;
        sZP[(r0 + 8) * 132 + l0]      = c10;
        sZP[(r0 + 8) * 132 + l0 + 64] = c11;
    }
    __syncthreads();

    // ------------------------- softmax over l (warp w -> row w) ---------------
    {
        float zv[4];
        float zm = -FLT_MAX;
        #pragma unroll
        for (int q = 0; q < 4; q++) {
            zv[q] = sZP[w * 132 + lane + 32 * q];
            zm = fmaxf(zm, zv[q]);
        }
        #pragma unroll
        for (int o = 16; o > 0; o >>= 1)
            zm = fmaxf(zm, __shfl_xor_sync(0xffffffffu, zm, o));
        float s = 0.f;
        #pragma unroll
        for (int q = 0; q < 4; q++) { zv[q] = expf(zv[q] - zm); s += zv[q]; }
        #pragma unroll
        for (int o = 16; o > 0; o >>= 1)
            s += __shfl_xor_sync(0xffffffffu, s, o);
        const float inv = 1.0f / s;
        #pragma unroll
        for (int q = 0; q < 4; q++)
            sZP[w * 132 + lane + 32 * q] = zv[q] * inv;
    }
    __syncthreads();

    // ------------------------- att = P @ lt -------------------------
    {
        const int rg = t >> 6, c = t & 63;
        const bool q3 = (c < 8);
        float a0q[4] = {0.f, 0.f, 0.f, 0.f};
        float a1q[4] = {0.f, 0.f, 0.f, 0.f};
        #pragma unroll 2
        for (int l = 0; l < 128; l++) {
            const float p0 = sZP[rg * 132 + l];
            const float p1 = sZP[(rg + 8) * 132 + l];
            const float* row = &sLT[l * 202 + c];
            const float v0 = row[0], v1 = row[64], v2 = row[128];
            a0q[0] = fmaf(p0, v0, a0q[0]); a1q[0] = fmaf(p1, v0, a1q[0]);
            a0q[1] = fmaf(p0, v1, a0q[1]); a1q[1] = fmaf(p1, v1, a1q[1]);
            a0q[2] = fmaf(p0, v2, a0q[2]); a1q[2] = fmaf(p1, v2, a1q[2]);
            if (q3) {
                const float v3 = row[192];
                a0q[3] = fmaf(p0, v3, a0q[3]); a1q[3] = fmaf(p1, v3, a1q[3]);
            }
        }
        sAT[rg * 202 + c]        = a0q[0]; sAT[(rg + 8) * 202 + c]        = a1q[0];
        sAT[rg * 202 + c + 64]   = a0q[1]; sAT[(rg + 8) * 202 + c + 64]   = a1q[1];
        sAT[rg * 202 + c + 128]  = a0q[2]; sAT[(rg + 8) * 202 + c + 128]  = a1q[2];
        if (q3) { sAT[rg * 202 + c + 192] = a0q[3];
                  sAT[(rg + 8) * 202 + c + 192] = a1q[3]; }
    }
    __syncthreads();

    // -------- epilogue: warp j builds g = U.V, then out = tanh(g @ W^T) -------
    {
        const int j = w;                 // warp -> output row (16 warps, 16 rows)
        const int gr = r0g + j;
        const int pos = sPOS[j];
        float* outrow = out + (size_t)(b * L + gr) * OUTC;

        float gf[7], ga[7], gm[7];
        #pragma unroll
        for (int c = 0; c < 7; c++) {
            const int d = lane + 32 * c;
            const bool ok = (c < 6) || (lane < 8);
            const float xl = ok ? sLT[gr * 202 + d] : 0.f;
            const float xh = ok ? sH[d] : 0.f;
            const float xa = ok ? sAT[j * 202 + d] : 0.f;
            const float xr = ok ? sRT[j * 202 + d] : 0.f;
            const float xp = ok ? sLT[pos * 202 + d] : 0.f;
            gf[c] = xl * xh;
            ga[c] = xa * xr;
            gm[c] = xr * xp;
        }
        // cosine columns: 0 (full), 41 (att), 62 (maxatt)
        {
            float s0 = 0.f, s1 = 0.f, s2 = 0.f;
            #pragma unroll
            for (int c = 0; c < 7; c++) { s0 += gf[c]; s1 += ga[c]; s2 += gm[c]; }
            #pragma unroll
            for (int o = 16; o > 0; o >>= 1) {
                s0 += __shfl_xor_sync(0xffffffffu, s0, o);
                s1 += __shfl_xor_sync(0xffffffffu, s1, o);
                s2 += __shfl_xor_sync(0xffffffffu, s2, o);
            }
            if (lane == 0) {
                outrow[0]  = tanhf(s0);
                outrow[41] = tanhf(s1);
                outrow[62] = tanhf(s2);
            }
        }
        // mp columns
        #pragma unroll 2
        for (int m = 0; m < 20; m++) {
            float a0 = 0.f, a1 = 0.f, a2 = 0.f;
            #pragma unroll
            for (int c = 0; c < 7; c++) {
                const int d = lane + 32 * c;
                a0 = fmaf(gf[c], sW[m * 224 + d], a0);
                a1 = fmaf(ga[c], sW[(20 + m) * 224 + d], a1);
                a2 = fmaf(gm[c], sW[(40 + m) * 224 + d], a2);
            }
            #pragma unroll
            for (int o = 16; o > 0; o >>= 1) {
                a0 += __shfl_xor_sync(0xffffffffu, a0, o);
                a1 += __shfl_xor_sync(0xffffffffu, a1, o);
                a2 += __shfl_xor_sync(0xffffffffu, a2, o);
            }
            if (lane == 0) {
                outrow[1 + m]  = tanhf(a0);
                outrow[42 + m] = tanhf(a1);
                outrow[63 + m] = tanhf(a2);
            }
        }
    }
}

// ---------------------------------------------------------------------------
extern "C" void kernel_launch(void* const* d_in, const int* in_sizes, int n_in,
                              void* d_out, int out_size)
{
    const float* reps_lt   = (const float*)d_in[0];
    const float* reps_rt   = (const float*)d_in[1];
    const float* fw_h_rt   = (const float*)d_in[2];
    const float* bw_h_rt   = (const float*)d_in[3];
    const float* w_full    = (const float*)d_in[4];
    const float* w_maxpool = (const float*)d_in[5];
    const float* w_att     = (const float*)d_in[6];
    const float* w_maxatt  = (const float*)d_in[7];
    const float* attn_w1   = (const float*)d_in[8];
    const float* attn_w2   = (const float*)d_in[9];
    const float* diag_w    = (const float*)d_in[10];
    float* out = (float*)d_out;

    const int smem_match = 55564 * 4;   // 222256 B
    cudaFuncSetAttribute(k_match, cudaFuncAttributeMaxDynamicSharedMemorySize, smem_match);

    // maxpool first (independent) so ncu's fixed-skip capture lands on k_match
    dim3 g2(MP, B); k_maxpool<<<g2, 256>>>(reps_lt, reps_rt, w_maxpool, out);
    dim3 g1(8, B);  k_proj<<<g1, 128>>>(reps_lt, reps_rt, attn_w1, attn_w2, diag_w);
    dim3 g3(8, B);  k_match<<<g3, 512, smem_match>>>(reps_lt, reps_rt, fw_h_rt, bw_h_rt,
                                                     w_full, w_att, w_maxatt, out);
}

// round 8
// speedup vs baseline: 1.6633x; 1.0892x over previous
#include <cuda_runtime.h>
#include <cuda_bf16.h>
#include <math.h>
#include <float.h>

// Shapes (fixed by the problem)
#define B 64
#define L 128
#define D 200
#define MP 20
#define ATT 50
#define OUTC 83   // 21 + 20 + 21 + 21

// ---------------------------------------------------------------------------
// Scratch (device globals; no allocations allowed)
// ---------------------------------------------------------------------------
__device__ float g_e_lt[B * L * ATT];       // tanh(lt @ w2)             [b,l,a]
__device__ float g_e_rt[B * L * ATT];       // tanh(rt @ w1) * diag      [b,r,a]
__device__ float g_nl[B * L];               // sqrt(max(|lt_l|^2, EPS))  [b,l]
__device__ unsigned g_lt_hi2[B * L * 128];  // lt bf16 hi, packed pairs, Kpad=256
__device__ unsigned g_lt_lo2[B * L * 128];  // lt bf16 lo

// ---------------------------------------------------------------------------
// Helpers (base-PTX only: ldmatrix sm_75+, mma.sync bf16 sm_80+)
// ---------------------------------------------------------------------------
__device__ __forceinline__ unsigned smem_u32(const void* p) {
    unsigned a;
    asm("{ .reg .u64 t; cvta.to.shared.u64 t, %1; cvt.u32.u64 %0, t; }"
        : "=r"(a) : "l"(p));
    return a;
}
__device__ __forceinline__ void ldsm_x4(unsigned* r, unsigned addr) {
    asm volatile("ldmatrix.sync.aligned.m8n8.x4.shared.b16 {%0,%1,%2,%3}, [%4];"
                 : "=r"(r[0]), "=r"(r[1]), "=r"(r[2]), "=r"(r[3]) : "r"(addr));
}
__device__ __forceinline__ void mma_bf16(float* c, const unsigned* a,
                                         const unsigned* b) {
    asm volatile(
        "mma.sync.aligned.m16n8k16.row.col.f32.bf16.bf16.f32 "
        "{%0,%1,%2,%3}, {%4,%5,%6,%7}, {%8,%9}, {%0,%1,%2,%3};"
        : "+f"(c[0]), "+f"(c[1]), "+f"(c[2]), "+f"(c[3])
        : "r"(a[0]), "r"(a[1]), "r"(a[2]), "r"(a[3]), "r"(b[0]), "r"(b[1]));
}
// byte offset of bf16 element (r, k) inside a [128][64] bf16 plane,
// XOR-swizzled so ldmatrix (8 rows x 16B) is bank-conflict-free.
__device__ __forceinline__ unsigned offp(int r, int k) {
    return (unsigned)(r * 128 + ((((k >> 3) ^ (r & 7)) & 7) << 4) + ((k & 7) << 1));
}

// ---------------------------------------------------------------------------
// Kernel 0: bf16 hi/lo split of lt (Kpad=256, zero-padded), packed pairs.
// ---------------------------------------------------------------------------
__global__ __launch_bounds__(256) void k_prep(const float* __restrict__ lt)
{
    const int b = blockIdx.x;
    for (int idx = threadIdx.x; idx < L * 128; idx += 256) {
        const int r = idx >> 7, kk = idx & 127, k = kk * 2;
        const float* rr = lt + ((size_t)(b * L + r)) * D;
        const float f0 = (k < 200) ? rr[k] : 0.f;
        const float f1 = (k + 1 < 200) ? rr[k + 1] : 0.f;
        __nv_bfloat162 h = __floats2bfloat162_rn(f0, f1);
        const float h0 = __low2float(h), h1 = __high2float(h);
        __nv_bfloat162 l = __floats2bfloat162_rn(f0 - h0, f1 - h1);
        const unsigned gi = (unsigned)(((b * L + r) << 7) + kk);
        g_lt_hi2[gi] = *(unsigned*)&h;
        g_lt_lo2[gi] = *(unsigned*)&l;
    }
}

// ---------------------------------------------------------------------------
// Kernel 2: maxpool match via mma.sync (bf16 split, fp32 accum).
// Per (m,b): C[l,k] = lt_l . (w_m (.) rt_k)
//   C = A_hi@B_hi^T + A_hi@B_lo^T + A_lo@B_hi^T
// B stored [n][k] row-major == col-major KxN  ->  NON-trans ldmatrix gives the
// exact mma B fragment (the .trans variant was the round-7 bug).
// K = 200 padded to 208, 4 chunks of 64 (last: 1 k-step), double-buffered.
// 8 warps: warp grid 4(M) x 2(N), 32x64 C-tile per warp.
// out[b,l,21+m] = tanh(max_k C[l,k]).
// ---------------------------------------------------------------------------
#define MMA_SMEM_BYTES 132992
__global__ __launch_bounds__(256) void k_mp_mma(
    const float* __restrict__ rt, const float* __restrict__ wmp,
    float* __restrict__ out)
{
    extern __shared__ char smem[];
    const unsigned sb = smem_u32(smem);
    float* sW   = (float*)(smem + 131072);   // [224] w row, zero-padded
    float* sRED = (float*)(smem + 131968);   // [128][2]

    const int m = blockIdx.x, b = blockIdx.y;
    const int tid = threadIdx.x, wid = tid >> 5, lane = tid & 31;
    const int m0 = (wid & 3) * 32, n0 = (wid >> 2) * 64, wn = wid >> 2;

    // plane byte offsets within a buffer: 0:A_hi 16384:A_lo 32768:B_hi 49152:B_lo
    for (int d = tid; d < 224; d += 256) sW[d] = (d < 200) ? wmp[m * 200 + d] : 0.f;
    __syncthreads();

    auto load_chunk = [&](int c, int buf) {
        char* base = smem + buf * 65536;
        // A planes from precomputed split (coalesced)
        for (int idx = tid; idx < 4096; idx += 256) {
            const int r = idx >> 5, kk = idx & 31;
            const unsigned gi = (unsigned)(((b * L + r) << 7) + c * 32 + kk);
            const unsigned o = offp(r, 2 * kk);
            *(unsigned*)(base + o)         = g_lt_hi2[gi];
            *(unsigned*)(base + 16384 + o) = g_lt_lo2[gi];
        }
        // B planes: (w (.) rt) converted + split on the fly
        for (int idx = tid; idx < 4096; idx += 256) {
            const int r = idx >> 5, kk = idx & 31;
            const int k = c * 64 + 2 * kk;
            float f0 = 0.f, f1 = 0.f;
            if (k < 200) {
                const float2 v = *(const float2*)&rt[(size_t)(b * L + r) * D + k];
                f0 = v.x * sW[k];
                f1 = (k + 1 < 200) ? v.y * sW[k + 1] : 0.f;
            }
            __nv_bfloat162 h = __floats2bfloat162_rn(f0, f1);
            const float h0 = __low2float(h), h1 = __high2float(h);
            __nv_bfloat162 l = __floats2bfloat162_rn(f0 - h0, f1 - h1);
            const unsigned o = offp(r, 2 * kk);
            *(unsigned*)(base + 32768 + o) = *(unsigned*)&h;
            *(unsigned*)(base + 49152 + o) = *(unsigned*)&l;
        }
    };

    float acc[2][8][4];
    #pragma unroll
    for (int mt = 0; mt < 2; mt++)
        #pragma unroll
        for (int nt = 0; nt < 8; nt++)
            #pragma unroll
            for (int q = 0; q < 4; q++) acc[mt][nt][q] = 0.f;

    auto compute = [&](int buf, int nk) {
        const unsigned pb = sb + buf * 65536;
        for (int ks = 0; ks < nk; ks++) {
            unsigned ah[2][4], al[2][4], bb[4][4];
            const int kca = ks * 16 + ((lane >> 4) << 3);
            #pragma unroll
            for (int mt = 0; mt < 2; mt++) {
                const int row = m0 + 16 * mt + (lane & 15);
                ldsm_x4(ah[mt], pb + offp(row, kca));
                ldsm_x4(al[mt], pb + 16384 + offp(row, kca));
            }
            // B: non-trans ldmatrix; addresses pick (n-row, k-col 0/8) tiles:
            //  thr 0-7: n0-7 k0-7 | thr 8-15: n0-7 k8-15
            //  thr16-23: n8-15 k0-7 | thr24-31: n8-15 k8-15
            const int kcb = ks * 16 + (((lane >> 3) & 1) << 3);
            const int rowb = (lane & 7) + ((lane >> 4) << 3);
            #pragma unroll
            for (int nt2 = 0; nt2 < 4; nt2++)
                ldsm_x4(bb[nt2], pb + 32768 + offp(n0 + nt2 * 16 + rowb, kcb));
            #pragma unroll
            for (int mt = 0; mt < 2; mt++)
                #pragma unroll
                for (int nt = 0; nt < 8; nt++) {
                    const unsigned* bp = &bb[nt >> 1][(nt & 1) * 2];
                    mma_bf16(acc[mt][nt], ah[mt], bp);   // hi x hi
                    mma_bf16(acc[mt][nt], al[mt], bp);   // lo x hi
                }
            #pragma unroll
            for (int nt2 = 0; nt2 < 4; nt2++)
                ldsm_x4(bb[nt2], pb + 49152 + offp(n0 + nt2 * 16 + rowb, kcb));
            #pragma unroll
            for (int mt = 0; mt < 2; mt++)
                #pragma unroll
                for (int nt = 0; nt < 8; nt++)
                    mma_bf16(acc[mt][nt], ah[mt], &bb[nt >> 1][(nt & 1) * 2]); // hi x lo
        }
    };

    load_chunk(0, 0);
    __syncthreads();
    const int nks[4] = {4, 4, 4, 1};
    #pragma unroll 1
    for (int c = 0; c < 4; c++) {
        if (c < 3) load_chunk(c + 1, (c + 1) & 1);
        compute(c & 1, nks[c]);
        __syncthreads();
    }

    // epilogue: max over k (C columns), tanh, store
    #pragma unroll
    for (int mt = 0; mt < 2; mt++) {
        float mxA = -FLT_MAX, mxB = -FLT_MAX;
        #pragma unroll
        for (int nt = 0; nt < 8; nt++) {
            mxA = fmaxf(mxA, fmaxf(acc[mt][nt][0], acc[mt][nt][1]));
            mxB = fmaxf(mxB, fmaxf(acc[mt][nt][2], acc[mt][nt][3]));
        }
        #pragma unroll
        for (int o = 1; o < 4; o <<= 1) {
            mxA = fmaxf(mxA, __shfl_xor_sync(0xffffffffu, mxA, o));
            mxB = fmaxf(mxB, __shfl_xor_sync(0xffffffffu, mxB, o));
        }
        if ((lane & 3) == 0) {
            const int ra = m0 + 16 * mt + (lane >> 2);
            sRED[ra * 2 + wn]       = mxA;
            sRED[(ra + 8) * 2 + wn] = mxB;
        }
    }
    __syncthreads();
    if (tid < 128) {
        const float v = fmaxf(sRED[tid * 2], sRED[tid * 2 + 1]);
        out[((size_t)(b * L + tid)) * OUTC + 21 + m] = tanhf(v);
    }
}

// ---------------------------------------------------------------------------
// Kernel 1: attention projections + lt row norms (unchanged).
// ---------------------------------------------------------------------------
__global__ __launch_bounds__(128) void k_proj(
    const float* __restrict__ lt, const float* __restrict__ rt,
    const float* __restrict__ w1, const float* __restrict__ w2,
    const float* __restrict__ diag)
{
    __shared__ float sX[32][202];
    __shared__ float sD[64];

    const int tile = blockIdx.x, b = blockIdx.y;
    const int t = threadIdx.x;
    const int row0 = b * L + tile * 16;

    for (int idx = t; idx < 3200; idx += 128) {
        const int r = idx / 100, q = idx - r * 100;
        const int gr = row0 + (r & 15);
        const float* src = (r < 16) ? lt : rt;
        *(float2*)&sX[r][2 * q] = *(const float2*)&src[(size_t)gr * D + 2 * q];
    }
    if (t < ATT) sD[t] = diag[t];
    __syncthreads();

    if (t < 100) {
        const bool isLt = (t < 50);
        const int a = isLt ? t : t - 50;
        const float* wsrc = isLt ? w2 : w1;
        const int rbase = isLt ? 0 : 16;

        unsigned long long acc2[16];
        #pragma unroll
        for (int r = 0; r < 16; r++) acc2[r] = 0ull;

        #pragma unroll 2
        for (int d = 0; d < 200; d += 2) {
            const float wlo = wsrc[d * ATT + a];
            const float whi = wsrc[(d + 1) * ATT + a];
            unsigned long long w2r;
            asm("mov.b64 %0, {%1, %2};" : "=l"(w2r) : "f"(wlo), "f"(whi));
            #pragma unroll
            for (int r = 0; r < 16; r++) {
                const unsigned long long x2 =
                    *(const unsigned long long*)&sX[rbase + r][d];
                asm("fma.rn.f32x2 %0, %1, %2, %0;"
                    : "+l"(acc2[r]) : "l"(x2), "l"(w2r));
            }
        }
        #pragma unroll
        for (int r = 0; r < 16; r++) {
            float lo, hi;
            asm("mov.b64 {%0, %1}, %2;" : "=f"(lo), "=f"(hi) : "l"(acc2[r]));
            const float v = tanhf(lo + hi);
            if (isLt) g_e_lt[(size_t)(row0 + r) * ATT + a] = v;
            else      g_e_rt[(size_t)(row0 + r) * ATT + a] = v * sD[a];
        }
    } else if (t < 116) {
        const int r = t - 100;
        float ss = 0.f;
        #pragma unroll 4
        for (int d = 0; d < 200; d += 2) {
            const float2 x = *(const float2*)&sX[r][d];
            ss = fmaf(x.x, x.x, fmaf(x.y, x.y, ss));
        }
        g_nl[row0 + r] = sqrtf(fmaxf(ss, 1e-6f));
    }
}

// ---------------------------------------------------------------------------
// Kernel 3: fused full + attentive + max-attentive match (unchanged).
// ---------------------------------------------------------------------------
__global__ __launch_bounds__(512) void k_match(
    const float* __restrict__ lt, const float* __restrict__ rt,
    const float* __restrict__ fw, const float* __restrict__ bw,
    const float* __restrict__ w_full, const float* __restrict__ w_att,
    const float* __restrict__ w_maxatt, float* __restrict__ out)
{
    extern __shared__ float sm[];
    float* sLT  = sm;            // [128][202]
    float* sRT  = sm + 25856;    // [16][202]
    float* sAT  = sm + 29088;    // [16][202]
    float* sEL  = sm + 32320;    // [128][51]
    float* sER  = sm + 38848;    // [16][51]
    float* sH   = sm + 39664;    // [204]
    float* sW   = sm + 39868;    // [60][224] zero-padded d>=200
    float* sZP  = sm + 53308;    // [16][132]
    float* sNL  = sm + 55420;    // [128]
    int*   sPOS = (int*)(sm + 55548);  // [16]

    const int tile = blockIdx.x, b = blockIdx.y;
    const int t = threadIdx.x;
    const int lane = t & 31, w = t >> 5;     // 16 warps
    const int r0g = tile * 16;
    const float* ltb = lt + (size_t)b * L * D;
    const float* rtb = rt + (size_t)b * L * D;

    for (int idx = t; idx < 12800; idx += 512) {
        const int rr = idx / 100, q = idx - rr * 100;
        *(float2*)&sLT[rr * 202 + 2 * q] = *(const float2*)&ltb[(size_t)rr * D + 2 * q];
    }
    for (int idx = t; idx < 1600; idx += 512) {
        const int rr = idx / 100, q = idx - rr * 100;
        *(float2*)&sRT[rr * 202 + 2 * q] =
            *(const float2*)&rtb[(size_t)(r0g + rr) * D + 2 * q];
    }
    for (int idx = t; idx < 6400; idx += 512) {
        const int l = idx / 50, k = idx - l * 50;
        sEL[l * 51 + k] = g_e_lt[(size_t)b * L * ATT + idx];
    }
    for (int idx = t; idx < 800; idx += 512) {
        const int j = idx / 50, k = idx - j * 50;
        sER[j * 51 + k] = g_e_rt[(size_t)(b * L + r0g) * ATT + idx];
    }
    for (int idx = t; idx < 60 * 224; idx += 512) {
        const int mrow = idx / 224, d = idx - mrow * 224;
        float v = 0.f;
        if (d < 200) {
            if (mrow < 20)      v = w_full[mrow * 200 + d];
            else if (mrow < 40) v = w_att[(mrow - 20) * 200 + d];
            else                v = w_maxatt[(mrow - 40) * 200 + d];
        }
        sW[mrow * 224 + d] = v;
    }
    if (t < 204) { sH[t] = (t < 100) ? fw[b * 100 + t]
                         : (t < 200) ? bw[b * 100 + t - 100] : 0.f; }
    if (t < 128) sNL[t] = g_nl[b * L + t];
    __syncthreads();

    // S = rt_tile @ lt^T
    {
        const int r0 = t >> 6, l0 = t & 63;
        const float* a0 = &sRT[r0 * 202];
        const float* a1 = &sRT[(r0 + 8) * 202];
        const float* b0 = &sLT[l0 * 202];
        const float* b1 = &sLT[(l0 + 64) * 202];
        float c00 = 0.f, c01 = 0.f, c10 = 0.f, c11 = 0.f;
        #pragma unroll 4
        for (int d = 0; d < 200; d += 2) {
            const float2 x0 = *(const float2*)&a0[d];
            const float2 x1 = *(const float2*)&a1[d];
            const float2 y0 = *(const float2*)&b0[d];
            const float2 y1 = *(const float2*)&b1[d];
            c00 = fmaf(x0.x, y0.x, fmaf(x0.y, y0.y, c00));
            c01 = fmaf(x0.x, y1.x, fmaf(x0.y, y1.y, c01));
            c10 = fmaf(x1.x, y0.x, fmaf(x1.y, y0.y, c10));
            c11 = fmaf(x1.x, y1.x, fmaf(x1.y, y1.y, c11));
        }
        sZP[r0 * 132 + l0]            = c00;
        sZP[r0 * 132 + l0 + 64]       = c01;
        sZP[(r0 + 8) * 132 + l0]      = c10;
        sZP[(r0 + 8) * 132 + l0 + 64] = c11;
    }
    __syncthreads();

    // argmax_l S[r][l]/nl[l]
    {
        float bv = -FLT_MAX; int bi = 0;
        #pragma unroll
        for (int q = 0; q < 4; q++) {
            const int l = lane + 32 * q;
            const float v = sZP[w * 132 + l] / sNL[l];
            if (v > bv) { bv = v; bi = l; }
        }
        #pragma unroll
        for (int o = 16; o > 0; o >>= 1) {
            const float ov = __shfl_xor_sync(0xffffffffu, bv, o);
            const int   oi = __shfl_xor_sync(0xffffffffu, bi, o);
            if (ov > bv || (ov == bv && oi < bi)) { bv = ov; bi = oi; }
        }
        if (lane == 0) sPOS[w] = bi;
    }
    __syncthreads();

    // Z = e_rt_tile @ e_lt^T
    {
        const int r0 = t >> 6, l0 = t & 63;
        const float* a0 = &sER[r0 * 51];
        const float* a1 = &sER[(r0 + 8) * 51];
        const float* b0 = &sEL[l0 * 51];
        const float* b1 = &sEL[(l0 + 64) * 51];
        float c00 = 0.f, c01 = 0.f, c10 = 0.f, c11 = 0.f;
        #pragma unroll 5
        for (int k = 0; k < 50; k++) {
            const float x0 = a0[k], x1 = a1[k], y0 = b0[k], y1 = b1[k];
            c00 = fmaf(x0, y0, c00); c01 = fmaf(x0, y1, c01);
            c10 = fmaf(x1, y0, c10); c11 = fmaf(x1, y1, c11);
        }
        sZP[r0 * 132 + l0]            = c00;
        sZP[r0 * 132 + l0 + 64]       = c01;
        sZP[(r0 + 8) * 132 + l0]      = c10;
        sZP[(r0 + 8) * 132 + l0 + 64] = c11;
    }
    __syncthreads();

    // softmax over l (warp w -> row w)
    {
        float zv[4];
        float zm = -FLT_MAX;
        #pragma unroll
        for (int q = 0; q < 4; q++) {
            zv[q] = sZP[w * 132 + lane + 32 * q];
            zm = fmaxf(zm, zv[q]);
        }
        #pragma unroll
        for (int o = 16; o > 0; o >>= 1)
            zm = fmaxf(zm, __shfl_xor_sync(0xffffffffu, zm, o));
        float s = 0.f;
        #pragma unroll
        for (int q = 0; q < 4; q++) { zv[q] = expf(zv[q] - zm); s += zv[q]; }
        #pragma unroll
        for (int o = 16; o > 0; o >>= 1)
            s += __shfl_xor_sync(0xffffffffu, s, o);
        const float inv = 1.0f / s;
        #pragma unroll
        for (int q = 0; q < 4; q++)
            sZP[w * 132 + lane + 32 * q] = zv[q] * inv;
    }
    __syncthreads();

    // att = P @ lt
    {
        const int rg = t >> 6, c = t & 63;
        const bool q3 = (c < 8);
        float a0q[4] = {0.f, 0.f, 0.f, 0.f};
        float a1q[4] = {0.f, 0.f, 0.f, 0.f};
        #pragma unroll 2
        for (int l = 0; l < 128; l++) {
            const float p0 = sZP[rg * 132 + l];
            const float p1 = sZP[(rg + 8) * 132 + l];
            const float* row = &sLT[l * 202 + c];
            const float v0 = row[0], v1 = row[64], v2 = row[128];
            a0q[0] = fmaf(p0, v0, a0q[0]); a1q[0] = fmaf(p1, v0, a1q[0]);
            a0q[1] = fmaf(p0, v1, a0q[1]); a1q[1] = fmaf(p1, v1, a1q[1]);
            a0q[2] = fmaf(p0, v2, a0q[2]); a1q[2] = fmaf(p1, v2, a1q[2]);
            if (q3) {
                const float v3 = row[192];
                a0q[3] = fmaf(p0, v3, a0q[3]); a1q[3] = fmaf(p1, v3, a1q[3]);
            }
        }
        sAT[rg * 202 + c]        = a0q[0]; sAT[(rg + 8) * 202 + c]        = a1q[0];
        sAT[rg * 202 + c + 64]   = a0q[1]; sAT[(rg + 8) * 202 + c + 64]   = a1q[1];
        sAT[rg * 202 + c + 128]  = a0q[2]; sAT[(rg + 8) * 202 + c + 128]  = a1q[2];
        if (q3) { sAT[rg * 202 + c + 192] = a0q[3];
                  sAT[(rg + 8) * 202 + c + 192] = a1q[3]; }
    }
    __syncthreads();

    // epilogue: warp j builds g = U.V, out = tanh(g @ W^T)
    {
        const int j = w;
        const int gr = r0g + j;
        const int pos = sPOS[j];
        float* outrow = out + (size_t)(b * L + gr) * OUTC;

        float gf[7], ga[7], gm[7];
        #pragma unroll
        for (int c = 0; c < 7; c++) {
            const int d = lane + 32 * c;
            const bool ok = (c < 6) || (lane < 8);
            const float xl = ok ? sLT[gr * 202 + d] : 0.f;
            const float xh = ok ? sH[d] : 0.f;
            const float xa = ok ? sAT[j * 202 + d] : 0.f;
            const float xr = ok ? sRT[j * 202 + d] : 0.f;
            const float xp = ok ? sLT[pos * 202 + d] : 0.f;
            gf[c] = xl * xh;
            ga[c] = xa * xr;
            gm[c] = xr * xp;
        }
        {
            float s0 = 0.f, s1 = 0.f, s2 = 0.f;
            #pragma unroll
            for (int c = 0; c < 7; c++) { s0 += gf[c]; s1 += ga[c]; s2 += gm[c]; }
            #pragma unroll
            for (int o = 16; o > 0; o >>= 1) {
                s0 += __shfl_xor_sync(0xffffffffu, s0, o);
                s1 += __shfl_xor_sync(0xffffffffu, s1, o);
                s2 += __shfl_xor_sync(0xffffffffu, s2, o);
            }
            if (lane == 0) {
                outrow[0]  = tanhf(s0);
                outrow[41] = tanhf(s1);
                outrow[62] = tanhf(s2);
            }
        }
        #pragma unroll 2
        for (int m = 0; m < 20; m++) {
            float a0 = 0.f, a1 = 0.f, a2 = 0.f;
            #pragma unroll
            for (int c = 0; c < 7; c++) {
                const int d = lane + 32 * c;
                a0 = fmaf(gf[c], sW[m * 224 + d], a0);
                a1 = fmaf(ga[c], sW[(20 + m) * 224 + d], a1);
                a2 = fmaf(gm[c], sW[(40 + m) * 224 + d], a2);
            }
            #pragma unroll
            for (int o = 16; o > 0; o >>= 1) {
                a0 += __shfl_xor_sync(0xffffffffu, a0, o);
                a1 += __shfl_xor_sync(0xffffffffu, a1, o);
                a2 += __shfl_xor_sync(0xffffffffu, a2, o);
            }
            if (lane == 0) {
                outrow[1 + m]  = tanhf(a0);
                outrow[42 + m] = tanhf(a1);
                outrow[63 + m] = tanhf(a2);
            }
        }
    }
}

// ---------------------------------------------------------------------------
extern "C" void kernel_launch(void* const* d_in, const int* in_sizes, int n_in,
                              void* d_out, int out_size)
{
    const float* reps_lt   = (const float*)d_in[0];
    const float* reps_rt   = (const float*)d_in[1];
    const float* fw_h_rt   = (const float*)d_in[2];
    const float* bw_h_rt   = (const float*)d_in[3];
    const float* w_full    = (const float*)d_in[4];
    const float* w_maxpool = (const float*)d_in[5];
    const float* w_att     = (const float*)d_in[6];
    const float* w_maxatt  = (const float*)d_in[7];
    const float* attn_w1   = (const float*)d_in[8];
    const float* attn_w2   = (const float*)d_in[9];
    const float* diag_w    = (const float*)d_in[10];
    float* out = (float*)d_out;

    const int smem_match = 55564 * 4;   // 222256 B
    cudaFuncSetAttribute(k_match, cudaFuncAttributeMaxDynamicSharedMemorySize, smem_match);
    cudaFuncSetAttribute(k_mp_mma, cudaFuncAttributeMaxDynamicSharedMemorySize, MMA_SMEM_BYTES);

    k_prep<<<B, 256>>>(reps_lt);
    dim3 g2(MP, B); k_mp_mma<<<g2, 256, MMA_SMEM_BYTES>>>(reps_rt, w_maxpool, out);
    dim3 g1(8, B);  k_proj<<<g1, 128>>>(reps_lt, reps_rt, attn_w1, attn_w2, diag_w);
    dim3 g3(8, B);  k_match<<<g3, 512, smem_match>>>(reps_lt, reps_rt, fw_h_rt, bw_h_rt,
                                                     w_full, w_att, w_maxatt, out);
}

// round 9
// speedup vs baseline: 2.1856x; 1.3140x over previous
#include <cuda_runtime.h>
#include <cuda_bf16.h>
#include <math.h>
#include <float.h>

// Shapes (fixed by the problem)
#define B 64
#define L 128
#define D 200
#define MP 20
#define ATT 50
#define OUTC 83   // 21 + 20 + 21 + 21

// ---------------------------------------------------------------------------
// Scratch (device globals; no allocations allowed)
// ---------------------------------------------------------------------------
__device__ float g_e_lt[B * L * ATT];       // tanh(lt @ w2)             [b,l,a]
__device__ float g_e_rt[B * L * ATT];       // tanh(rt @ w1) * diag      [b,r,a]
__device__ float g_nl[B * L];               // sqrt(max(|lt_l|^2, EPS))  [b,l]
__device__ int   g_pos[B * L];              // argmax_l rel[r][l]        [b,r]
__device__ unsigned g_lt_hi2[B * L * 128];  // lt bf16 hi, packed pairs, Kpad=256
__device__ unsigned g_lt_lo2[B * L * 128];  // lt bf16 lo

// ---------------------------------------------------------------------------
// Helpers (base-PTX only: ldmatrix sm_75+, mma.sync bf16 sm_80+, cp.async sm_80+)
// ---------------------------------------------------------------------------
__device__ __forceinline__ unsigned smem_u32(const void* p) {
    unsigned a;
    asm("{ .reg .u64 t; cvta.to.shared.u64 t, %1; cvt.u32.u64 %0, t; }"
        : "=r"(a) : "l"(p));
    return a;
}
__device__ __forceinline__ void ldsm_x4(unsigned* r, unsigned addr) {
    asm volatile("ldmatrix.sync.aligned.m8n8.x4.shared.b16 {%0,%1,%2,%3}, [%4];"
                 : "=r"(r[0]), "=r"(r[1]), "=r"(r[2]), "=r"(r[3]) : "r"(addr));
}
__device__ __forceinline__ void mma_bf16(float* c, const unsigned* a,
                                         const unsigned* b) {
    asm volatile(
        "mma.sync.aligned.m16n8k16.row.col.f32.bf16.bf16.f32 "
        "{%0,%1,%2,%3}, {%4,%5,%6,%7}, {%8,%9}, {%0,%1,%2,%3};"
        : "+f"(c[0]), "+f"(c[1]), "+f"(c[2]), "+f"(c[3])
        : "r"(a[0]), "r"(a[1]), "r"(a[2]), "r"(a[3]), "r"(b[0]), "r"(b[1]));
}
__device__ __forceinline__ void cp_async16(unsigned dst, const void* src) {
    asm volatile("cp.async.ca.shared.global [%0], [%1], 16;"
                 :: "r"(dst), "l"(src) : "memory");
}
__device__ __forceinline__ void cp_async_wait_all() {
    asm volatile("cp.async.commit_group;\ncp.async.wait_group 0;" ::: "memory");
}
// byte offset of bf16 element (r, k) inside a [128][64] bf16 plane,
// XOR-swizzled so ldmatrix (8 rows x 16B) is bank-conflict-free.
__device__ __forceinline__ unsigned offp(int r, int k) {
    return (unsigned)(r * 128 + ((((k >> 3) ^ (r & 7)) & 7) << 4) + ((k & 7) << 1));
}

// ---------------------------------------------------------------------------
// Kernel 0: bf16 hi/lo split of lt (Kpad=256, zero-padded), packed pairs.
// ---------------------------------------------------------------------------
__global__ __launch_bounds__(256) void k_prep(const float* __restrict__ lt)
{
    const int b = blockIdx.x;
    for (int idx = threadIdx.x; idx < L * 128; idx += 256) {
        const int r = idx >> 7, kk = idx & 127, k = kk * 2;
        const float* rr = lt + ((size_t)(b * L + r)) * D;
        const float f0 = (k < 200) ? rr[k] : 0.f;
        const float f1 = (k + 1 < 200) ? rr[k + 1] : 0.f;
        __nv_bfloat162 h = __floats2bfloat162_rn(f0, f1);
        const float h0 = __low2float(h), h1 = __high2float(h);
        __nv_bfloat162 l = __floats2bfloat162_rn(f0 - h0, f1 - h1);
        const unsigned gi = (unsigned)(((b * L + r) << 7) + kk);
        g_lt_hi2[gi] = *(unsigned*)&h;
        g_lt_lo2[gi] = *(unsigned*)&l;
    }
}

// ---------------------------------------------------------------------------
// Kernel 1: attention projections + lt row norms (unchanged).
// ---------------------------------------------------------------------------
__global__ __launch_bounds__(128) void k_proj(
    const float* __restrict__ lt, const float* __restrict__ rt,
    const float* __restrict__ w1, const float* __restrict__ w2,
    const float* __restrict__ diag)
{
    __shared__ float sX[32][202];
    __shared__ float sD[64];

    const int tile = blockIdx.x, b = blockIdx.y;
    const int t = threadIdx.x;
    const int row0 = b * L + tile * 16;

    for (int idx = t; idx < 3200; idx += 128) {
        const int r = idx / 100, q = idx - r * 100;
        const int gr = row0 + (r & 15);
        const float* src = (r < 16) ? lt : rt;
        *(float2*)&sX[r][2 * q] = *(const float2*)&src[(size_t)gr * D + 2 * q];
    }
    if (t < ATT) sD[t] = diag[t];
    __syncthreads();

    if (t < 100) {
        const bool isLt = (t < 50);
        const int a = isLt ? t : t - 50;
        const float* wsrc = isLt ? w2 : w1;
        const int rbase = isLt ? 0 : 16;

        unsigned long long acc2[16];
        #pragma unroll
        for (int r = 0; r < 16; r++) acc2[r] = 0ull;

        #pragma unroll 2
        for (int d = 0; d < 200; d += 2) {
            const float wlo = wsrc[d * ATT + a];
            const float whi = wsrc[(d + 1) * ATT + a];
            unsigned long long w2r;
            asm("mov.b64 %0, {%1, %2};" : "=l"(w2r) : "f"(wlo), "f"(whi));
            #pragma unroll
            for (int r = 0; r < 16; r++) {
                const unsigned long long x2 =
                    *(const unsigned long long*)&sX[rbase + r][d];
                asm("fma.rn.f32x2 %0, %1, %2, %0;"
                    : "+l"(acc2[r]) : "l"(x2), "l"(w2r));
            }
        }
        #pragma unroll
        for (int r = 0; r < 16; r++) {
            float lo, hi;
            asm("mov.b64 {%0, %1}, %2;" : "=f"(lo), "=f"(hi) : "l"(acc2[r]));
            const float v = tanhf(lo + hi);
            if (isLt) g_e_lt[(size_t)(row0 + r) * ATT + a] = v;
            else      g_e_rt[(size_t)(row0 + r) * ATT + a] = v * sD[a];
        }
    } else if (t < 116) {
        const int r = t - 100;
        float ss = 0.f;
        #pragma unroll 4
        for (int d = 0; d < 200; d += 2) {
            const float2 x = *(const float2*)&sX[r][d];
            ss = fmaf(x.x, x.x, fmaf(x.y, x.y, ss));
        }
        g_nl[row0 + r] = sqrtf(fmaxf(ss, 1e-6f));
    }
}

// ---------------------------------------------------------------------------
// Kernel 1b: fp32 S = rt @ lt^T per batch, argmax_l S[r][l]/nl[l] -> g_pos.
// FFMA2 GEMM skeleton from the round-2 k_maxpool (known good); argmax epilogue
// scans in ascending-l order with strict '>' => first-occurrence tie-break.
// One CTA per b (128x128 tile, K=200). fp32 keeps argmax flip-safe.
// ---------------------------------------------------------------------------
__global__ __launch_bounds__(256, 2) void k_s(
    const float* __restrict__ rt, const float* __restrict__ lt)
{
    const int b = blockIdx.x;

    __shared__ float Asd[2][8][260];   // duplicated A (rt) rows
    __shared__ float Bs[2][8][132];    // B (lt) rows
    __shared__ float red_v[128][17];
    __shared__ int   red_i[128][17];
    __shared__ float sINL[128];

    const float* ab = rt + (size_t)b * L * D;
    const float* bbp = lt + (size_t)b * L * D;

    const int tid = threadIdx.x;
    const int ty = tid >> 4, tx = tid & 15;
    const int lr = tid >> 1, lc = (tid & 1) * 4;

    if (tid < 128) sINL[tid] = 1.0f / g_nl[b * L + tid];

    unsigned long long acc[8][4];
    #pragma unroll
    for (int i = 0; i < 8; i++)
        #pragma unroll
        for (int j = 0; j < 4; j++) acc[i][j] = 0ull;

    float4 ra, rb;
    auto ld_regs = [&](int k0) {
        ra = *reinterpret_cast<const float4*>(ab + lr * D + k0 + lc);
        rb = *reinterpret_cast<const float4*>(bbp + lr * D + k0 + lc);
    };
    auto st_smem = [&](int bf) {
        *reinterpret_cast<float2*>(&Asd[bf][lc + 0][2 * lr]) = make_float2(ra.x, ra.x);
        *reinterpret_cast<float2*>(&Asd[bf][lc + 1][2 * lr]) = make_float2(ra.y, ra.y);
        *reinterpret_cast<float2*>(&Asd[bf][lc + 2][2 * lr]) = make_float2(ra.z, ra.z);
        *reinterpret_cast<float2*>(&Asd[bf][lc + 3][2 * lr]) = make_float2(ra.w, ra.w);
        Bs[bf][lc + 0][lr] = rb.x; Bs[bf][lc + 1][lr] = rb.y;
        Bs[bf][lc + 2][lr] = rb.z; Bs[bf][lc + 3][lr] = rb.w;
    };
    auto compute = [&](int bf) {
        #pragma unroll
        for (int kk = 0; kk < 8; kk++) {
            unsigned long long a2[8], b2[4];
            #pragma unroll
            for (int q = 0; q < 4; q++) {
                ulonglong2 v = *reinterpret_cast<const ulonglong2*>(
                    &Asd[bf][kk][2 * (ty * 8 + 2 * q)]);
                a2[2 * q] = v.x; a2[2 * q + 1] = v.y;
            }
            {
                ulonglong2 v0 = *reinterpret_cast<const ulonglong2*>(&Bs[bf][kk][8 * tx]);
                ulonglong2 v1 = *reinterpret_cast<const ulonglong2*>(&Bs[bf][kk][8 * tx + 4]);
                b2[0] = v0.x; b2[1] = v0.y; b2[2] = v1.x; b2[3] = v1.y;
            }
            #pragma unroll
            for (int i = 0; i < 8; i++)
                #pragma unroll
                for (int j = 0; j < 4; j++)
                    asm("fma.rn.f32x2 %0, %1, %2, %0;"
                        : "+l"(acc[i][j]) : "l"(a2[i]), "l"(b2[j]));
        }
    };

    ld_regs(0);
    st_smem(0);
    __syncthreads();
    #pragma unroll 1
    for (int kt = 1; kt < 25; kt++) {
        ld_regs(kt * 8);
        compute((kt - 1) & 1);
        st_smem(kt & 1);
        __syncthreads();
    }
    compute(0);

    // argmax over columns l = 8*tx + 2*j + e (scaled by 1/nl[l])
    #pragma unroll
    for (int i = 0; i < 8; i++) {
        float bv = -FLT_MAX; int bi = 0;
        #pragma unroll
        for (int j = 0; j < 4; j++) {
            const int l0 = 8 * tx + 2 * j;
            const unsigned long long v = acc[i][j];
            const float lo = __uint_as_float((unsigned)(v & 0xffffffffull)) * sINL[l0];
            const float hi = __uint_as_float((unsigned)(v >> 32)) * sINL[l0 + 1];
            if (lo > bv) { bv = lo; bi = l0; }
            if (hi > bv) { bv = hi; bi = l0 + 1; }
        }
        red_v[ty * 8 + i][tx] = bv;
        red_i[ty * 8 + i][tx] = bi;
    }
    __syncthreads();
    if (tid < 128) {
        float v = red_v[tid][0]; int idx = red_i[tid][0];
        #pragma unroll
        for (int x = 1; x < 16; x++)
            if (red_v[tid][x] > v) { v = red_v[tid][x]; idx = red_i[tid][x]; }
        g_pos[b * L + tid] = idx;
    }
}

// ---------------------------------------------------------------------------
// Kernel 2: maxpool match via mma.sync (bf16 split, fp32 accum).
// Single-buffered (67 KB smem) with __launch_bounds__(256,2): overlap now
// comes from 2 CTAs/SM instead of an intra-CTA "pipeline" that never
// overlapped. A-plane fills use cp.async 16B (swizzle is 16B-granular).
// ---------------------------------------------------------------------------
#define MMA_SMEM_BYTES 67456   // 65536 planes + 896 sW + 1024 sRED
__global__ __launch_bounds__(256, 2) void k_mp_mma(
    const float* __restrict__ rt, const float* __restrict__ wmp,
    float* __restrict__ out)
{
    extern __shared__ char smem[];
    const unsigned sb = smem_u32(smem);
    float* sW   = (float*)(smem + 65536);   // [224] w row, zero-padded
    float* sRED = (float*)(smem + 66432);   // [128][2]

    const int m = blockIdx.x, b = blockIdx.y;
    const int tid = threadIdx.x, wid = tid >> 5, lane = tid & 31;
    const int m0 = (wid & 3) * 32, n0 = (wid >> 2) * 64, wn = wid >> 2;

    // plane byte offsets: 0:A_hi 16384:A_lo 32768:B_hi 49152:B_lo
    for (int d = tid; d < 224; d += 256) sW[d] = (d < 200) ? wmp[m * 200 + d] : 0.f;
    __syncthreads();

    auto load_chunk = [&](int c) {
        // A planes via cp.async 16B (4 packed pairs = 8 bf16 = one swizzle atom)
        for (int idx = tid; idx < 1024; idx += 256) {
            const int r = idx >> 3, kk4 = (idx & 7) * 4;
            const unsigned gi = (unsigned)(((b * L + r) << 7) + c * 32 + kk4);
            const unsigned o = offp(r, 2 * kk4);
            cp_async16(sb + o,         &g_lt_hi2[gi]);
            cp_async16(sb + 16384 + o, &g_lt_lo2[gi]);
        }
        // B planes: (w (.) rt) converted + split on the fly
        for (int idx = tid; idx < 4096; idx += 256) {
            const int r = idx >> 5, kk = idx & 31;
            const int k = c * 64 + 2 * kk;
            float f0 = 0.f, f1 = 0.f;
            if (k < 200) {
                const float2 v = *(const float2*)&rt[(size_t)(b * L + r) * D + k];
                f0 = v.x * sW[k];
                f1 = (k + 1 < 200) ? v.y * sW[k + 1] : 0.f;
            }
            __nv_bfloat162 h = __floats2bfloat162_rn(f0, f1);
            const float h0 = __low2float(h), h1 = __high2float(h);
            __nv_bfloat162 l = __floats2bfloat162_rn(f0 - h0, f1 - h1);
            const unsigned o = offp(r, 2 * kk);
            *(unsigned*)(smem + 32768 + o) = *(unsigned*)&h;
            *(unsigned*)(smem + 49152 + o) = *(unsigned*)&l;
        }
        cp_async_wait_all();
    };

    float acc[2][8][4];
    #pragma unroll
    for (int mt = 0; mt < 2; mt++)
        #pragma unroll
        for (int nt = 0; nt < 8; nt++)
            #pragma unroll
            for (int q = 0; q < 4; q++) acc[mt][nt][q] = 0.f;

    auto compute = [&](int nk) {
        for (int ks = 0; ks < nk; ks++) {
            unsigned ah[2][4], al[2][4], bb[4][4];
            const int kca = ks * 16 + ((lane >> 4) << 3);
            #pragma unroll
            for (int mt = 0; mt < 2; mt++) {
                const int row = m0 + 16 * mt + (lane & 15);
                ldsm_x4(ah[mt], sb + offp(row, kca));
                ldsm_x4(al[mt], sb + 16384 + offp(row, kca));
            }
            const int kcb = ks * 16 + (((lane >> 3) & 1) << 3);
            const int rowb = (lane & 7) + ((lane >> 4) << 3);
            #pragma unroll
            for (int nt2 = 0; nt2 < 4; nt2++)
                ldsm_x4(bb[nt2], sb + 32768 + offp(n0 + nt2 * 16 + rowb, kcb));
            #pragma unroll
            for (int mt = 0; mt < 2; mt++)
                #pragma unroll
                for (int nt = 0; nt < 8; nt++) {
                    const unsigned* bp = &bb[nt >> 1][(nt & 1) * 2];
                    mma_bf16(acc[mt][nt], ah[mt], bp);   // hi x hi
                    mma_bf16(acc[mt][nt], al[mt], bp);   // lo x hi
                }
            #pragma unroll
            for (int nt2 = 0; nt2 < 4; nt2++)
                ldsm_x4(bb[nt2], sb + 49152 + offp(n0 + nt2 * 16 + rowb, kcb));
            #pragma unroll
            for (int mt = 0; mt < 2; mt++)
                #pragma unroll
                for (int nt = 0; nt < 8; nt++)
                    mma_bf16(acc[mt][nt], ah[mt], &bb[nt >> 1][(nt & 1) * 2]); // hi x lo
        }
    };

    const int nks[4] = {4, 4, 4, 1};
    #pragma unroll 1
    for (int c = 0; c < 4; c++) {
        load_chunk(c);
        __syncthreads();
        compute(nks[c]);
        __syncthreads();
    }

    // epilogue: max over k (C columns), tanh, store
    #pragma unroll
    for (int mt = 0; mt < 2; mt++) {
        float mxA = -FLT_MAX, mxB = -FLT_MAX;
        #pragma unroll
        for (int nt = 0; nt < 8; nt++) {
            mxA = fmaxf(mxA, fmaxf(acc[mt][nt][0], acc[mt][nt][1]));
            mxB = fmaxf(mxB, fmaxf(acc[mt][nt][2], acc[mt][nt][3]));
        }
        #pragma unroll
        for (int o = 1; o < 4; o <<= 1) {
            mxA = fmaxf(mxA, __shfl_xor_sync(0xffffffffu, mxA, o));
            mxB = fmaxf(mxB, __shfl_xor_sync(0xffffffffu, mxB, o));
        }
        if ((lane & 3) == 0) {
            const int ra = m0 + 16 * mt + (lane >> 2);
            sRED[ra * 2 + wn]       = mxA;
            sRED[(ra + 8) * 2 + wn] = mxB;
        }
    }
    __syncthreads();
    if (tid < 128) {
        const float v = fmaxf(sRED[tid * 2], sRED[tid * 2 + 1]);
        out[((size_t)(b * L + tid)) * OUTC + 21 + m] = tanhf(v);
    }
}

// ---------------------------------------------------------------------------
// Kernel 3: fused full + attentive + max-attentive match (v2: S-GEMM and
// argmax removed; pos comes precomputed from k_s via g_pos).
// ---------------------------------------------------------------------------
__global__ __launch_bounds__(512) void k_match(
    const float* __restrict__ lt, const float* __restrict__ rt,
    const float* __restrict__ fw, const float* __restrict__ bw,
    const float* __restrict__ w_full, const float* __restrict__ w_att,
    const float* __restrict__ w_maxatt, float* __restrict__ out)
{
    extern __shared__ float sm[];
    float* sLT  = sm;            // [128][202]
    float* sRT  = sm + 25856;    // [16][202]
    float* sAT  = sm + 29088;    // [16][202]
    float* sEL  = sm + 32320;    // [128][51]
    float* sER  = sm + 38848;    // [16][51]
    float* sH   = sm + 39664;    // [204]
    float* sW   = sm + 39868;    // [60][224] zero-padded d>=200
    float* sZP  = sm + 53308;    // [16][132]
    int*   sPOS = (int*)(sm + 55420);  // [16]
    // total <= 55564 floats = 222256 B

    const int tile = blockIdx.x, b = blockIdx.y;
    const int t = threadIdx.x;
    const int lane = t & 31, w = t >> 5;     // 16 warps
    const int r0g = tile * 16;
    const float* ltb = lt + (size_t)b * L * D;
    const float* rtb = rt + (size_t)b * L * D;

    for (int idx = t; idx < 12800; idx += 512) {
        const int rr = idx / 100, q = idx - rr * 100;
        *(float2*)&sLT[rr * 202 + 2 * q] = *(const float2*)&ltb[(size_t)rr * D + 2 * q];
    }
    for (int idx = t; idx < 1600; idx += 512) {
        const int rr = idx / 100, q = idx - rr * 100;
        *(float2*)&sRT[rr * 202 + 2 * q] =
            *(const float2*)&rtb[(size_t)(r0g + rr) * D + 2 * q];
    }
    for (int idx = t; idx < 6400; idx += 512) {
        const int l = idx / 50, k = idx - l * 50;
        sEL[l * 51 + k] = g_e_lt[(size_t)b * L * ATT + idx];
    }
    for (int idx = t; idx < 800; idx += 512) {
        const int j = idx / 50, k = idx - j * 50;
        sER[j * 51 + k] = g_e_rt[(size_t)(b * L + r0g) * ATT + idx];
    }
    for (int idx = t; idx < 60 * 224; idx += 512) {
        const int mrow = idx / 224, d = idx - mrow * 224;
        float v = 0.f;
        if (d < 200) {
            if (mrow < 20)      v = w_full[mrow * 200 + d];
            else if (mrow < 40) v = w_att[(mrow - 20) * 200 + d];
            else                v = w_maxatt[(mrow - 40) * 200 + d];
        }
        sW[mrow * 224 + d] = v;
    }
    if (t < 204) { sH[t] = (t < 100) ? fw[b * 100 + t]
                         : (t < 200) ? bw[b * 100 + t - 100] : 0.f; }
    if (t < 16) sPOS[t] = g_pos[b * L + r0g + t];
    __syncthreads();

    // Z = e_rt_tile @ e_lt^T
    {
        const int r0 = t >> 6, l0 = t & 63;
        const float* a0 = &sER[r0 * 51];
        const float* a1 = &sER[(r0 + 8) * 51];
        const float* b0 = &sEL[l0 * 51];
        const float* b1 = &sEL[(l0 + 64) * 51];
        float c00 = 0.f, c01 = 0.f, c10 = 0.f, c11 = 0.f;
        #pragma unroll 5
        for (int k = 0; k < 50; k++) {
            const float x0 = a0[k], x1 = a1[k], y0 = b0[k], y1 = b1[k];
            c00 = fmaf(x0, y0, c00); c01 = fmaf(x0, y1, c01);
            c10 = fmaf(x1, y0, c10); c11 = fmaf(x1, y1, c11);
        }
        sZP[r0 * 132 + l0]            = c00;
        sZP[r0 * 132 + l0 + 64]       = c01;
        sZP[(r0 + 8) * 132 + l0]      = c10;
        sZP[(r0 + 8) * 132 + l0 + 64] = c11;
    }
    __syncthreads();

    // softmax over l (warp w -> row w)
    {
        float zv[4];
        float zm = -FLT_MAX;
        #pragma unroll
        for (int q = 0; q < 4; q++) {
            zv[q] = sZP[w * 132 + lane + 32 * q];
            zm = fmaxf(zm, zv[q]);
        }
        #pragma unroll
        for (int o = 16; o > 0; o >>= 1)
            zm = fmaxf(zm, __shfl_xor_sync(0xffffffffu, zm, o));
        float s = 0.f;
        #pragma unroll
        for (int q = 0; q < 4; q++) { zv[q] = expf(zv[q] - zm); s += zv[q]; }
        #pragma unroll
        for (int o = 16; o > 0; o >>= 1)
            s += __shfl_xor_sync(0xffffffffu, s, o);
        const float inv = 1.0f / s;
        #pragma unroll
        for (int q = 0; q < 4; q++)
            sZP[w * 132 + lane + 32 * q] = zv[q] * inv;
    }
    __syncthreads();

    // att = P @ lt
    {
        const int rg = t >> 6, c = t & 63;
        const bool q3 = (c < 8);
        float a0q[4] = {0.f, 0.f, 0.f, 0.f};
        float a1q[4] = {0.f, 0.f, 0.f, 0.f};
        #pragma unroll 2
        for (int l = 0; l < 128; l++) {
            const float p0 = sZP[rg * 132 + l];
            const float p1 = sZP[(rg + 8) * 132 + l];
            const float* row = &sLT[l * 202 + c];
            const float v0 = row[0], v1 = row[64], v2 = row[128];
            a0q[0] = fmaf(p0, v0, a0q[0]); a1q[0] = fmaf(p1, v0, a1q[0]);
            a0q[1] = fmaf(p0, v1, a0q[1]); a1q[1] = fmaf(p1, v1, a1q[1]);
            a0q[2] = fmaf(p0, v2, a0q[2]); a1q[2] = fmaf(p1, v2, a1q[2]);
            if (q3) {
                const float v3 = row[192];
                a0q[3] = fmaf(p0, v3, a0q[3]); a1q[3] = fmaf(p1, v3, a1q[3]);
            }
        }
        sAT[rg * 202 + c]        = a0q[0]; sAT[(rg + 8) * 202 + c]        = a1q[0];
        sAT[rg * 202 + c + 64]   = a0q[1]; sAT[(rg + 8) * 202 + c + 64]   = a1q[1];
        sAT[rg * 202 + c + 128]  = a0q[2]; sAT[(rg + 8) * 202 + c + 128]  = a1q[2];
        if (q3) { sAT[rg * 202 + c + 192] = a0q[3];
                  sAT[(rg + 8) * 202 + c + 192] = a1q[3]; }
    }
    __syncthreads();

    // epilogue: warp j builds g = U.V, out = tanh(g @ W^T)
    {
        const int j = w;
        const int gr = r0g + j;
        const int pos = sPOS[j];
        float* outrow = out + (size_t)(b * L + gr) * OUTC;

        float gf[7], ga[7], gm[7];
        #pragma unroll
        for (int c = 0; c < 7; c++) {
            const int d = lane + 32 * c;
            const bool ok = (c < 6) || (lane < 8);
            const float xl = ok ? sLT[gr * 202 + d] : 0.f;
            const float xh = ok ? sH[d] : 0.f;
            const float xa = ok ? sAT[j * 202 + d] : 0.f;
            const float xr = ok ? sRT[j * 202 + d] : 0.f;
            const float xp = ok ? sLT[pos * 202 + d] : 0.f;
            gf[c] = xl * xh;
            ga[c] = xa * xr;
            gm[c] = xr * xp;
        }
        {
            float s0 = 0.f, s1 = 0.f, s2 = 0.f;
            #pragma unroll
            for (int c = 0; c < 7; c++) { s0 += gf[c]; s1 += ga[c]; s2 += gm[c]; }
            #pragma unroll
            for (int o = 16; o > 0; o >>= 1) {
                s0 += __shfl_xor_sync(0xffffffffu, s0, o);
                s1 += __shfl_xor_sync(0xffffffffu, s1, o);
                s2 += __shfl_xor_sync(0xffffffffu, s2, o);
            }
            if (lane == 0) {
                outrow[0]  = tanhf(s0);
                outrow[41] = tanhf(s1);
                outrow[62] = tanhf(s2);
            }
        }
        #pragma unroll 2
        for (int m = 0; m < 20; m++) {
            float a0 = 0.f, a1 = 0.f, a2 = 0.f;
            #pragma unroll
            for (int c = 0; c < 7; c++) {
                const int d = lane + 32 * c;
                a0 = fmaf(gf[c], sW[m * 224 + d], a0);
                a1 = fmaf(ga[c], sW[(20 + m) * 224 + d], a1);
                a2 = fmaf(gm[c], sW[(40 + m) * 224 + d], a2);
            }
            #pragma unroll
            for (int o = 16; o > 0; o >>= 1) {
                a0 += __shfl_xor_sync(0xffffffffu, a0, o);
                a1 += __shfl_xor_sync(0xffffffffu, a1, o);
                a2 += __shfl_xor_sync(0xffffffffu, a2, o);
            }
            if (lane == 0) {
                outrow[1 + m]  = tanhf(a0);
                outrow[42 + m] = tanhf(a1);
                outrow[63 + m] = tanhf(a2);
            }
        }
    }
}

// ---------------------------------------------------------------------------
extern "C" void kernel_launch(void* const* d_in, const int* in_sizes, int n_in,
                              void* d_out, int out_size)
{
    const float* reps_lt   = (const float*)d_in[0];
    const float* reps_rt   = (const float*)d_in[1];
    const float* fw_h_rt   = (const float*)d_in[2];
    const float* bw_h_rt   = (const float*)d_in[3];
    const float* w_full    = (const float*)d_in[4];
    const float* w_maxpool = (const float*)d_in[5];
    const float* w_att     = (const float*)d_in[6];
    const float* w_maxatt  = (const float*)d_in[7];
    const float* attn_w1   = (const float*)d_in[8];
    const float* attn_w2   = (const float*)d_in[9];
    const float* diag_w    = (const float*)d_in[10];
    float* out = (float*)d_out;

    const int smem_match = 55564 * 4;   // 222256 B
    cudaFuncSetAttribute(k_match, cudaFuncAttributeMaxDynamicSharedMemorySize, smem_match);
    cudaFuncSetAttribute(k_mp_mma, cudaFuncAttributeMaxDynamicSharedMemorySize, MMA_SMEM_BYTES);

    k_prep<<<B, 256>>>(reps_lt);
    dim3 g1(8, B);  k_proj<<<g1, 128>>>(reps_lt, reps_rt, attn_w1, attn_w2, diag_w);
    k_s<<<B, 256>>>(reps_rt, reps_lt);
    dim3 g2(MP, B); k_mp_mma<<<g2, 256, MMA_SMEM_BYTES>>>(reps_rt, w_maxpool, out);
    dim3 g3(8, B);  k_match<<<g3, 512, smem_match>>>(reps_lt, reps_rt, fw_h_rt, bw_h_rt,
                                                     w_full, w_att, w_maxatt, out);
}

// round 10
// speedup vs baseline: 2.5686x; 1.1753x over previous
#include <cuda_runtime.h>
#include <cuda_bf16.h>
#include <math.h>
#include <float.h>

// Shapes (fixed by the problem)
#define B 64
#define L 128
#define D 200
#define MP 20
#define ATT 50
#define OUTC 83   // 21 + 20 + 21 + 21

// ---------------------------------------------------------------------------
// Scratch (device globals; no allocations allowed)
// ---------------------------------------------------------------------------
__device__ float g_e_lt[B * L * ATT];       // tanh(lt @ w2)             [b,l,a]
__device__ float g_e_rt[B * L * ATT];       // tanh(rt @ w1) * diag      [b,r,a]
__device__ float g_nl[B * L];               // sqrt(max(|lt_l|^2, EPS))  [b,l]
__device__ int   g_pos[B * L];              // argmax_l rel[r][l]        [b,r]
__device__ float g_att[B * L * D];          // attention-weighted lt     [b,r,d]
__device__ unsigned g_lt_hi2[B * L * 128];  // lt bf16 hi, packed pairs, Kpad=256
__device__ unsigned g_lt_lo2[B * L * 128];  // lt bf16 lo

// ---------------------------------------------------------------------------
// Helpers (base-PTX only: ldmatrix sm_75+, mma.sync bf16 sm_80+, cp.async sm_80+)
// ---------------------------------------------------------------------------
__device__ __forceinline__ unsigned smem_u32(const void* p) {
    unsigned a;
    asm("{ .reg .u64 t; cvta.to.shared.u64 t, %1; cvt.u32.u64 %0, t; }"
        : "=r"(a) : "l"(p));
    return a;
}
__device__ __forceinline__ void ldsm_x4(unsigned* r, unsigned addr) {
    asm volatile("ldmatrix.sync.aligned.m8n8.x4.shared.b16 {%0,%1,%2,%3}, [%4];"
                 : "=r"(r[0]), "=r"(r[1]), "=r"(r[2]), "=r"(r[3]) : "r"(addr));
}
__device__ __forceinline__ void mma_bf16(float* c, const unsigned* a,
                                         const unsigned* b) {
    asm volatile(
        "mma.sync.aligned.m16n8k16.row.col.f32.bf16.bf16.f32 "
        "{%0,%1,%2,%3}, {%4,%5,%6,%7}, {%8,%9}, {%0,%1,%2,%3};"
        : "+f"(c[0]), "+f"(c[1]), "+f"(c[2]), "+f"(c[3])
        : "r"(a[0]), "r"(a[1]), "r"(a[2]), "r"(a[3]), "r"(b[0]), "r"(b[1]));
}
__device__ __forceinline__ void cp_async16(unsigned dst, const void* src) {
    asm volatile("cp.async.ca.shared.global [%0], [%1], 16;"
                 :: "r"(dst), "l"(src) : "memory");
}
__device__ __forceinline__ void cp_async_commit() {
    asm volatile("cp.async.commit_group;" ::: "memory");
}
template <int N> __device__ __forceinline__ void cp_async_wait() {
    asm volatile("cp.async.wait_group %0;" :: "n"(N) : "memory");
}
__device__ __forceinline__ void cp_async_wait_all() {
    asm volatile("cp.async.commit_group;\ncp.async.wait_group 0;" ::: "memory");
}
// byte offset of bf16 element (r, k) inside a [128][64] bf16 plane,
// XOR-swizzled so ldmatrix (8 rows x 16B) is bank-conflict-free.
__device__ __forceinline__ unsigned offp(int r, int k) {
    return (unsigned)(r * 128 + ((((k >> 3) ^ (r & 7)) & 7) << 4) + ((k & 7) << 1));
}

// ---------------------------------------------------------------------------
// Kernel 0: bf16 hi/lo split of lt (Kpad=256, zero-padded), packed pairs.
// ---------------------------------------------------------------------------
__global__ __launch_bounds__(256) void k_prep(const float* __restrict__ lt)
{
    const int b = blockIdx.x;
    for (int idx = threadIdx.x; idx < L * 128; idx += 256) {
        const int r = idx >> 7, kk = idx & 127, k = kk * 2;
        const float* rr = lt + ((size_t)(b * L + r)) * D;
        const float f0 = (k < 200) ? rr[k] : 0.f;
        const float f1 = (k + 1 < 200) ? rr[k + 1] : 0.f;
        __nv_bfloat162 h = __floats2bfloat162_rn(f0, f1);
        const float h0 = __low2float(h), h1 = __high2float(h);
        __nv_bfloat162 l = __floats2bfloat162_rn(f0 - h0, f1 - h1);
        const unsigned gi = (unsigned)(((b * L + r) << 7) + kk);
        g_lt_hi2[gi] = *(unsigned*)&h;
        g_lt_lo2[gi] = *(unsigned*)&l;
    }
}

// ---------------------------------------------------------------------------
// Kernel 1: attention projections + lt row norms (unchanged).
// ---------------------------------------------------------------------------
__global__ __launch_bounds__(128) void k_proj(
    const float* __restrict__ lt, const float* __restrict__ rt,
    const float* __restrict__ w1, const float* __restrict__ w2,
    const float* __restrict__ diag)
{
    __shared__ float sX[32][202];
    __shared__ float sD[64];

    const int tile = blockIdx.x, b = blockIdx.y;
    const int t = threadIdx.x;
    const int row0 = b * L + tile * 16;

    for (int idx = t; idx < 3200; idx += 128) {
        const int r = idx / 100, q = idx - r * 100;
        const int gr = row0 + (r & 15);
        const float* src = (r < 16) ? lt : rt;
        *(float2*)&sX[r][2 * q] = *(const float2*)&src[(size_t)gr * D + 2 * q];
    }
    if (t < ATT) sD[t] = diag[t];
    __syncthreads();

    if (t < 100) {
        const bool isLt = (t < 50);
        const int a = isLt ? t : t - 50;
        const float* wsrc = isLt ? w2 : w1;
        const int rbase = isLt ? 0 : 16;

        unsigned long long acc2[16];
        #pragma unroll
        for (int r = 0; r < 16; r++) acc2[r] = 0ull;

        #pragma unroll 2
        for (int d = 0; d < 200; d += 2) {
            const float wlo = wsrc[d * ATT + a];
            const float whi = wsrc[(d + 1) * ATT + a];
            unsigned long long w2r;
            asm("mov.b64 %0, {%1, %2};" : "=l"(w2r) : "f"(wlo), "f"(whi));
            #pragma unroll
            for (int r = 0; r < 16; r++) {
                const unsigned long long x2 =
                    *(const unsigned long long*)&sX[rbase + r][d];
                asm("fma.rn.f32x2 %0, %1, %2, %0;"
                    : "+l"(acc2[r]) : "l"(x2), "l"(w2r));
            }
        }
        #pragma unroll
        for (int r = 0; r < 16; r++) {
            float lo, hi;
            asm("mov.b64 {%0, %1}, %2;" : "=f"(lo), "=f"(hi) : "l"(acc2[r]));
            const float v = tanhf(lo + hi);
            if (isLt) g_e_lt[(size_t)(row0 + r) * ATT + a] = v;
            else      g_e_rt[(size_t)(row0 + r) * ATT + a] = v * sD[a];
        }
    } else if (t < 116) {
        const int r = t - 100;
        float ss = 0.f;
        #pragma unroll 4
        for (int d = 0; d < 200; d += 2) {
            const float2 x = *(const float2*)&sX[r][d];
            ss = fmaf(x.x, x.x, fmaf(x.y, x.y, ss));
        }
        g_nl[row0 + r] = sqrtf(fmaxf(ss, 1e-6f));
    }
}

// ---------------------------------------------------------------------------
// Kernel 1b: fp32 S = rt @ lt^T per batch, argmax -> g_pos (unchanged).
// ---------------------------------------------------------------------------
__global__ __launch_bounds__(256, 2) void k_s(
    const float* __restrict__ rt, const float* __restrict__ lt)
{
    const int b = blockIdx.x;

    __shared__ float Asd[2][8][260];
    __shared__ float Bs[2][8][132];
    __shared__ float red_v[128][17];
    __shared__ int   red_i[128][17];
    __shared__ float sINL[128];

    const float* ab = rt + (size_t)b * L * D;
    const float* bbp = lt + (size_t)b * L * D;

    const int tid = threadIdx.x;
    const int ty = tid >> 4, tx = tid & 15;
    const int lr = tid >> 1, lc = (tid & 1) * 4;

    if (tid < 128) sINL[tid] = 1.0f / g_nl[b * L + tid];

    unsigned long long acc[8][4];
    #pragma unroll
    for (int i = 0; i < 8; i++)
        #pragma unroll
        for (int j = 0; j < 4; j++) acc[i][j] = 0ull;

    float4 ra, rb;
    auto ld_regs = [&](int k0) {
        ra = *reinterpret_cast<const float4*>(ab + lr * D + k0 + lc);
        rb = *reinterpret_cast<const float4*>(bbp + lr * D + k0 + lc);
    };
    auto st_smem = [&](int bf) {
        *reinterpret_cast<float2*>(&Asd[bf][lc + 0][2 * lr]) = make_float2(ra.x, ra.x);
        *reinterpret_cast<float2*>(&Asd[bf][lc + 1][2 * lr]) = make_float2(ra.y, ra.y);
        *reinterpret_cast<float2*>(&Asd[bf][lc + 2][2 * lr]) = make_float2(ra.z, ra.z);
        *reinterpret_cast<float2*>(&Asd[bf][lc + 3][2 * lr]) = make_float2(ra.w, ra.w);
        Bs[bf][lc + 0][lr] = rb.x; Bs[bf][lc + 1][lr] = rb.y;
        Bs[bf][lc + 2][lr] = rb.z; Bs[bf][lc + 3][lr] = rb.w;
    };
    auto compute = [&](int bf) {
        #pragma unroll
        for (int kk = 0; kk < 8; kk++) {
            unsigned long long a2[8], b2[4];
            #pragma unroll
            for (int q = 0; q < 4; q++) {
                ulonglong2 v = *reinterpret_cast<const ulonglong2*>(
                    &Asd[bf][kk][2 * (ty * 8 + 2 * q)]);
                a2[2 * q] = v.x; a2[2 * q + 1] = v.y;
            }
            {
                ulonglong2 v0 = *reinterpret_cast<const ulonglong2*>(&Bs[bf][kk][8 * tx]);
                ulonglong2 v1 = *reinterpret_cast<const ulonglong2*>(&Bs[bf][kk][8 * tx + 4]);
                b2[0] = v0.x; b2[1] = v0.y; b2[2] = v1.x; b2[3] = v1.y;
            }
            #pragma unroll
            for (int i = 0; i < 8; i++)
                #pragma unroll
                for (int j = 0; j < 4; j++)
                    asm("fma.rn.f32x2 %0, %1, %2, %0;"
                        : "+l"(acc[i][j]) : "l"(a2[i]), "l"(b2[j]));
        }
    };

    ld_regs(0);
    st_smem(0);
    __syncthreads();
    #pragma unroll 1
    for (int kt = 1; kt < 25; kt++) {
        ld_regs(kt * 8);
        compute((kt - 1) & 1);
        st_smem(kt & 1);
        __syncthreads();
    }
    compute(0);

    #pragma unroll
    for (int i = 0; i < 8; i++) {
        float bv = -FLT_MAX; int bi = 0;
        #pragma unroll
        for (int j = 0; j < 4; j++) {
            const int l0 = 8 * tx + 2 * j;
            const unsigned long long v = acc[i][j];
            const float lo = __uint_as_float((unsigned)(v & 0xffffffffull)) * sINL[l0];
            const float hi = __uint_as_float((unsigned)(v >> 32)) * sINL[l0 + 1];
            if (lo > bv) { bv = lo; bi = l0; }
            if (hi > bv) { bv = hi; bi = l0 + 1; }
        }
        red_v[ty * 8 + i][tx] = bv;
        red_i[ty * 8 + i][tx] = bi;
    }
    __syncthreads();
    if (tid < 128) {
        float v = red_v[tid][0]; int idx = red_i[tid][0];
        #pragma unroll
        for (int x = 1; x < 16; x++)
            if (red_v[tid][x] > v) { v = red_v[tid][x]; idx = red_i[tid][x]; }
        g_pos[b * L + tid] = idx;
    }
}

// ---------------------------------------------------------------------------
// Kernel 2: maxpool match via mma.sync (unchanged from round 9).
// ---------------------------------------------------------------------------
#define MMA_SMEM_BYTES 67456
__global__ __launch_bounds__(256, 2) void k_mp_mma(
    const float* __restrict__ rt, const float* __restrict__ wmp,
    float* __restrict__ out)
{
    extern __shared__ char smem[];
    const unsigned sb = smem_u32(smem);
    float* sW   = (float*)(smem + 65536);
    float* sRED = (float*)(smem + 66432);

    const int m = blockIdx.x, b = blockIdx.y;
    const int tid = threadIdx.x, wid = tid >> 5, lane = tid & 31;
    const int m0 = (wid & 3) * 32, n0 = (wid >> 2) * 64, wn = wid >> 2;

    for (int d = tid; d < 224; d += 256) sW[d] = (d < 200) ? wmp[m * 200 + d] : 0.f;
    __syncthreads();

    auto load_chunk = [&](int c) {
        for (int idx = tid; idx < 1024; idx += 256) {
            const int r = idx >> 3, kk4 = (idx & 7) * 4;
            const unsigned gi = (unsigned)(((b * L + r) << 7) + c * 32 + kk4);
            const unsigned o = offp(r, 2 * kk4);
            cp_async16(sb + o,         &g_lt_hi2[gi]);
            cp_async16(sb + 16384 + o, &g_lt_lo2[gi]);
        }
        for (int idx = tid; idx < 4096; idx += 256) {
            const int r = idx >> 5, kk = idx & 31;
            const int k = c * 64 + 2 * kk;
            float f0 = 0.f, f1 = 0.f;
            if (k < 200) {
                const float2 v = *(const float2*)&rt[(size_t)(b * L + r) * D + k];
                f0 = v.x * sW[k];
                f1 = (k + 1 < 200) ? v.y * sW[k + 1] : 0.f;
            }
            __nv_bfloat162 h = __floats2bfloat162_rn(f0, f1);
            const float h0 = __low2float(h), h1 = __high2float(h);
            __nv_bfloat162 l = __floats2bfloat162_rn(f0 - h0, f1 - h1);
            const unsigned o = offp(r, 2 * kk);
            *(unsigned*)(smem + 32768 + o) = *(unsigned*)&h;
            *(unsigned*)(smem + 49152 + o) = *(unsigned*)&l;
        }
        cp_async_wait_all();
    };

    float acc[2][8][4];
    #pragma unroll
    for (int mt = 0; mt < 2; mt++)
        #pragma unroll
        for (int nt = 0; nt < 8; nt++)
            #pragma unroll
            for (int q = 0; q < 4; q++) acc[mt][nt][q] = 0.f;

    auto compute = [&](int nk) {
        for (int ks = 0; ks < nk; ks++) {
            unsigned ah[2][4], al[2][4], bb[4][4];
            const int kca = ks * 16 + ((lane >> 4) << 3);
            #pragma unroll
            for (int mt = 0; mt < 2; mt++) {
                const int row = m0 + 16 * mt + (lane & 15);
                ldsm_x4(ah[mt], sb + offp(row, kca));
                ldsm_x4(al[mt], sb + 16384 + offp(row, kca));
            }
            const int kcb = ks * 16 + (((lane >> 3) & 1) << 3);
            const int rowb = (lane & 7) + ((lane >> 4) << 3);
            #pragma unroll
            for (int nt2 = 0; nt2 < 4; nt2++)
                ldsm_x4(bb[nt2], sb + 32768 + offp(n0 + nt2 * 16 + rowb, kcb));
            #pragma unroll
            for (int mt = 0; mt < 2; mt++)
                #pragma unroll
                for (int nt = 0; nt < 8; nt++) {
                    const unsigned* bp = &bb[nt >> 1][(nt & 1) * 2];
                    mma_bf16(acc[mt][nt], ah[mt], bp);
                    mma_bf16(acc[mt][nt], al[mt], bp);
                }
            #pragma unroll
            for (int nt2 = 0; nt2 < 4; nt2++)
                ldsm_x4(bb[nt2], sb + 49152 + offp(n0 + nt2 * 16 + rowb, kcb));
            #pragma unroll
            for (int mt = 0; mt < 2; mt++)
                #pragma unroll
                for (int nt = 0; nt < 8; nt++)
                    mma_bf16(acc[mt][nt], ah[mt], &bb[nt >> 1][(nt & 1) * 2]);
        }
    };

    const int nks[4] = {4, 4, 4, 1};
    #pragma unroll 1
    for (int c = 0; c < 4; c++) {
        load_chunk(c);
        __syncthreads();
        compute(nks[c]);
        __syncthreads();
    }

    #pragma unroll
    for (int mt = 0; mt < 2; mt++) {
        float mxA = -FLT_MAX, mxB = -FLT_MAX;
        #pragma unroll
        for (int nt = 0; nt < 8; nt++) {
            mxA = fmaxf(mxA, fmaxf(acc[mt][nt][0], acc[mt][nt][1]));
            mxB = fmaxf(mxB, fmaxf(acc[mt][nt][2], acc[mt][nt][3]));
        }
        #pragma unroll
        for (int o = 1; o < 4; o <<= 1) {
            mxA = fmaxf(mxA, __shfl_xor_sync(0xffffffffu, mxA, o));
            mxB = fmaxf(mxB, __shfl_xor_sync(0xffffffffu, mxB, o));
        }
        if ((lane & 3) == 0) {
            const int ra = m0 + 16 * mt + (lane >> 2);
            sRED[ra * 2 + wn]       = mxA;
            sRED[(ra + 8) * 2 + wn] = mxB;
        }
    }
    __syncthreads();
    if (tid < 128) {
        const float v = fmaxf(sRED[tid * 2], sRED[tid * 2 + 1]);
        out[((size_t)(b * L + tid)) * OUTC + 21 + m] = tanhf(v);
    }
}

// ---------------------------------------------------------------------------
// Kernel 3a: attention (Z gemm, softmax, att = P @ lt) -> g_att.
// grid (8, B), 256 threads, ~64 KB smem -> 3 CTAs/SM.
// lt streamed in 16-row tiles via cp.async, double-buffered; tiles 0/1 are
// pre-issued before the fills so their latency hides under Z/softmax.
// ---------------------------------------------------------------------------
#define ATT_SMEM_BYTES (15984 * 4)
__global__ __launch_bounds__(256) void k_att(const float* __restrict__ lt)
{
    extern __shared__ float sm[];
    float* sEL = sm;            // [128][51]
    float* sER = sm + 6528;     // [16][51]
    float* sZP = sm + 7344;     // [16][132]
    float* sT  = sm + 9456;     // [2][16][204]
    const unsigned sTb = smem_u32(sT);

    const int tile = blockIdx.x, b = blockIdx.y;
    const int t = threadIdx.x;
    const int lane = t & 31, w = t >> 5;   // 8 warps
    const int r0g = tile * 16;
    const float* ltb = lt + (size_t)b * L * D;

    auto issue = [&](int T) {
        const float* src = ltb + (size_t)(T * 16) * D;
        for (int idx = t; idx < 800; idx += 256) {
            const int l = idx / 50, q = idx - l * 50;
            cp_async16(sTb + (T & 1) * 13056 + l * 816 + q * 16,
                       src + (size_t)l * D + 4 * q);
        }
        cp_async_commit();
    };

    issue(0);
    issue(1);

    // fills
    for (int idx = t; idx < L * ATT; idx += 256) {
        const int l = idx / 50, k = idx - l * 50;
        sEL[l * 51 + k] = g_e_lt[(size_t)b * L * ATT + idx];
    }
    for (int idx = t; idx < 16 * ATT; idx += 256) {
        const int j = idx / 50, k = idx - j * 50;
        sER[j * 51 + k] = g_e_rt[(size_t)(b * L + r0g) * ATT + idx];
    }
    __syncthreads();

    // Z = e_rt_tile @ e_lt^T  (thread: col c = t&127, rows rr+2j)
    {
        const int c = t & 127, rr = t >> 7;
        float acc[8];
        #pragma unroll
        for (int j = 0; j < 8; j++) acc[j] = 0.f;
        #pragma unroll 2
        for (int a = 0; a < 50; a++) {
            const float x = sEL[c * 51 + a];
            #pragma unroll
            for (int j = 0; j < 8; j++)
                acc[j] = fmaf(sER[(rr + 2 * j) * 51 + a], x, acc[j]);
        }
        #pragma unroll
        for (int j = 0; j < 8; j++) sZP[(rr + 2 * j) * 132 + c] = acc[j];
    }
    __syncthreads();

    // softmax over l (warp w -> rows 2w, 2w+1)
    #pragma unroll
    for (int rr = 0; rr < 2; rr++) {
        const int r = 2 * w + rr;
        float zv[4];
        float zm = -FLT_MAX;
        #pragma unroll
        for (int q = 0; q < 4; q++) {
            zv[q] = sZP[r * 132 + lane + 32 * q];
            zm = fmaxf(zm, zv[q]);
        }
        #pragma unroll
        for (int o = 16; o > 0; o >>= 1)
            zm = fmaxf(zm, __shfl_xor_sync(0xffffffffu, zm, o));
        float s = 0.f;
        #pragma unroll
        for (int q = 0; q < 4; q++) { zv[q] = expf(zv[q] - zm); s += zv[q]; }
        #pragma unroll
        for (int o = 16; o > 0; o >>= 1)
            s += __shfl_xor_sync(0xffffffffu, s, o);
        const float inv = 1.0f / s;
        #pragma unroll
        for (int q = 0; q < 4; q++)
            sZP[r * 132 + lane + 32 * q] = zv[q] * inv;
    }
    __syncthreads();

    // att = P @ lt (streamed tiles); thread: rows rg+4i, cols c+64q
    {
        const int rg = t >> 6, c = t & 63;
        const bool q3 = (c < 8);
        float acc[4][4];
        #pragma unroll
        for (int i = 0; i < 4; i++)
            #pragma unroll
            for (int q = 0; q < 4; q++) acc[i][q] = 0.f;

        #pragma unroll 1
        for (int T = 0; T < 8; T++) {
            if (T < 7) cp_async_wait<1>(); else cp_async_wait<0>();
            __syncthreads();
            const float* tb = &sT[(T & 1) * 3264];
            #pragma unroll
            for (int lo = 0; lo < 16; lo++) {
                const int l = T * 16 + lo;
                const float p0 = sZP[rg * 132 + l];
                const float p1 = sZP[(rg + 4) * 132 + l];
                const float p2 = sZP[(rg + 8) * 132 + l];
                const float p3 = sZP[(rg + 12) * 132 + l];
                const float* row = &tb[lo * 204 + c];
                const float v0 = row[0], v1 = row[64], v2 = row[128];
                acc[0][0] = fmaf(p0, v0, acc[0][0]); acc[1][0] = fmaf(p1, v0, acc[1][0]);
                acc[2][0] = fmaf(p2, v0, acc[2][0]); acc[3][0] = fmaf(p3, v0, acc[3][0]);
                acc[0][1] = fmaf(p0, v1, acc[0][1]); acc[1][1] = fmaf(p1, v1, acc[1][1]);
                acc[2][1] = fmaf(p2, v1, acc[2][1]); acc[3][1] = fmaf(p3, v1, acc[3][1]);
                acc[0][2] = fmaf(p0, v2, acc[0][2]); acc[1][2] = fmaf(p1, v2, acc[1][2]);
                acc[2][2] = fmaf(p2, v2, acc[2][2]); acc[3][2] = fmaf(p3, v2, acc[3][2]);
                if (q3) {
                    const float v3 = row[192];
                    acc[0][3] = fmaf(p0, v3, acc[0][3]); acc[1][3] = fmaf(p1, v3, acc[1][3]);
                    acc[2][3] = fmaf(p2, v3, acc[2][3]); acc[3][3] = fmaf(p3, v3, acc[3][3]);
                }
            }
            __syncthreads();
            if (T < 6) issue(T + 2);
        }

        #pragma unroll
        for (int i = 0; i < 4; i++) {
            float* dst = g_att + (size_t)(b * L + r0g + rg + 4 * i) * D;
            dst[c]       = acc[i][0];
            dst[c + 64]  = acc[i][1];
            dst[c + 128] = acc[i][2];
            if (q3) dst[c + 192] = acc[i][3];
        }
    }
}

// ---------------------------------------------------------------------------
// Kernel 3b: epilogue — full/attentive/max-attentive dots + tanh.
// grid (8, B), 256 threads, ~55 KB smem -> 4 CTAs/SM. Warp j of 8 handles
// rows 2j, 2j+1; row vectors read coalesced from gmem (L2-hot).
// ---------------------------------------------------------------------------
#define EPI_SMEM_BYTES (13664 * 4)
__global__ __launch_bounds__(256) void k_epi(
    const float* __restrict__ lt, const float* __restrict__ rt,
    const float* __restrict__ fw, const float* __restrict__ bw,
    const float* __restrict__ w_full, const float* __restrict__ w_att,
    const float* __restrict__ w_maxatt, float* __restrict__ out)
{
    extern __shared__ float sm[];
    float* sW  = sm;                   // [60][224] zero-padded
    float* sH  = sm + 13440;           // [204]
    int*   sPOS = (int*)(sm + 13644);  // [16]

    const int tile = blockIdx.x, b = blockIdx.y;
    const int t = threadIdx.x;
    const int lane = t & 31, w = t >> 5;   // 8 warps
    const int r0g = tile * 16;

    for (int idx = t; idx < 60 * 56; idx += 256) {
        const int mrow = idx / 56, q = idx - mrow * 56;
        float4 v = make_float4(0.f, 0.f, 0.f, 0.f);
        if (q < 50) {
            const float* src = (mrow < 20) ? w_full + mrow * 200
                             : (mrow < 40) ? w_att + (mrow - 20) * 200
                                           : w_maxatt + (mrow - 40) * 200;
            v = *(const float4*)(src + 4 * q);
        }
        *(float4*)&sW[mrow * 224 + 4 * q] = v;
    }
    if (t < 204) { sH[t] = (t < 100) ? fw[b * 100 + t]
                         : (t < 200) ? bw[b * 100 + t - 100] : 0.f; }
    if (t < 16) sPOS[t] = g_pos[b * L + r0g + t];
    __syncthreads();

    #pragma unroll 1
    for (int rr = 0; rr < 2; rr++) {
        const int j = 2 * w + rr;
        const int gr = r0g + j;
        const int pos = sPOS[j];
        const float* ltrow  = lt + (size_t)(b * L + gr) * D;
        const float* rtrow  = rt + (size_t)(b * L + gr) * D;
        const float* atrow  = g_att + (size_t)(b * L + gr) * D;
        const float* posrow = lt + (size_t)(b * L + pos) * D;
        float* outrow = out + (size_t)(b * L + gr) * OUTC;

        float gf[7], ga[7], gm[7];
        #pragma unroll
        for (int c = 0; c < 7; c++) {
            const int d = lane + 32 * c;
            const bool ok = (c < 6) || (lane < 8);
            const float xl = ok ? ltrow[d] : 0.f;
            const float xh = ok ? sH[d] : 0.f;
            const float xa = ok ? atrow[d] : 0.f;
            const float xr = ok ? rtrow[d] : 0.f;
            const float xp = ok ? posrow[d] : 0.f;
            gf[c] = xl * xh;
            ga[c] = xa * xr;
            gm[c] = xr * xp;
        }
        {
            float s0 = 0.f, s1 = 0.f, s2 = 0.f;
            #pragma unroll
            for (int c = 0; c < 7; c++) { s0 += gf[c]; s1 += ga[c]; s2 += gm[c]; }
            #pragma unroll
            for (int o = 16; o > 0; o >>= 1) {
                s0 += __shfl_xor_sync(0xffffffffu, s0, o);
                s1 += __shfl_xor_sync(0xffffffffu, s1, o);
                s2 += __shfl_xor_sync(0xffffffffu, s2, o);
            }
            if (lane == 0) {
                outrow[0]  = tanhf(s0);
                outrow[41] = tanhf(s1);
                outrow[62] = tanhf(s2);
            }
        }
        #pragma unroll 2
        for (int m = 0; m < 20; m++) {
            float a0 = 0.f, a1 = 0.f, a2 = 0.f;
            #pragma unroll
            for (int c = 0; c < 7; c++) {
                const int d = lane + 32 * c;
                a0 = fmaf(gf[c], sW[m * 224 + d], a0);
                a1 = fmaf(ga[c], sW[(20 + m) * 224 + d], a1);
                a2 = fmaf(gm[c], sW[(40 + m) * 224 + d], a2);
            }
            #pragma unroll
            for (int o = 16; o > 0; o >>= 1) {
                a0 += __shfl_xor_sync(0xffffffffu, a0, o);
                a1 += __shfl_xor_sync(0xffffffffu, a1, o);
                a2 += __shfl_xor_sync(0xffffffffu, a2, o);
            }
            if (lane == 0) {
                outrow[1 + m]  = tanhf(a0);
                outrow[42 + m] = tanhf(a1);
                outrow[63 + m] = tanhf(a2);
            }
        }
    }
}

// ---------------------------------------------------------------------------
extern "C" void kernel_launch(void* const* d_in, const int* in_sizes, int n_in,
                              void* d_out, int out_size)
{
    const float* reps_lt   = (const float*)d_in[0];
    const float* reps_rt   = (const float*)d_in[1];
    const float* fw_h_rt   = (const float*)d_in[2];
    const float* bw_h_rt   = (const float*)d_in[3];
    const float* w_full    = (const float*)d_in[4];
    const float* w_maxpool = (const float*)d_in[5];
    const float* w_att     = (const float*)d_in[6];
    const float* w_maxatt  = (const float*)d_in[7];
    const float* attn_w1   = (const float*)d_in[8];
    const float* attn_w2   = (const float*)d_in[9];
    const float* diag_w    = (const float*)d_in[10];
    float* out = (float*)d_out;

    cudaFuncSetAttribute(k_mp_mma, cudaFuncAttributeMaxDynamicSharedMemorySize, MMA_SMEM_BYTES);
    cudaFuncSetAttribute(k_att, cudaFuncAttributeMaxDynamicSharedMemorySize, ATT_SMEM_BYTES);
    cudaFuncSetAttribute(k_epi, cudaFuncAttributeMaxDynamicSharedMemorySize, EPI_SMEM_BYTES);

    k_prep<<<B, 256>>>(reps_lt);
    dim3 g1(8, B);  k_proj<<<g1, 128>>>(reps_lt, reps_rt, attn_w1, attn_w2, diag_w);
    k_s<<<B, 256>>>(reps_rt, reps_lt);
    dim3 g2(MP, B); k_mp_mma<<<g2, 256, MMA_SMEM_BYTES>>>(reps_rt, w_maxpool, out);
    dim3 g3(8, B);  k_att<<<g3, 256, ATT_SMEM_BYTES>>>(reps_lt);
    dim3 g4(8, B);  k_epi<<<g4, 256, EPI_SMEM_BYTES>>>(reps_lt, reps_rt, fw_h_rt, bw_h_rt,
                                                       w_full, w_att, w_maxatt, out);
}

// round 11
// speedup vs baseline: 3.1276x; 1.2176x over previous
#include <cuda_runtime.h>
#include <cuda_bf16.h>
#include <math.h>
#include <float.h>

// Shapes (fixed by the problem)
#define B 64
#define L 128
#define D 200
#define MP 20
#define ATT 50
#define OUTC 83   // 21 + 20 + 21 + 21

// ---------------------------------------------------------------------------
// Scratch (device globals; no allocations allowed)
// ---------------------------------------------------------------------------
__device__ float g_e_lt[B * L * ATT];       // tanh(lt @ w2)             [b,l,a]
__device__ float g_e_rt[B * L * ATT];       // tanh(rt @ w1) * diag      [b,r,a]
__device__ float g_nl[B * L];               // sqrt(max(|lt_l|^2, EPS))  [b,l]
__device__ int   g_pos[B * L];              // argmax_l rel[r][l]        [b,r]
__device__ float g_att[B * L * D];          // attention-weighted lt     [b,r,d]
__device__ unsigned g_lt_hi2[B * L * 128];  // lt bf16 hi, packed pairs, Kpad=256
__device__ unsigned g_lt_lo2[B * L * 128];  // lt bf16 lo

// ---------------------------------------------------------------------------
// Helpers (base-PTX only: ldmatrix sm_75+, mma.sync bf16 sm_80+, cp.async sm_80+)
// ---------------------------------------------------------------------------
__device__ __forceinline__ unsigned smem_u32(const void* p) {
    unsigned a;
    asm("{ .reg .u64 t; cvta.to.shared.u64 t, %1; cvt.u32.u64 %0, t; }"
        : "=r"(a) : "l"(p));
    return a;
}
__device__ __forceinline__ void ldsm_x4(unsigned* r, unsigned addr) {
    asm volatile("ldmatrix.sync.aligned.m8n8.x4.shared.b16 {%0,%1,%2,%3}, [%4];"
                 : "=r"(r[0]), "=r"(r[1]), "=r"(r[2]), "=r"(r[3]) : "r"(addr));
}
__device__ __forceinline__ void mma_bf16(float* c, const unsigned* a,
                                         const unsigned* b) {
    asm volatile(
        "mma.sync.aligned.m16n8k16.row.col.f32.bf16.bf16.f32 "
        "{%0,%1,%2,%3}, {%4,%5,%6,%7}, {%8,%9}, {%0,%1,%2,%3};"
        : "+f"(c[0]), "+f"(c[1]), "+f"(c[2]), "+f"(c[3])
        : "r"(a[0]), "r"(a[1]), "r"(a[2]), "r"(a[3]), "r"(b[0]), "r"(b[1]));
}
__device__ __forceinline__ void cp_async16(unsigned dst, const void* src) {
    asm volatile("cp.async.ca.shared.global [%0], [%1], 16;"
                 :: "r"(dst), "l"(src) : "memory");
}
__device__ __forceinline__ void cp_async_commit() {
    asm volatile("cp.async.commit_group;" ::: "memory");
}
template <int N> __device__ __forceinline__ void cp_async_wait() {
    asm volatile("cp.async.wait_group %0;" :: "n"(N) : "memory");
}
__device__ __forceinline__ void cp_async_wait_all() {
    asm volatile("cp.async.commit_group;\ncp.async.wait_group 0;" ::: "memory");
}
// byte offset of bf16 element (r, k) inside a [128][64] bf16 plane,
// XOR-swizzled so ldmatrix (8 rows x 16B) is bank-conflict-free.
__device__ __forceinline__ unsigned offp(int r, int k) {
    return (unsigned)(r * 128 + ((((k >> 3) ^ (r & 7)) & 7) << 4) + ((k & 7) << 1));
}

// ---------------------------------------------------------------------------
// Kernel 0: bf16 hi/lo split of lt (Kpad=256, zero-padded), packed pairs.
// ---------------------------------------------------------------------------
__global__ __launch_bounds__(256) void k_prep(const float* __restrict__ lt)
{
    const int b = blockIdx.x;
    for (int idx = threadIdx.x; idx < L * 128; idx += 256) {
        const int r = idx >> 7, kk = idx & 127, k = kk * 2;
        const float* rr = lt + ((size_t)(b * L + r)) * D;
        const float f0 = (k < 200) ? rr[k] : 0.f;
        const float f1 = (k + 1 < 200) ? rr[k + 1] : 0.f;
        __nv_bfloat162 h = __floats2bfloat162_rn(f0, f1);
        const float h0 = __low2float(h), h1 = __high2float(h);
        __nv_bfloat162 l = __floats2bfloat162_rn(f0 - h0, f1 - h1);
        const unsigned gi = (unsigned)(((b * L + r) << 7) + kk);
        g_lt_hi2[gi] = *(unsigned*)&h;
        g_lt_lo2[gi] = *(unsigned*)&l;
    }
}

// ---------------------------------------------------------------------------
// Kernel 1: attention projections + lt row norms (unchanged).
// ---------------------------------------------------------------------------
__global__ __launch_bounds__(128) void k_proj(
    const float* __restrict__ lt, const float* __restrict__ rt,
    const float* __restrict__ w1, const float* __restrict__ w2,
    const float* __restrict__ diag)
{
    __shared__ float sX[32][202];
    __shared__ float sD[64];

    const int tile = blockIdx.x, b = blockIdx.y;
    const int t = threadIdx.x;
    const int row0 = b * L + tile * 16;

    for (int idx = t; idx < 3200; idx += 128) {
        const int r = idx / 100, q = idx - r * 100;
        const int gr = row0 + (r & 15);
        const float* src = (r < 16) ? lt : rt;
        *(float2*)&sX[r][2 * q] = *(const float2*)&src[(size_t)gr * D + 2 * q];
    }
    if (t < ATT) sD[t] = diag[t];
    __syncthreads();

    if (t < 100) {
        const bool isLt = (t < 50);
        const int a = isLt ? t : t - 50;
        const float* wsrc = isLt ? w2 : w1;
        const int rbase = isLt ? 0 : 16;

        unsigned long long acc2[16];
        #pragma unroll
        for (int r = 0; r < 16; r++) acc2[r] = 0ull;

        #pragma unroll 2
        for (int d = 0; d < 200; d += 2) {
            const float wlo = wsrc[d * ATT + a];
            const float whi = wsrc[(d + 1) * ATT + a];
            unsigned long long w2r;
            asm("mov.b64 %0, {%1, %2};" : "=l"(w2r) : "f"(wlo), "f"(whi));
            #pragma unroll
            for (int r = 0; r < 16; r++) {
                const unsigned long long x2 =
                    *(const unsigned long long*)&sX[rbase + r][d];
                asm("fma.rn.f32x2 %0, %1, %2, %0;"
                    : "+l"(acc2[r]) : "l"(x2), "l"(w2r));
            }
        }
        #pragma unroll
        for (int r = 0; r < 16; r++) {
            float lo, hi;
            asm("mov.b64 {%0, %1}, %2;" : "=f"(lo), "=f"(hi) : "l"(acc2[r]));
            const float v = tanhf(lo + hi);
            if (isLt) g_e_lt[(size_t)(row0 + r) * ATT + a] = v;
            else      g_e_rt[(size_t)(row0 + r) * ATT + a] = v * sD[a];
        }
    } else if (t < 116) {
        const int r = t - 100;
        float ss = 0.f;
        #pragma unroll 4
        for (int d = 0; d < 200; d += 2) {
            const float2 x = *(const float2*)&sX[r][d];
            ss = fmaf(x.x, x.x, fmaf(x.y, x.y, ss));
        }
        g_nl[row0 + r] = sqrtf(fmaxf(ss, 1e-6f));
    }
}

// ---------------------------------------------------------------------------
// Kernel 1b: fp32 S = rt @ lt^T per batch, argmax -> g_pos (unchanged).
// ---------------------------------------------------------------------------
__global__ __launch_bounds__(256, 2) void k_s(
    const float* __restrict__ rt, const float* __restrict__ lt)
{
    const int b = blockIdx.x;

    __shared__ float Asd[2][8][260];
    __shared__ float Bs[2][8][132];
    __shared__ float red_v[128][17];
    __shared__ int   red_i[128][17];
    __shared__ float sINL[128];

    const float* ab = rt + (size_t)b * L * D;
    const float* bbp = lt + (size_t)b * L * D;

    const int tid = threadIdx.x;
    const int ty = tid >> 4, tx = tid & 15;
    const int lr = tid >> 1, lc = (tid & 1) * 4;

    if (tid < 128) sINL[tid] = 1.0f / g_nl[b * L + tid];

    unsigned long long acc[8][4];
    #pragma unroll
    for (int i = 0; i < 8; i++)
        #pragma unroll
        for (int j = 0; j < 4; j++) acc[i][j] = 0ull;

    float4 ra, rb;
    auto ld_regs = [&](int k0) {
        ra = *reinterpret_cast<const float4*>(ab + lr * D + k0 + lc);
        rb = *reinterpret_cast<const float4*>(bbp + lr * D + k0 + lc);
    };
    auto st_smem = [&](int bf) {
        *reinterpret_cast<float2*>(&Asd[bf][lc + 0][2 * lr]) = make_float2(ra.x, ra.x);
        *reinterpret_cast<float2*>(&Asd[bf][lc + 1][2 * lr]) = make_float2(ra.y, ra.y);
        *reinterpret_cast<float2*>(&Asd[bf][lc + 2][2 * lr]) = make_float2(ra.z, ra.z);
        *reinterpret_cast<float2*>(&Asd[bf][lc + 3][2 * lr]) = make_float2(ra.w, ra.w);
        Bs[bf][lc + 0][lr] = rb.x; Bs[bf][lc + 1][lr] = rb.y;
        Bs[bf][lc + 2][lr] = rb.z; Bs[bf][lc + 3][lr] = rb.w;
    };
    auto compute = [&](int bf) {
        #pragma unroll
        for (int kk = 0; kk < 8; kk++) {
            unsigned long long a2[8], b2[4];
            #pragma unroll
            for (int q = 0; q < 4; q++) {
                ulonglong2 v = *reinterpret_cast<const ulonglong2*>(
                    &Asd[bf][kk][2 * (ty * 8 + 2 * q)]);
                a2[2 * q] = v.x; a2[2 * q + 1] = v.y;
            }
            {
                ulonglong2 v0 = *reinterpret_cast<const ulonglong2*>(&Bs[bf][kk][8 * tx]);
                ulonglong2 v1 = *reinterpret_cast<const ulonglong2*>(&Bs[bf][kk][8 * tx + 4]);
                b2[0] = v0.x; b2[1] = v0.y; b2[2] = v1.x; b2[3] = v1.y;
            }
            #pragma unroll
            for (int i = 0; i < 8; i++)
                #pragma unroll
                for (int j = 0; j < 4; j++)
                    asm("fma.rn.f32x2 %0, %1, %2, %0;"
                        : "+l"(acc[i][j]) : "l"(a2[i]), "l"(b2[j]));
        }
    };

    ld_regs(0);
    st_smem(0);
    __syncthreads();
    #pragma unroll 1
    for (int kt = 1; kt < 25; kt++) {
        ld_regs(kt * 8);
        compute((kt - 1) & 1);
        st_smem(kt & 1);
        __syncthreads();
    }
    compute(0);

    #pragma unroll
    for (int i = 0; i < 8; i++) {
        float bv = -FLT_MAX; int bi = 0;
        #pragma unroll
        for (int j = 0; j < 4; j++) {
            const int l0 = 8 * tx + 2 * j;
            const unsigned long long v = acc[i][j];
            const float lo = __uint_as_float((unsigned)(v & 0xffffffffull)) * sINL[l0];
            const float hi = __uint_as_float((unsigned)(v >> 32)) * sINL[l0 + 1];
            if (lo > bv) { bv = lo; bi = l0; }
            if (hi > bv) { bv = hi; bi = l0 + 1; }
        }
        red_v[ty * 8 + i][tx] = bv;
        red_i[ty * 8 + i][tx] = bi;
    }
    __syncthreads();
    if (tid < 128) {
        float v = red_v[tid][0]; int idx = red_i[tid][0];
        #pragma unroll
        for (int x = 1; x < 16; x++)
            if (red_v[tid][x] > v) { v = red_v[tid][x]; idx = red_i[tid][x]; }
        g_pos[b * L + tid] = idx;
    }
}

// ---------------------------------------------------------------------------
// Kernel 2: maxpool match via mma.sync (bf16 split, fp32 accum).
// Round-11 change: B conversion uses TRUNCATION split (PRMT hi-pack,
// LOP3 mask+signflip, exact fp32 remainder, one CVT) and a fixed-k thread
// mapping so the w pair lives in registers. ~half the convert instructions.
// ---------------------------------------------------------------------------
#define MMA_SMEM_BYTES 67584   // 65536 planes + 1024 sW[256] + 1024 sRED
__global__ __launch_bounds__(256, 2) void k_mp_mma(
    const float* __restrict__ rt, const float* __restrict__ wmp,
    float* __restrict__ out)
{
    extern __shared__ char smem[];
    const unsigned sb = smem_u32(smem);
    float* sW   = (float*)(smem + 65536);   // [256] w row, zero-padded
    float* sRED = (float*)(smem + 66560);   // [128][2]

    const int m = blockIdx.x, b = blockIdx.y;
    const int tid = threadIdx.x, wid = tid >> 5, lane = tid & 31;
    const int m0 = (wid & 3) * 32, n0 = (wid >> 2) * 64, wn = wid >> 2;

    for (int d = tid; d < 256; d += 256) sW[d] = (d < 200) ? wmp[m * 200 + d] : 0.f;
    __syncthreads();

    const int kk  = tid & 31;      // fixed k-pair column per thread
    const int rg8 = tid >> 5;      // row group 0..7 (16 rows each)

    auto load_chunk = [&](int c) {
        // A planes via cp.async 16B (precomputed lt split)
        for (int idx = tid; idx < 1024; idx += 256) {
            const int r = idx >> 3, kk4 = (idx & 7) * 4;
            const unsigned gi = (unsigned)(((b * L + r) << 7) + c * 32 + kk4);
            const unsigned o = offp(r, 2 * kk4);
            cp_async16(sb + o,         &g_lt_hi2[gi]);
            cp_async16(sb + 16384 + o, &g_lt_lo2[gi]);
        }
        // B planes: (w (.) rt), truncation split. Thread owns k = c*64 + 2*kk.
        const int k = c * 64 + 2 * kk;
        const float w0 = sW[k], w1 = sW[k + 1];
        const bool valid = (k < 200);
        #pragma unroll 4
        for (int j = 0; j < 16; j++) {
            const int row = rg8 * 16 + j;
            float f0 = 0.f, f1 = 0.f;
            if (valid) {
                const float2 v = *(const float2*)&rt[(size_t)(b * L + row) * D + k];
                f0 = v.x * w0;
                f1 = v.y * w1;
            }
            const unsigned u0 = __float_as_uint(f0);
            const unsigned u1 = __float_as_uint(f1);
            const unsigned hi2 = __byte_perm(u0, u1, 0x7632);
            const float l0 = f0 + __uint_as_float((u0 & 0xFFFF0000u) ^ 0x80000000u);
            const float l1 = f1 + __uint_as_float((u1 & 0xFFFF0000u) ^ 0x80000000u);
            unsigned lo2;
            asm("cvt.rn.bf16x2.f32 %0, %1, %2;" : "=r"(lo2) : "f"(l1), "f"(l0));
            const unsigned o = offp(row, 2 * kk);
            *(unsigned*)(smem + 32768 + o) = hi2;
            *(unsigned*)(smem + 49152 + o) = lo2;
        }
        cp_async_wait_all();
    };

    float acc[2][8][4];
    #pragma unroll
    for (int mt = 0; mt < 2; mt++)
        #pragma unroll
        for (int nt = 0; nt < 8; nt++)
            #pragma unroll
            for (int q = 0; q < 4; q++) acc[mt][nt][q] = 0.f;

    auto compute = [&](int nk) {
        for (int ks = 0; ks < nk; ks++) {
            unsigned ah[2][4], al[2][4], bb[4][4];
            const int kca = ks * 16 + ((lane >> 4) << 3);
            #pragma unroll
            for (int mt = 0; mt < 2; mt++) {
                const int row = m0 + 16 * mt + (lane & 15);
                ldsm_x4(ah[mt], sb + offp(row, kca));
                ldsm_x4(al[mt], sb + 16384 + offp(row, kca));
            }
            const int kcb = ks * 16 + (((lane >> 3) & 1) << 3);
            const int rowb = (lane & 7) + ((lane >> 4) << 3);
            #pragma unroll
            for (int nt2 = 0; nt2 < 4; nt2++)
                ldsm_x4(bb[nt2], sb + 32768 + offp(n0 + nt2 * 16 + rowb, kcb));
            #pragma unroll
            for (int mt = 0; mt < 2; mt++)
                #pragma unroll
                for (int nt = 0; nt < 8; nt++) {
                    const unsigned* bp = &bb[nt >> 1][(nt & 1) * 2];
                    mma_bf16(acc[mt][nt], ah[mt], bp);
                    mma_bf16(acc[mt][nt], al[mt], bp);
                }
            #pragma unroll
            for (int nt2 = 0; nt2 < 4; nt2++)
                ldsm_x4(bb[nt2], sb + 49152 + offp(n0 + nt2 * 16 + rowb, kcb));
            #pragma unroll
            for (int mt = 0; mt < 2; mt++)
                #pragma unroll
                for (int nt = 0; nt < 8; nt++)
                    mma_bf16(acc[mt][nt], ah[mt], &bb[nt >> 1][(nt & 1) * 2]);
        }
    };

    const int nks[4] = {4, 4, 4, 1};
    #pragma unroll 1
    for (int c = 0; c < 4; c++) {
        load_chunk(c);
        __syncthreads();
        compute(nks[c]);
        __syncthreads();
    }

    #pragma unroll
    for (int mt = 0; mt < 2; mt++) {
        float mxA = -FLT_MAX, mxB = -FLT_MAX;
        #pragma unroll
        for (int nt = 0; nt < 8; nt++) {
            mxA = fmaxf(mxA, fmaxf(acc[mt][nt][0], acc[mt][nt][1]));
            mxB = fmaxf(mxB, fmaxf(acc[mt][nt][2], acc[mt][nt][3]));
        }
        #pragma unroll
        for (int o = 1; o < 4; o <<= 1) {
            mxA = fmaxf(mxA, __shfl_xor_sync(0xffffffffu, mxA, o));
            mxB = fmaxf(mxB, __shfl_xor_sync(0xffffffffu, mxB, o));
        }
        if ((lane & 3) == 0) {
            const int ra = m0 + 16 * mt + (lane >> 2);
            sRED[ra * 2 + wn]       = mxA;
            sRED[(ra + 8) * 2 + wn] = mxB;
        }
    }
    __syncthreads();
    if (tid < 128) {
        const float v = fmaxf(sRED[tid * 2], sRED[tid * 2 + 1]);
        out[((size_t)(b * L + tid)) * OUTC + 21 + m] = tanhf(v);
    }
}

// ---------------------------------------------------------------------------
// Kernel 3a: attention (Z gemm, softmax, att = P @ lt) -> g_att (unchanged).
// ---------------------------------------------------------------------------
#define ATT_SMEM_BYTES (15984 * 4)
__global__ __launch_bounds__(256) void k_att(const float* __restrict__ lt)
{
    extern __shared__ float sm[];
    float* sEL = sm;            // [128][51]
    float* sER = sm + 6528;     // [16][51]
    float* sZP = sm + 7344;     // [16][132]
    float* sT  = sm + 9456;     // [2][16][204]
    const unsigned sTb = smem_u32(sT);

    const int tile = blockIdx.x, b = blockIdx.y;
    const int t = threadIdx.x;
    const int lane = t & 31, w = t >> 5;   // 8 warps
    const int r0g = tile * 16;
    const float* ltb = lt + (size_t)b * L * D;

    auto issue = [&](int T) {
        const float* src = ltb + (size_t)(T * 16) * D;
        for (int idx = t; idx < 800; idx += 256) {
            const int l = idx / 50, q = idx - l * 50;
            cp_async16(sTb + (T & 1) * 13056 + l * 816 + q * 16,
                       src + (size_t)l * D + 4 * q);
        }
        cp_async_commit();
    };

    issue(0);
    issue(1);

    for (int idx = t; idx < L * ATT; idx += 256) {
        const int l = idx / 50, k = idx - l * 50;
        sEL[l * 51 + k] = g_e_lt[(size_t)b * L * ATT + idx];
    }
    for (int idx = t; idx < 16 * ATT; idx += 256) {
        const int j = idx / 50, k = idx - j * 50;
        sER[j * 51 + k] = g_e_rt[(size_t)(b * L + r0g) * ATT + idx];
    }
    __syncthreads();

    // Z = e_rt_tile @ e_lt^T
    {
        const int c = t & 127, rr = t >> 7;
        float acc[8];
        #pragma unroll
        for (int j = 0; j < 8; j++) acc[j] = 0.f;
        #pragma unroll 2
        for (int a = 0; a < 50; a++) {
            const float x = sEL[c * 51 + a];
            #pragma unroll
            for (int j = 0; j < 8; j++)
                acc[j] = fmaf(sER[(rr + 2 * j) * 51 + a], x, acc[j]);
        }
        #pragma unroll
        for (int j = 0; j < 8; j++) sZP[(rr + 2 * j) * 132 + c] = acc[j];
    }
    __syncthreads();

    // softmax over l (warp w -> rows 2w, 2w+1)
    #pragma unroll
    for (int rr = 0; rr < 2; rr++) {
        const int r = 2 * w + rr;
        float zv[4];
        float zm = -FLT_MAX;
        #pragma unroll
        for (int q = 0; q < 4; q++) {
            zv[q] = sZP[r * 132 + lane + 32 * q];
            zm = fmaxf(zm, zv[q]);
        }
        #pragma unroll
        for (int o = 16; o > 0; o >>= 1)
            zm = fmaxf(zm, __shfl_xor_sync(0xffffffffu, zm, o));
        float s = 0.f;
        #pragma unroll
        for (int q = 0; q < 4; q++) { zv[q] = expf(zv[q] - zm); s += zv[q]; }
        #pragma unroll
        for (int o = 16; o > 0; o >>= 1)
            s += __shfl_xor_sync(0xffffffffu, s, o);
        const float inv = 1.0f / s;
        #pragma unroll
        for (int q = 0; q < 4; q++)
            sZP[r * 132 + lane + 32 * q] = zv[q] * inv;
    }
    __syncthreads();

    // att = P @ lt (streamed tiles)
    {
        const int rg = t >> 6, c = t & 63;
        const bool q3 = (c < 8);
        float acc[4][4];
        #pragma unroll
        for (int i = 0; i < 4; i++)
            #pragma unroll
            for (int q = 0; q < 4; q++) acc[i][q] = 0.f;

        #pragma unroll 1
        for (int T = 0; T < 8; T++) {
            if (T < 7) cp_async_wait<1>(); else cp_async_wait<0>();
            __syncthreads();
            const float* tb = &sT[(T & 1) * 3264];
            #pragma unroll
            for (int lo = 0; lo < 16; lo++) {
                const int l = T * 16 + lo;
                const float p0 = sZP[rg * 132 + l];
                const float p1 = sZP[(rg + 4) * 132 + l];
                const float p2 = sZP[(rg + 8) * 132 + l];
                const float p3 = sZP[(rg + 12) * 132 + l];
                const float* row = &tb[lo * 204 + c];
                const float v0 = row[0], v1 = row[64], v2 = row[128];
                acc[0][0] = fmaf(p0, v0, acc[0][0]); acc[1][0] = fmaf(p1, v0, acc[1][0]);
                acc[2][0] = fmaf(p2, v0, acc[2][0]); acc[3][0] = fmaf(p3, v0, acc[3][0]);
                acc[0][1] = fmaf(p0, v1, acc[0][1]); acc[1][1] = fmaf(p1, v1, acc[1][1]);
                acc[2][1] = fmaf(p2, v1, acc[2][1]); acc[3][1] = fmaf(p3, v1, acc[3][1]);
                acc[0][2] = fmaf(p0, v2, acc[0][2]); acc[1][2] = fmaf(p1, v2, acc[1][2]);
                acc[2][2] = fmaf(p2, v2, acc[2][2]); acc[3][2] = fmaf(p3, v2, acc[3][2]);
                if (q3) {
                    const float v3 = row[192];
                    acc[0][3] = fmaf(p0, v3, acc[0][3]); acc[1][3] = fmaf(p1, v3, acc[1][3]);
                    acc[2][3] = fmaf(p2, v3, acc[2][3]); acc[3][3] = fmaf(p3, v3, acc[3][3]);
                }
            }
            __syncthreads();
            if (T < 6) issue(T + 2);
        }

        #pragma unroll
        for (int i = 0; i < 4; i++) {
            float* dst = g_att + (size_t)(b * L + r0g + rg + 4 * i) * D;
            dst[c]       = acc[i][0];
            dst[c + 64]  = acc[i][1];
            dst[c + 128] = acc[i][2];
            if (q3) dst[c + 192] = acc[i][3];
        }
    }
}

// ---------------------------------------------------------------------------
// Kernel 3b: epilogue — full/attentive/max-attentive dots + tanh (unchanged).
// ---------------------------------------------------------------------------
#define EPI_SMEM_BYTES (13664 * 4)
__global__ __launch_bounds__(256) void k_epi(
    const float* __restrict__ lt, const float* __restrict__ rt,
    const float* __restrict__ fw, const float* __restrict__ bw,
    const float* __restrict__ w_full, const float* __restrict__ w_att,
    const float* __restrict__ w_maxatt, float* __restrict__ out)
{
    extern __shared__ float sm[];
    float* sW  = sm;                   // [60][224] zero-padded
    float* sH  = sm + 13440;           // [204]
    int*   sPOS = (int*)(sm + 13644);  // [16]

    const int tile = blockIdx.x, b = blockIdx.y;
    const int t = threadIdx.x;
    const int lane = t & 31, w = t >> 5;   // 8 warps
    const int r0g = tile * 16;

    for (int idx = t; idx < 60 * 56; idx += 256) {
        const int mrow = idx / 56, q = idx - mrow * 56;
        float4 v = make_float4(0.f, 0.f, 0.f, 0.f);
        if (q < 50) {
            const float* src = (mrow < 20) ? w_full + mrow * 200
                             : (mrow < 40) ? w_att + (mrow - 20) * 200
                                           : w_maxatt + (mrow - 40) * 200;
            v = *(const float4*)(src + 4 * q);
        }
        *(float4*)&sW[mrow * 224 + 4 * q] = v;
    }
    if (t < 204) { sH[t] = (t < 100) ? fw[b * 100 + t]
                         : (t < 200) ? bw[b * 100 + t - 100] : 0.f; }
    if (t < 16) sPOS[t] = g_pos[b * L + r0g + t];
    __syncthreads();

    #pragma unroll 1
    for (int rr = 0; rr < 2; rr++) {
        const int j = 2 * w + rr;
        const int gr = r0g + j;
        const int pos = sPOS[j];
        const float* ltrow  = lt + (size_t)(b * L + gr) * D;
        const float* rtrow  = rt + (size_t)(b * L + gr) * D;
        const float* atrow  = g_att + (size_t)(b * L + gr) * D;
        const float* posrow = lt + (size_t)(b * L + pos) * D;
        float* outrow = out + (size_t)(b * L + gr) * OUTC;

        float gf[7], ga[7], gm[7];
        #pragma unroll
        for (int c = 0; c < 7; c++) {
            const int d = lane + 32 * c;
            const bool ok = (c < 6) || (lane < 8);
            const float xl = ok ? ltrow[d] : 0.f;
            const float xh = ok ? sH[d] : 0.f;
            const float xa = ok ? atrow[d] : 0.f;
            const float xr = ok ? rtrow[d] : 0.f;
            const float xp = ok ? posrow[d] : 0.f;
            gf[c] = xl * xh;
            ga[c] = xa * xr;
            gm[c] = xr * xp;
        }
        {
            float s0 = 0.f, s1 = 0.f, s2 = 0.f;
            #pragma unroll
            for (int c = 0; c < 7; c++) { s0 += gf[c]; s1 += ga[c]; s2 += gm[c]; }
            #pragma unroll
            for (int o = 16; o > 0; o >>= 1) {
                s0 += __shfl_xor_sync(0xffffffffu, s0, o);
                s1 += __shfl_xor_sync(0xffffffffu, s1, o);
                s2 += __shfl_xor_sync(0xffffffffu, s2, o);
            }
            if (lane == 0) {
                outrow[0]  = tanhf(s0);
                outrow[41] = tanhf(s1);
                outrow[62] = tanhf(s2);
            }
        }
        #pragma unroll 2
        for (int m = 0; m < 20; m++) {
            float a0 = 0.f, a1 = 0.f, a2 = 0.f;
            #pragma unroll
            for (int c = 0; c < 7; c++) {
                const int d = lane + 32 * c;
                a0 = fmaf(gf[c], sW[m * 224 + d], a0);
                a1 = fmaf(ga[c], sW[(20 + m) * 224 + d], a1);
                a2 = fmaf(gm[c], sW[(40 + m) * 224 + d], a2);
            }
            #pragma unroll
            for (int o = 16; o > 0; o >>= 1) {
                a0 += __shfl_xor_sync(0xffffffffu, a0, o);
                a1 += __shfl_xor_sync(0xffffffffu, a1, o);
                a2 += __shfl_xor_sync(0xffffffffu, a2, o);
            }
            if (lane == 0) {
                outrow[1 + m]  = tanhf(a0);
                outrow[42 + m] = tanhf(a1);
                outrow[63 + m] = tanhf(a2);
            }
        }
    }
}

// ---------------------------------------------------------------------------
// Launch: two independent chains overlapped via a forked stream.
//   chain L  : k_prep -> k_mp_mma              (writes out cols 21..40)
//   chain S1 : k_proj -> k_s -> k_att -> k_epi (writes out cols 0..20, 41..82)
// Disjoint output bytes; no shared scratch between chains after the fork.
// Stream/events created per call (never destroyed; 2 harness calls total) —
// no device-memory allocation, identical captured work every call.
// ---------------------------------------------------------------------------
extern "C" void kernel_launch(void* const* d_in, const int* in_sizes, int n_in,
                              void* d_out, int out_size)
{
    const float* reps_lt   = (const float*)d_in[0];
    const float* reps_rt   = (const float*)d_in[1];
    const float* fw_h_rt   = (const float*)d_in[2];
    const float* bw_h_rt   = (const float*)d_in[3];
    const float* w_full    = (const float*)d_in[4];
    const float* w_maxpool = (const float*)d_in[5];
    const float* w_att     = (const float*)d_in[6];
    const float* w_maxatt  = (const float*)d_in[7];
    const float* attn_w1   = (const float*)d_in[8];
    const float* attn_w2   = (const float*)d_in[9];
    const float* diag_w    = (const float*)d_in[10];
    float* out = (float*)d_out;

    cudaFuncSetAttribute(k_mp_mma, cudaFuncAttributeMaxDynamicSharedMemorySize, MMA_SMEM_BYTES);
    cudaFuncSetAttribute(k_att, cudaFuncAttributeMaxDynamicSharedMemorySize, ATT_SMEM_BYTES);
    cudaFuncSetAttribute(k_epi, cudaFuncAttributeMaxDynamicSharedMemorySize, EPI_SMEM_BYTES);

    cudaStream_t s1;
    cudaEvent_t e0, e1;
    cudaStreamCreateWithFlags(&s1, cudaStreamNonBlocking);
    cudaEventCreateWithFlags(&e0, cudaEventDisableTiming);
    cudaEventCreateWithFlags(&e1, cudaEventDisableTiming);

    cudaEventRecord(e0, 0);
    cudaStreamWaitEvent(s1, e0, 0);

    // S1 chain
    dim3 g1(8, B);
    k_proj<<<g1, 128, 0, s1>>>(reps_lt, reps_rt, attn_w1, attn_w2, diag_w);
    k_s<<<B, 256, 0, s1>>>(reps_rt, reps_lt);
    dim3 g3(8, B);
    k_att<<<g3, 256, ATT_SMEM_BYTES, s1>>>(reps_lt);
    dim3 g4(8, B);
    k_epi<<<g4, 256, EPI_SMEM_BYTES, s1>>>(reps_lt, reps_rt, fw_h_rt, bw_h_rt,
                                           w_full, w_att, w_maxatt, out);
    cudaEventRecord(e1, s1);

    // L chain
    k_prep<<<B, 256>>>(reps_lt);
    dim3 g2(MP, B);
    k_mp_mma<<<g2, 256, MMA_SMEM_BYTES>>>(reps_rt, w_maxpool, out);

    cudaStreamWaitEvent(0, e1, 0);
}

// round 13
// speedup vs baseline: 4.0477x; 1.2942x over previous
#include <cuda_runtime.h>
#include <cuda_fp16.h>
#include <math.h>
#include <float.h>

// Shapes (fixed by the problem)
#define B 64
#define L 128
#define D 200
#define MP 20
#define ATT 50
#define OUTC 83   // 21 + 20 + 21 + 21

// ---------------------------------------------------------------------------
// Scratch (device globals; no allocations allowed)
// ---------------------------------------------------------------------------
__device__ float g_e_lt[B * L * ATT];      // tanh(lt @ w2)            [b,l,a]
__device__ float g_e_rt[B * L * ATT];      // tanh(rt @ w1) * diag     [b,r,a]
__device__ int   g_pos[B * L];             // argmax_l rel[r][l]       [b,r]
__device__ float g_att[B * L * D];         // attention-weighted lt    [b,r,d]
__device__ unsigned g_lt_h2[B * L * 128];  // lt fp16 packed pairs, Kpad=256

// ---------------------------------------------------------------------------
// Helpers (base-PTX only: ldmatrix sm_75+, mma.sync fp16 sm_80+, cp.async)
// ---------------------------------------------------------------------------
__device__ __forceinline__ unsigned smem_u32(const void* p) {
    unsigned a;
    asm("{ .reg .u64 t; cvta.to.shared.u64 t, %1; cvt.u32.u64 %0, t; }"
        : "=r"(a) : "l"(p));
    return a;
}
__device__ __forceinline__ void ldsm_x4(unsigned* r, unsigned addr) {
    asm volatile("ldmatrix.sync.aligned.m8n8.x4.shared.b16 {%0,%1,%2,%3}, [%4];"
                 : "=r"(r[0]), "=r"(r[1]), "=r"(r[2]), "=r"(r[3]) : "r"(addr));
}
__device__ __forceinline__ void mma_fp16(float* c, const unsigned* a,
                                         const unsigned* b) {
    asm volatile(
        "mma.sync.aligned.m16n8k16.row.col.f32.f16.f16.f32 "
        "{%0,%1,%2,%3}, {%4,%5,%6,%7}, {%8,%9}, {%0,%1,%2,%3};"
        : "+f"(c[0]), "+f"(c[1]), "+f"(c[2]), "+f"(c[3])
        : "r"(a[0]), "r"(a[1]), "r"(a[2]), "r"(a[3]), "r"(b[0]), "r"(b[1]));
}
__device__ __forceinline__ void cp_async16(unsigned dst, const void* src) {
    asm volatile("cp.async.ca.shared.global [%0], [%1], 16;"
                 :: "r"(dst), "l"(src) : "memory");
}
__device__ __forceinline__ void cp_async_commit() {
    asm volatile("cp.async.commit_group;" ::: "memory");
}
template <int N> __device__ __forceinline__ void cp_async_wait() {
    asm volatile("cp.async.wait_group %0;" :: "n"(N) : "memory");
}
__device__ __forceinline__ void cp_async_wait_all() {
    asm volatile("cp.async.commit_group;\ncp.async.wait_group 0;" ::: "memory");
}
// byte offset of 16-bit element (r, k) inside a [128][64] plane,
// XOR-swizzled so ldmatrix (8 rows x 16B) is bank-conflict-free.
__device__ __forceinline__ unsigned offp(int r, int k) {
    return (unsigned)(r * 128 + ((((k >> 3) ^ (r & 7)) & 7) << 4) + ((k & 7) << 1));
}

// ---------------------------------------------------------------------------
// Kernel 0: fp16 pack of lt (Kpad=256, zero-padded), packed pairs.
// ---------------------------------------------------------------------------
__global__ __launch_bounds__(256) void k_prep(const float* __restrict__ lt)
{
    const int b = blockIdx.x;
    for (int idx = threadIdx.x; idx < L * 128; idx += 256) {
        const int r = idx >> 7, kk = idx & 127, k = kk * 2;
        const float* rr = lt + ((size_t)(b * L + r)) * D;
        const float f0 = (k < 200) ? rr[k] : 0.f;
        const float f1 = (k + 1 < 200) ? rr[k + 1] : 0.f;
        __half2 h = __floats2half2_rn(f0, f1);
        g_lt_h2[(unsigned)(((b * L + r) << 7) + kk)] = *(unsigned*)&h;
    }
}

// ---------------------------------------------------------------------------
// Kernel 1: attention projections (norm section removed — k_s self-computes).
// ---------------------------------------------------------------------------
__global__ __launch_bounds__(128) void k_proj(
    const float* __restrict__ lt, const float* __restrict__ rt,
    const float* __restrict__ w1, const float* __restrict__ w2,
    const float* __restrict__ diag)
{
    __shared__ float sX[32][202];
    __shared__ float sD[64];

    const int tile = blockIdx.x, b = blockIdx.y;
    const int t = threadIdx.x;
    const int row0 = b * L + tile * 16;

    for (int idx = t; idx < 3200; idx += 128) {
        const int r = idx / 100, q = idx - r * 100;
        const int gr = row0 + (r & 15);
        const float* src = (r < 16) ? lt : rt;
        *(float2*)&sX[r][2 * q] = *(const float2*)&src[(size_t)gr * D + 2 * q];
    }
    if (t < ATT) sD[t] = diag[t];
    __syncthreads();

    if (t < 100) {
        const bool isLt = (t < 50);
        const int a = isLt ? t : t - 50;
        const float* wsrc = isLt ? w2 : w1;
        const int rbase = isLt ? 0 : 16;

        unsigned long long acc2[16];
        #pragma unroll
        for (int r = 0; r < 16; r++) acc2[r] = 0ull;

        #pragma unroll 2
        for (int d = 0; d < 200; d += 2) {
            const float wlo = wsrc[d * ATT + a];
            const float whi = wsrc[(d + 1) * ATT + a];
            unsigned long long w2r;
            asm("mov.b64 %0, {%1, %2};" : "=l"(w2r) : "f"(wlo), "f"(whi));
            #pragma unroll
            for (int r = 0; r < 16; r++) {
                const unsigned long long x2 =
                    *(const unsigned long long*)&sX[rbase + r][d];
                asm("fma.rn.f32x2 %0, %1, %2, %0;"
                    : "+l"(acc2[r]) : "l"(x2), "l"(w2r));
            }
        }
        #pragma unroll
        for (int r = 0; r < 16; r++) {
            float lo, hi;
            asm("mov.b64 {%0, %1}, %2;" : "=f"(lo), "=f"(hi) : "l"(acc2[r]));
            const float v = tanhf(lo + hi);
            if (isLt) g_e_lt[(size_t)(row0 + r) * ATT + a] = v;
            else      g_e_rt[(size_t)(row0 + r) * ATT + a] = v * sD[a];
        }
    }
}

// ---------------------------------------------------------------------------
// Kernel 1b: fp32 S = rt @ lt^T per batch, argmax_l S[r][l]/nl[l] -> g_pos.
// Norms now computed IN-KERNEL from the lt rows already streamed as the B
// operand (thread covers k = lc mod 8 slice; pair (tid, tid^1) covers a row).
// ---------------------------------------------------------------------------
__global__ __launch_bounds__(256, 2) void k_s(
    const float* __restrict__ rt, const float* __restrict__ lt)
{
    const int b = blockIdx.x;

    __shared__ float Asd[2][8][260];
    __shared__ float Bs[2][8][132];
    __shared__ float red_v[128][17];
    __shared__ int   red_i[128][17];
    __shared__ float sINL[128];

    const float* ab = rt + (size_t)b * L * D;
    const float* bbp = lt + (size_t)b * L * D;

    const int tid = threadIdx.x;
    const int ty = tid >> 4, tx = tid & 15;
    const int lr = tid >> 1, lc = (tid & 1) * 4;

    unsigned long long acc[8][4];
    #pragma unroll
    for (int i = 0; i < 8; i++)
        #pragma unroll
        for (int j = 0; j < 4; j++) acc[i][j] = 0ull;

    float nacc = 0.f;
    float4 ra, rb;
    auto ld_regs = [&](int k0) {
        ra = *reinterpret_cast<const float4*>(ab + lr * D + k0 + lc);
        rb = *reinterpret_cast<const float4*>(bbp + lr * D + k0 + lc);
    };
    auto st_smem = [&](int bf) {
        *reinterpret_cast<float2*>(&Asd[bf][lc + 0][2 * lr]) = make_float2(ra.x, ra.x);
        *reinterpret_cast<float2*>(&Asd[bf][lc + 1][2 * lr]) = make_float2(ra.y, ra.y);
        *reinterpret_cast<float2*>(&Asd[bf][lc + 2][2 * lr]) = make_float2(ra.z, ra.z);
        *reinterpret_cast<float2*>(&Asd[bf][lc + 3][2 * lr]) = make_float2(ra.w, ra.w);
        Bs[bf][lc + 0][lr] = rb.x; Bs[bf][lc + 1][lr] = rb.y;
        Bs[bf][lc + 2][lr] = rb.z; Bs[bf][lc + 3][lr] = rb.w;
        nacc = fmaf(rb.x, rb.x, fmaf(rb.y, rb.y, fmaf(rb.z, rb.z,
               fmaf(rb.w, rb.w, nacc))));
    };
    auto compute = [&](int bf) {
        #pragma unroll
        for (int kk = 0; kk < 8; kk++) {
            unsigned long long a2[8], b2[4];
            #pragma unroll
            for (int q = 0; q < 4; q++) {
                ulonglong2 v = *reinterpret_cast<const ulonglong2*>(
                    &Asd[bf][kk][2 * (ty * 8 + 2 * q)]);
                a2[2 * q] = v.x; a2[2 * q + 1] = v.y;
            }
            {
                ulonglong2 v0 = *reinterpret_cast<const ulonglong2*>(&Bs[bf][kk][8 * tx]);
                ulonglong2 v1 = *reinterpret_cast<const ulonglong2*>(&Bs[bf][kk][8 * tx + 4]);
                b2[0] = v0.x; b2[1] = v0.y; b2[2] = v1.x; b2[3] = v1.y;
            }
            #pragma unroll
            for (int i = 0; i < 8; i++)
                #pragma unroll
                for (int j = 0; j < 4; j++)
                    asm("fma.rn.f32x2 %0, %1, %2, %0;"
                        : "+l"(acc[i][j]) : "l"(a2[i]), "l"(b2[j]));
        }
    };

    ld_regs(0);
    st_smem(0);
    __syncthreads();
    #pragma unroll 1
    for (int kt = 1; kt < 25; kt++) {
        ld_regs(kt * 8);
        compute((kt - 1) & 1);
        st_smem(kt & 1);
        __syncthreads();
    }
    compute(0);

    // finish row norms: pair (tid, tid^1) covers row lr
    {
        const float other = __shfl_xor_sync(0xffffffffu, nacc, 1);
        if ((tid & 1) == 0)
            sINL[lr] = 1.0f / sqrtf(fmaxf(nacc + other, 1e-6f));
    }
    __syncthreads();

    #pragma unroll
    for (int i = 0; i < 8; i++) {
        float bv = -FLT_MAX; int bi = 0;
        #pragma unroll
        for (int j = 0; j < 4; j++) {
            const int l0 = 8 * tx + 2 * j;
            const unsigned long long v = acc[i][j];
            const float lo = __uint_as_float((unsigned)(v & 0xffffffffull)) * sINL[l0];
            const float hi = __uint_as_float((unsigned)(v >> 32)) * sINL[l0 + 1];
            if (lo > bv) { bv = lo; bi = l0; }
            if (hi > bv) { bv = hi; bi = l0 + 1; }
        }
        red_v[ty * 8 + i][tx] = bv;
        red_i[ty * 8 + i][tx] = bi;
    }
    __syncthreads();
    if (tid < 128) {
        float v = red_v[tid][0]; int idx = red_i[tid][0];
        #pragma unroll
        for (int x = 1; x < 16; x++)
            if (red_v[tid][x] > v) { v = red_v[tid][x]; idx = red_i[tid][x]; }
        g_pos[b * L + tid] = idx;
    }
}

// ---------------------------------------------------------------------------
// Kernel 2: maxpool match via SINGLE fp16 mma.sync (fp32 accum).
// tanh saturation at the max makes single fp16 safe here (err ~1e-4 << 1e-3).
// 1/3 the MMAs and 1/2 the conversion of the bf16-split version; smem 35 KB.
// ---------------------------------------------------------------------------
#define MMA_SMEM_BYTES 34816   // 32768 planes + 1024 sW[256] + 1024 sRED
__global__ __launch_bounds__(256, 2) void k_mp_mma(
    const float* __restrict__ rt, const float* __restrict__ wmp,
    float* __restrict__ out)
{
    extern __shared__ char smem[];
    const unsigned sb = smem_u32(smem);
    float* sW   = (float*)(smem + 32768);   // [256] w row, zero-padded
    float* sRED = (float*)(smem + 33792);   // [128][2]

    const int m = blockIdx.x, b = blockIdx.y;
    const int tid = threadIdx.x, wid = tid >> 5, lane = tid & 31;
    const int m0 = (wid & 3) * 32, n0 = (wid >> 2) * 64, wn = wid >> 2;

    for (int d = tid; d < 256; d += 256) sW[d] = (d < 200) ? wmp[m * 200 + d] : 0.f;
    __syncthreads();

    const int kk  = tid & 31;      // fixed k-pair column per thread
    const int rg8 = tid >> 5;      // row group 0..7 (16 rows each)

    auto load_chunk = [&](int c) {
        // A plane via cp.async 16B (precomputed lt fp16)
        for (int idx = tid; idx < 1024; idx += 256) {
            const int r = idx >> 3, kk4 = (idx & 7) * 4;
            const unsigned gi = (unsigned)(((b * L + r) << 7) + c * 32 + kk4);
            cp_async16(sb + offp(r, 2 * kk4), &g_lt_h2[gi]);
        }
        // B plane: (w (.) rt) -> fp16. Thread owns k = c*64 + 2*kk.
        const int k = c * 64 + 2 * kk;
        const float w0 = sW[k], w1 = sW[k + 1];
        const bool valid = (k < 200);
        #pragma unroll 4
        for (int j = 0; j < 16; j++) {
            const int row = rg8 * 16 + j;
            float f0 = 0.f, f1 = 0.f;
            if (valid) {
                const float2 v = *(const float2*)&rt[(size_t)(b * L + row) * D + k];
                f0 = v.x * w0;
                f1 = v.y * w1;
            }
            __half2 h = __floats2half2_rn(f0, f1);
            *(unsigned*)(smem + 16384 + offp(row, 2 * kk)) = *(unsigned*)&h;
        }
        cp_async_wait_all();
    };

    float acc[2][8][4];
    #pragma unroll
    for (int mt = 0; mt < 2; mt++)
        #pragma unroll
        for (int nt = 0; nt < 8; nt++)
            #pragma unroll
            for (int q = 0; q < 4; q++) acc[mt][nt][q] = 0.f;

    auto compute = [&](int nk) {
        for (int ks = 0; ks < nk; ks++) {
            unsigned ah[2][4], bb[4][4];
            const int kca = ks * 16 + ((lane >> 4) << 3);
            #pragma unroll
            for (int mt = 0; mt < 2; mt++)
                ldsm_x4(ah[mt], sb + offp(m0 + 16 * mt + (lane & 15), kca));
            const int kcb = ks * 16 + (((lane >> 3) & 1) << 3);
            const int rowb = (lane & 7) + ((lane >> 4) << 3);
            #pragma unroll
            for (int nt2 = 0; nt2 < 4; nt2++)
                ldsm_x4(bb[nt2], sb + 16384 + offp(n0 + nt2 * 16 + rowb, kcb));
            #pragma unroll
            for (int mt = 0; mt < 2; mt++)
                #pragma unroll
                for (int nt = 0; nt < 8; nt++)
                    mma_fp16(acc[mt][nt], ah[mt], &bb[nt >> 1][(nt & 1) * 2]);
        }
    };

    const int nks[4] = {4, 4, 4, 1};
    #pragma unroll 1
    for (int c = 0; c < 4; c++) {
        load_chunk(c);
        __syncthreads();
        compute(nks[c]);
        __syncthreads();
    }

    #pragma unroll
    for (int mt = 0; mt < 2; mt++) {
        float mxA = -FLT_MAX, mxB = -FLT_MAX;
        #pragma unroll
        for (int nt = 0; nt < 8; nt++) {
            mxA = fmaxf(mxA, fmaxf(acc[mt][nt][0], acc[mt][nt][1]));
            mxB = fmaxf(mxB, fmaxf(acc[mt][nt][2], acc[mt][nt][3]));
        }
        #pragma unroll
        for (int o = 1; o < 4; o <<= 1) {
            mxA = fmaxf(mxA, __shfl_xor_sync(0xffffffffu, mxA, o));
            mxB = fmaxf(mxB, __shfl_xor_sync(0xffffffffu, mxB, o));
        }
        if ((lane & 3) == 0) {
            const int ra = m0 + 16 * mt + (lane >> 2);
            sRED[ra * 2 + wn]       = mxA;
            sRED[(ra + 8) * 2 + wn] = mxB;
        }
    }
    __syncthreads();
    if (tid < 128) {
        const float v = fmaxf(sRED[tid * 2], sRED[tid * 2 + 1]);
        out[((size_t)(b * L + tid)) * OUTC + 21 + m] = tanhf(v);
    }
}

// ---------------------------------------------------------------------------
// Kernel 3a: attention (Z gemm, softmax, att = P @ lt) -> g_att.
// Streaming tiles shrunk to 8 rows: smem ~51 KB -> 4 CTAs/SM, sub-1-wave grid.
// ---------------------------------------------------------------------------
#define ATT_SMEM_BYTES (12720 * 4)
__global__ __launch_bounds__(256, 4) void k_att(const float* __restrict__ lt)
{
    extern __shared__ float sm[];
    float* sEL = sm;            // [128][51]
    float* sER = sm + 6528;     // [16][51]
    float* sZP = sm + 7344;     // [16][132]
    float* sT  = sm + 9456;     // [2][8][204]
    const unsigned sTb = smem_u32(sT);

    const int tile = blockIdx.x, b = blockIdx.y;
    const int t = threadIdx.x;
    const int lane = t & 31, w = t >> 5;   // 8 warps
    const int r0g = tile * 16;
    const float* ltb = lt + (size_t)b * L * D;

    auto issue = [&](int T) {
        const float* src = ltb + (size_t)(T * 8) * D;
        for (int idx = t; idx < 400; idx += 256) {
            const int l = idx / 50, q = idx - l * 50;
            cp_async16(sTb + (T & 1) * 6528 + l * 816 + q * 16,
                       src + (size_t)l * D + 4 * q);
        }
        cp_async_commit();
    };

    issue(0);
    issue(1);

    for (int idx = t; idx < L * ATT; idx += 256) {
        const int l = idx / 50, k = idx - l * 50;
        sEL[l * 51 + k] = g_e_lt[(size_t)b * L * ATT + idx];
    }
    for (int idx = t; idx < 16 * ATT; idx += 256) {
        const int j = idx / 50, k = idx - j * 50;
        sER[j * 51 + k] = g_e_rt[(size_t)(b * L + r0g) * ATT + idx];
    }
    __syncthreads();

    // Z = e_rt_tile @ e_lt^T
    {
        const int c = t & 127, rr = t >> 7;
        float acc[8];
        #pragma unroll
        for (int j = 0; j < 8; j++) acc[j] = 0.f;
        #pragma unroll 2
        for (int a = 0; a < 50; a++) {
            const float x = sEL[c * 51 + a];
            #pragma unroll
            for (int j = 0; j < 8; j++)
                acc[j] = fmaf(sER[(rr + 2 * j) * 51 + a], x, acc[j]);
        }
        #pragma unroll
        for (int j = 0; j < 8; j++) sZP[(rr + 2 * j) * 132 + c] = acc[j];
    }
    __syncthreads();

    // softmax over l (warp w -> rows 2w, 2w+1)
    #pragma unroll
    for (int rr = 0; rr < 2; rr++) {
        const int r = 2 * w + rr;
        float zv[4];
        float zm = -FLT_MAX;
        #pragma unroll
        for (int q = 0; q < 4; q++) {
            zv[q] = sZP[r * 132 + lane + 32 * q];
            zm = fmaxf(zm, zv[q]);
        }
        #pragma unroll
        for (int o = 16; o > 0; o >>= 1)
            zm = fmaxf(zm, __shfl_xor_sync(0xffffffffu, zm, o));
        float s = 0.f;
        #pragma unroll
        for (int q = 0; q < 4; q++) { zv[q] = expf(zv[q] - zm); s += zv[q]; }
        #pragma unroll
        for (int o = 16; o > 0; o >>= 1)
            s += __shfl_xor_sync(0xffffffffu, s, o);
        const float inv = 1.0f / s;
        #pragma unroll
        for (int q = 0; q < 4; q++)
            sZP[r * 132 + lane + 32 * q] = zv[q] * inv;
    }
    __syncthreads();

    // att = P @ lt (streamed 8-row tiles)
    {
        const int rg = t >> 6, c = t & 63;
        const bool q3 = (c < 8);
        float acc[4][4];
        #pragma unroll
        for (int i = 0; i < 4; i++)
            #pragma unroll
            for (int q = 0; q < 4; q++) acc[i][q] = 0.f;

        #pragma unroll 1
        for (int T = 0; T < 16; T++) {
            if (T < 15) cp_async_wait<1>(); else cp_async_wait<0>();
            __syncthreads();
            const float* tb = &sT[(T & 1) * 1632];
            #pragma unroll
            for (int lo = 0; lo < 8; lo++) {
                const int l = T * 8 + lo;
                const float p0 = sZP[rg * 132 + l];
                const float p1 = sZP[(rg + 4) * 132 + l];
                const float p2 = sZP[(rg + 8) * 132 + l];
                const float p3 = sZP[(rg + 12) * 132 + l];
                const float* row = &tb[lo * 204 + c];
                const float v0 = row[0], v1 = row[64], v2 = row[128];
                acc[0][0] = fmaf(p0, v0, acc[0][0]); acc[1][0] = fmaf(p1, v0, acc[1][0]);
                acc[2][0] = fmaf(p2, v0, acc[2][0]); acc[3][0] = fmaf(p3, v0, acc[3][0]);
                acc[0][1] = fmaf(p0, v1, acc[0][1]); acc[1][1] = fmaf(p1, v1, acc[1][1]);
                acc[2][1] = fmaf(p2, v1, acc[2][1]); acc[3][1] = fmaf(p3, v1, acc[3][1]);
                acc[0][2] = fmaf(p0, v2, acc[0][2]); acc[1][2] = fmaf(p1, v2, acc[1][2]);
                acc[2][2] = fmaf(p2, v2, acc[2][2]); acc[3][2] = fmaf(p3, v2, acc[3][2]);
                if (q3) {
                    const float v3 = row[192];
                    acc[0][3] = fmaf(p0, v3, acc[0][3]); acc[1][3] = fmaf(p1, v3, acc[1][3]);
                    acc[2][3] = fmaf(p2, v3, acc[2][3]); acc[3][3] = fmaf(p3, v3, acc[3][3]);
                }
            }
            __syncthreads();
            if (T < 14) issue(T + 2);
        }

        #pragma unroll
        for (int i = 0; i < 4; i++) {
            float* dst = g_att + (size_t)(b * L + r0g + rg + 4 * i) * D;
            dst[c]       = acc[i][0];
            dst[c + 64]  = acc[i][1];
            dst[c + 128] = acc[i][2];
            if (q3) dst[c + 192] = acc[i][3];
        }
    }
}

// ---------------------------------------------------------------------------
// Kernel 3b: epilogue — full/attentive/max-attentive dots + tanh (unchanged).
// ---------------------------------------------------------------------------
#define EPI_SMEM_BYTES (13664 * 4)
__global__ __launch_bounds__(256) void k_epi(
    const float* __restrict__ lt, const float* __restrict__ rt,
    const float* __restrict__ fw, const float* __restrict__ bw,
    const float* __restrict__ w_full, const float* __restrict__ w_att,
    const float* __restrict__ w_maxatt, float* __restrict__ out)
{
    extern __shared__ float sm[];
    float* sW  = sm;                   // [60][224] zero-padded
    float* sH  = sm + 13440;           // [204]
    int*   sPOS = (int*)(sm + 13644);  // [16]

    const int tile = blockIdx.x, b = blockIdx.y;
    const int t = threadIdx.x;
    const int lane = t & 31, w = t >> 5;   // 8 warps
    const int r0g = tile * 16;

    for (int idx = t; idx < 60 * 56; idx += 256) {
        const int mrow = idx / 56, q = idx - mrow * 56;
        float4 v = make_float4(0.f, 0.f, 0.f, 0.f);
        if (q < 50) {
            const float* src = (mrow < 20) ? w_full + mrow * 200
                             : (mrow < 40) ? w_att + (mrow - 20) * 200
                                           : w_maxatt + (mrow - 40) * 200;
            v = *(const float4*)(src + 4 * q);
        }
        *(float4*)&sW[mrow * 224 + 4 * q] = v;
    }
    if (t < 204) { sH[t] = (t < 100) ? fw[b * 100 + t]
                         : (t < 200) ? bw[b * 100 + t - 100] : 0.f; }
    if (t < 16) sPOS[t] = g_pos[b * L + r0g + t];
    __syncthreads();

    #pragma unroll 1
    for (int rr = 0; rr < 2; rr++) {
        const int j = 2 * w + rr;
        const int gr = r0g + j;
        const int pos = sPOS[j];
        const float* ltrow  = lt + (size_t)(b * L + gr) * D;
        const float* rtrow  = rt + (size_t)(b * L + gr) * D;
        const float* atrow  = g_att + (size_t)(b * L + gr) * D;
        const float* posrow = lt + (size_t)(b * L + pos) * D;
        float* outrow = out + (size_t)(b * L + gr) * OUTC;

        float gf[7], ga[7], gm[7];
        #pragma unroll
        for (int c = 0; c < 7; c++) {
            const int d = lane + 32 * c;
            const bool ok = (c < 6) || (lane < 8);
            const float xl = ok ? ltrow[d] : 0.f;
            const float xh = ok ? sH[d] : 0.f;
            const float xa = ok ? atrow[d] : 0.f;
            const float xr = ok ? rtrow[d] : 0.f;
            const float xp = ok ? posrow[d] : 0.f;
            gf[c] = xl * xh;
            ga[c] = xa * xr;
            gm[c] = xr * xp;
        }
        {
            float s0 = 0.f, s1 = 0.f, s2 = 0.f;
            #pragma unroll
            for (int c = 0; c < 7; c++) { s0 += gf[c]; s1 += ga[c]; s2 += gm[c]; }
            #pragma unroll
            for (int o = 16; o > 0; o >>= 1) {
                s0 += __shfl_xor_sync(0xffffffffu, s0, o);
                s1 += __shfl_xor_sync(0xffffffffu, s1, o);
                s2 += __shfl_xor_sync(0xffffffffu, s2, o);
            }
            if (lane == 0) {
                outrow[0]  = tanhf(s0);
                outrow[41] = tanhf(s1);
                outrow[62] = tanhf(s2);
            }
        }
        #pragma unroll 2
        for (int m = 0; m < 20; m++) {
            float a0 = 0.f, a1 = 0.f, a2 = 0.f;
            #pragma unroll
            for (int c = 0; c < 7; c++) {
                const int d = lane + 32 * c;
                a0 = fmaf(gf[c], sW[m * 224 + d], a0);
                a1 = fmaf(ga[c], sW[(20 + m) * 224 + d], a1);
                a2 = fmaf(gm[c], sW[(40 + m) * 224 + d], a2);
            }
            #pragma unroll
            for (int o = 16; o > 0; o >>= 1) {
                a0 += __shfl_xor_sync(0xffffffffu, a0, o);
                a1 += __shfl_xor_sync(0xffffffffu, a1, o);
                a2 += __shfl_xor_sync(0xffffffffu, a2, o);
            }
            if (lane == 0) {
                outrow[1 + m]  = tanhf(a0);
                outrow[42 + m] = tanhf(a1);
                outrow[63 + m] = tanhf(a2);
            }
        }
    }
}

// ---------------------------------------------------------------------------
// Launch topology (graph-capturable; same every call):
//   default (L): k_s -> [e_s] -> k_prep -> k_mp_mma          (out cols 21..40)
//   s1      (S): k_proj -> k_att -> (wait e_s) -> k_epi      (out cols 0..20,41..82)
//   default waits e1 (end of S).
// ---------------------------------------------------------------------------
extern "C" void kernel_launch(void* const* d_in, const int* in_sizes, int n_in,
                              void* d_out, int out_size)
{
    const float* reps_lt   = (const float*)d_in[0];
    const float* reps_rt   = (const float*)d_in[1];
    const float* fw_h_rt   = (const float*)d_in[2];
    const float* bw_h_rt   = (const float*)d_in[3];
    const float* w_full    = (const float*)d_in[4];
    const float* w_maxpool = (const float*)d_in[5];
    const float* w_att     = (const float*)d_in[6];
    const float* w_maxatt  = (const float*)d_in[7];
    const float* attn_w1   = (const float*)d_in[8];
    const float* attn_w2   = (const float*)d_in[9];
    const float* diag_w    = (const float*)d_in[10];
    float* out = (float*)d_out;

    cudaFuncSetAttribute(k_mp_mma, cudaFuncAttributeMaxDynamicSharedMemorySize, MMA_SMEM_BYTES);
    cudaFuncSetAttribute(k_att, cudaFuncAttributeMaxDynamicSharedMemorySize, ATT_SMEM_BYTES);
    cudaFuncSetAttribute(k_epi, cudaFuncAttributeMaxDynamicSharedMemorySize, EPI_SMEM_BYTES);

    cudaStream_t s1;
    cudaEvent_t e0, es, e1;
    cudaStreamCreateWithFlags(&s1, cudaStreamNonBlocking);
    cudaEventCreateWithFlags(&e0, cudaEventDisableTiming);
    cudaEventCreateWithFlags(&es, cudaEventDisableTiming);
    cudaEventCreateWithFlags(&e1, cudaEventDisableTiming);

    cudaEventRecord(e0, 0);
    cudaStreamWaitEvent(s1, e0, 0);

    // S chain (part 1)
    dim3 g1(8, B);
    k_proj<<<g1, 128, 0, s1>>>(reps_lt, reps_rt, attn_w1, attn_w2, diag_w);
    dim3 g3(8, B);
    k_att<<<g3, 256, ATT_SMEM_BYTES, s1>>>(reps_lt);

    // L chain
    k_s<<<B, 256>>>(reps_rt, reps_lt);
    cudaEventRecord(es, 0);
    k_prep<<<B, 256>>>(reps_lt);
    dim3 g2(MP, B);
    k_mp_mma<<<g2, 256, MMA_SMEM_BYTES>>>(reps_rt, w_maxpool, out);

    // S chain (part 2) — epi needs g_pos (L) + g_att (S)
    cudaStreamWaitEvent(s1, es, 0);
    dim3 g4(8, B);
    k_epi<<<g4, 256, EPI_SMEM_BYTES, s1>>>(reps_lt, reps_rt, fw_h_rt, bw_h_rt,
                                           w_full, w_att, w_maxatt, out);
    cudaEventRecord(e1, s1);

    cudaStreamWaitEvent(0, e1, 0);
}

// round 16
// speedup vs baseline: 4.2132x; 1.0409x over previous
#include <cuda_runtime.h>
#include <cuda_fp16.h>
#include <math.h>
#include <float.h>

// Shapes (fixed by the problem)
#define B 64
#define L 128
#define D 200
#define MP 20
#define ATT 50
#define OUTC 83   // 21 + 20 + 21 + 21

// ---------------------------------------------------------------------------
// Scratch (device globals; no allocations allowed)
// ---------------------------------------------------------------------------
__device__ float g_e_lt[B * L * ATT];      // tanh(lt @ w2)            [b,l,a]
__device__ float g_e_rt[B * L * ATT];      // tanh(rt @ w1) * diag     [b,r,a]
__device__ int   g_pos[B * L];             // argmax_l rel[r][l]       [b,r]
__device__ float g_att[B * L * D];         // attention-weighted lt    [b,r,d]
__device__ float g_G[3 * B * L * 200];     // gating vectors (full/att/maxatt)
__device__ unsigned g_lt_h2[B * L * 128];  // lt fp16 packed pairs, Kpad=256

// ---------------------------------------------------------------------------
// Helpers (base-PTX only: ldmatrix sm_75+, mma.sync fp16 sm_80+, cp.async)
// ---------------------------------------------------------------------------
__device__ __forceinline__ unsigned smem_u32(const void* p) {
    unsigned a;
    asm("{ .reg .u64 t; cvta.to.shared.u64 t, %1; cvt.u32.u64 %0, t; }"
        : "=r"(a) : "l"(p));
    return a;
}
__device__ __forceinline__ void ldsm_x4(unsigned* r, unsigned addr) {
    asm volatile("ldmatrix.sync.aligned.m8n8.x4.shared.b16 {%0,%1,%2,%3}, [%4];"
                 : "=r"(r[0]), "=r"(r[1]), "=r"(r[2]), "=r"(r[3]) : "r"(addr));
}
__device__ __forceinline__ void mma_fp16(float* c, const unsigned* a,
                                         const unsigned* b) {
    asm volatile(
        "mma.sync.aligned.m16n8k16.row.col.f32.f16.f16.f32 "
        "{%0,%1,%2,%3}, {%4,%5,%6,%7}, {%8,%9}, {%0,%1,%2,%3};"
        : "+f"(c[0]), "+f"(c[1]), "+f"(c[2]), "+f"(c[3])
        : "r"(a[0]), "r"(a[1]), "r"(a[2]), "r"(a[3]), "r"(b[0]), "r"(b[1]));
}
__device__ __forceinline__ void cp_async16(unsigned dst, const void* src) {
    asm volatile("cp.async.ca.shared.global [%0], [%1], 16;"
                 :: "r"(dst), "l"(src) : "memory");
}
__device__ __forceinline__ void cp_async_commit() {
    asm volatile("cp.async.commit_group;" ::: "memory");
}
template <int N> __device__ __forceinline__ void cp_async_wait() {
    asm volatile("cp.async.wait_group %0;" :: "n"(N) : "memory");
}
__device__ __forceinline__ void cp_async_wait_all() {
    asm volatile("cp.async.commit_group;\ncp.async.wait_group 0;" ::: "memory");
}
// byte offset of 16-bit element (r, k) inside a [128][64] plane,
// XOR-swizzled so ldmatrix (8 rows x 16B) is bank-conflict-free.
__device__ __forceinline__ unsigned offp(int r, int k) {
    return (unsigned)(r * 128 + ((((k >> 3) ^ (r & 7)) & 7) << 4) + ((k & 7) << 1));
}

// ---------------------------------------------------------------------------
// Kernel 0: fp16 pack of lt (Kpad=256, zero-padded). Grid (8, B): 512 blocks.
// ---------------------------------------------------------------------------
__global__ __launch_bounds__(256) void k_prep(const float* __restrict__ lt)
{
    const int tile = blockIdx.x, b = blockIdx.y;
    const int row0 = b * L + tile * 16;
    for (int idx = threadIdx.x; idx < 16 * 128; idx += 256) {
        const int r = idx >> 7, kk = idx & 127, k = kk * 2;
        const float* rr = lt + ((size_t)(row0 + r)) * D;
        const float f0 = (k < 200) ? rr[k] : 0.f;
        const float f1 = (k + 1 < 200) ? rr[k + 1] : 0.f;
        __half2 h = __floats2half2_rn(f0, f1);
        g_lt_h2[(unsigned)(((row0 + r) << 7) + kk)] = *(unsigned*)&h;
    }
}

// ---------------------------------------------------------------------------
// Kernel 1: attention projections (unchanged).
// ---------------------------------------------------------------------------
__global__ __launch_bounds__(128) void k_proj(
    const float* __restrict__ lt, const float* __restrict__ rt,
    const float* __restrict__ w1, const float* __restrict__ w2,
    const float* __restrict__ diag)
{
    __shared__ float sX[32][202];
    __shared__ float sD[64];

    const int tile = blockIdx.x, b = blockIdx.y;
    const int t = threadIdx.x;
    const int row0 = b * L + tile * 16;

    for (int idx = t; idx < 3200; idx += 128) {
        const int r = idx / 100, q = idx - r * 100;
        const int gr = row0 + (r & 15);
        const float* src = (r < 16) ? lt : rt;
        *(float2*)&sX[r][2 * q] = *(const float2*)&src[(size_t)gr * D + 2 * q];
    }
    if (t < ATT) sD[t] = diag[t];
    __syncthreads();

    if (t < 100) {
        const bool isLt = (t < 50);
        const int a = isLt ? t : t - 50;
        const float* wsrc = isLt ? w2 : w1;
        const int rbase = isLt ? 0 : 16;

        unsigned long long acc2[16];
        #pragma unroll
        for (int r = 0; r < 16; r++) acc2[r] = 0ull;

        #pragma unroll 2
        for (int d = 0; d < 200; d += 2) {
            const float wlo = wsrc[d * ATT + a];
            const float whi = wsrc[(d + 1) * ATT + a];
            unsigned long long w2r;
            asm("mov.b64 %0, {%1, %2};" : "=l"(w2r) : "f"(wlo), "f"(whi));
            #pragma unroll
            for (int r = 0; r < 16; r++) {
                const unsigned long long x2 =
                    *(const unsigned long long*)&sX[rbase + r][d];
                asm("fma.rn.f32x2 %0, %1, %2, %0;"
                    : "+l"(acc2[r]) : "l"(x2), "l"(w2r));
            }
        }
        #pragma unroll
        for (int r = 0; r < 16; r++) {
            float lo, hi;
            asm("mov.b64 {%0, %1}, %2;" : "=f"(lo), "=f"(hi) : "l"(acc2[r]));
            const float v = tanhf(lo + hi);
            if (isLt) g_e_lt[(size_t)(row0 + r) * ATT + a] = v;
            else      g_e_rt[(size_t)(row0 + r) * ATT + a] = v * sD[a];
        }
    }
}

// ---------------------------------------------------------------------------
// Kernel 1b: fp32 S = rt @ lt^T per batch, argmax -> g_pos (unchanged).
// ---------------------------------------------------------------------------
__global__ __launch_bounds__(256, 2) void k_s(
    const float* __restrict__ rt, const float* __restrict__ lt)
{
    const int b = blockIdx.x;

    __shared__ float Asd[2][8][260];
    __shared__ float Bs[2][8][132];
    __shared__ float red_v[128][17];
    __shared__ int   red_i[128][17];
    __shared__ float sINL[128];

    const float* ab = rt + (size_t)b * L * D;
    const float* bbp = lt + (size_t)b * L * D;

    const int tid = threadIdx.x;
    const int ty = tid >> 4, tx = tid & 15;
    const int lr = tid >> 1, lc = (tid & 1) * 4;

    unsigned long long acc[8][4];
    #pragma unroll
    for (int i = 0; i < 8; i++)
        #pragma unroll
        for (int j = 0; j < 4; j++) acc[i][j] = 0ull;

    float nacc = 0.f;
    float4 ra, rb;
    auto ld_regs = [&](int k0) {
        ra = *reinterpret_cast<const float4*>(ab + lr * D + k0 + lc);
        rb = *reinterpret_cast<const float4*>(bbp + lr * D + k0 + lc);
    };
    auto st_smem = [&](int bf) {
        *reinterpret_cast<float2*>(&Asd[bf][lc + 0][2 * lr]) = make_float2(ra.x, ra.x);
        *reinterpret_cast<float2*>(&Asd[bf][lc + 1][2 * lr]) = make_float2(ra.y, ra.y);
        *reinterpret_cast<float2*>(&Asd[bf][lc + 2][2 * lr]) = make_float2(ra.z, ra.z);
        *reinterpret_cast<float2*>(&Asd[bf][lc + 3][2 * lr]) = make_float2(ra.w, ra.w);
        Bs[bf][lc + 0][lr] = rb.x; Bs[bf][lc + 1][lr] = rb.y;
        Bs[bf][lc + 2][lr] = rb.z; Bs[bf][lc + 3][lr] = rb.w;
        nacc = fmaf(rb.x, rb.x, fmaf(rb.y, rb.y, fmaf(rb.z, rb.z,
               fmaf(rb.w, rb.w, nacc))));
    };
    auto compute = [&](int bf) {
        #pragma unroll
        for (int kk = 0; kk < 8; kk++) {
            unsigned long long a2[8], b2[4];
            #pragma unroll
            for (int q = 0; q < 4; q++) {
                ulonglong2 v = *reinterpret_cast<const ulonglong2*>(
                    &Asd[bf][kk][2 * (ty * 8 + 2 * q)]);
                a2[2 * q] = v.x; a2[2 * q + 1] = v.y;
            }
            {
                ulonglong2 v0 = *reinterpret_cast<const ulonglong2*>(&Bs[bf][kk][8 * tx]);
                ulonglong2 v1 = *reinterpret_cast<const ulonglong2*>(&Bs[bf][kk][8 * tx + 4]);
                b2[0] = v0.x; b2[1] = v0.y; b2[2] = v1.x; b2[3] = v1.y;
            }
            #pragma unroll
            for (int i = 0; i < 8; i++)
                #pragma unroll
                for (int j = 0; j < 4; j++)
                    asm("fma.rn.f32x2 %0, %1, %2, %0;"
                        : "+l"(acc[i][j]) : "l"(a2[i]), "l"(b2[j]));
        }
    };

    ld_regs(0);
    st_smem(0);
    __syncthreads();
    #pragma unroll 1
    for (int kt = 1; kt < 25; kt++) {
        ld_regs(kt * 8);
        compute((kt - 1) & 1);
        st_smem(kt & 1);
        __syncthreads();
    }
    compute(0);

    {
        const float other = __shfl_xor_sync(0xffffffffu, nacc, 1);
        if ((tid & 1) == 0)
            sINL[lr] = 1.0f / sqrtf(fmaxf(nacc + other, 1e-6f));
    }
    __syncthreads();

    #pragma unroll
    for (int i = 0; i < 8; i++) {
        float bv = -FLT_MAX; int bi = 0;
        #pragma unroll
        for (int j = 0; j < 4; j++) {
            const int l0 = 8 * tx + 2 * j;
            const unsigned long long v = acc[i][j];
            const float lo = __uint_as_float((unsigned)(v & 0xffffffffull)) * sINL[l0];
            const float hi = __uint_as_float((unsigned)(v >> 32)) * sINL[l0 + 1];
            if (lo > bv) { bv = lo; bi = l0; }
            if (hi > bv) { bv = hi; bi = l0 + 1; }
        }
        red_v[ty * 8 + i][tx] = bv;
        red_i[ty * 8 + i][tx] = bi;
    }
    __syncthreads();
    if (tid < 128) {
        float v = red_v[tid][0]; int idx = red_i[tid][0];
        #pragma unroll
        for (int x = 1; x < 16; x++)
            if (red_v[tid][x] > v) { v = red_v[tid][x]; idx = red_i[tid][x]; }
        g_pos[b * L + tid] = idx;
    }
}

// ---------------------------------------------------------------------------
// Kernel 2: maxpool match via SINGLE fp16 mma.sync (unchanged from round 13).
// ---------------------------------------------------------------------------
#define MMA_SMEM_BYTES 34816   // 32768 planes + 1024 sW[256] + 1024 sRED
__global__ __launch_bounds__(256, 2) void k_mp_mma(
    const float* __restrict__ rt, const float* __restrict__ wmp,
    float* __restrict__ out)
{
    extern __shared__ char smem[];
    const unsigned sb = smem_u32(smem);
    float* sW   = (float*)(smem + 32768);   // [256] w row, zero-padded
    float* sRED = (float*)(smem + 33792);   // [128][2]

    const int m = blockIdx.x, b = blockIdx.y;
    const int tid = threadIdx.x, wid = tid >> 5, lane = tid & 31;
    const int m0 = (wid & 3) * 32, n0 = (wid >> 2) * 64, wn = wid >> 2;

    for (int d = tid; d < 256; d += 256) sW[d] = (d < 200) ? wmp[m * 200 + d] : 0.f;
    __syncthreads();

    const int kk  = tid & 31;
    const int rg8 = tid >> 5;

    auto load_chunk = [&](int c) {
        for (int idx = tid; idx < 1024; idx += 256) {
            const int r = idx >> 3, kk4 = (idx & 7) * 4;
            const unsigned gi = (unsigned)(((b * L + r) << 7) + c * 32 + kk4);
            cp_async16(sb + offp(r, 2 * kk4), &g_lt_h2[gi]);
        }
        const int k = c * 64 + 2 * kk;
        const float w0 = sW[k], w1 = sW[k + 1];
        const bool valid = (k < 200);
        #pragma unroll 4
        for (int j = 0; j < 16; j++) {
            const int row = rg8 * 16 + j;
            float f0 = 0.f, f1 = 0.f;
            if (valid) {
                const float2 v = *(const float2*)&rt[(size_t)(b * L + row) * D + k];
                f0 = v.x * w0;
                f1 = v.y * w1;
            }
            __half2 h = __floats2half2_rn(f0, f1);
            *(unsigned*)(smem + 16384 + offp(row, 2 * kk)) = *(unsigned*)&h;
        }
        cp_async_wait_all();
    };

    float acc[2][8][4];
    #pragma unroll
    for (int mt = 0; mt < 2; mt++)
        #pragma unroll
        for (int nt = 0; nt < 8; nt++)
            #pragma unroll
            for (int q = 0; q < 4; q++) acc[mt][nt][q] = 0.f;

    auto compute = [&](int nk) {
        for (int ks = 0; ks < nk; ks++) {
            unsigned ah[2][4], bb[4][4];
            const int kca = ks * 16 + ((lane >> 4) << 3);
            #pragma unroll
            for (int mt = 0; mt < 2; mt++)
                ldsm_x4(ah[mt], sb + offp(m0 + 16 * mt + (lane & 15), kca));
            const int kcb = ks * 16 + (((lane >> 3) & 1) << 3);
            const int rowb = (lane & 7) + ((lane >> 4) << 3);
            #pragma unroll
            for (int nt2 = 0; nt2 < 4; nt2++)
                ldsm_x4(bb[nt2], sb + 16384 + offp(n0 + nt2 * 16 + rowb, kcb));
            #pragma unroll
            for (int mt = 0; mt < 2; mt++)
                #pragma unroll
                for (int nt = 0; nt < 8; nt++)
                    mma_fp16(acc[mt][nt], ah[mt], &bb[nt >> 1][(nt & 1) * 2]);
        }
    };

    const int nks[4] = {4, 4, 4, 1};
    #pragma unroll 1
    for (int c = 0; c < 4; c++) {
        load_chunk(c);
        __syncthreads();
        compute(nks[c]);
        __syncthreads();
    }

    #pragma unroll
    for (int mt = 0; mt < 2; mt++) {
        float mxA = -FLT_MAX, mxB = -FLT_MAX;
        #pragma unroll
        for (int nt = 0; nt < 8; nt++) {
            mxA = fmaxf(mxA, fmaxf(acc[mt][nt][0], acc[mt][nt][1]));
            mxB = fmaxf(mxB, fmaxf(acc[mt][nt][2], acc[mt][nt][3]));
        }
        #pragma unroll
        for (int o = 1; o < 4; o <<= 1) {
            mxA = fmaxf(mxA, __shfl_xor_sync(0xffffffffu, mxA, o));
            mxB = fmaxf(mxB, __shfl_xor_sync(0xffffffffu, mxB, o));
        }
        if ((lane & 3) == 0) {
            const int ra = m0 + 16 * mt + (lane >> 2);
            sRED[ra * 2 + wn]       = mxA;
            sRED[(ra + 8) * 2 + wn] = mxB;
        }
    }
    __syncthreads();
    if (tid < 128) {
        const float v = fmaxf(sRED[tid * 2], sRED[tid * 2 + 1]);
        out[((size_t)(b * L + tid)) * OUTC + 21 + m] = tanhf(v);
    }
}

// ---------------------------------------------------------------------------
// Kernel 3a: attention (Z gemm, softmax, att = P @ lt) -> g_att (unchanged).
// ---------------------------------------------------------------------------
#define ATT_SMEM_BYTES (12720 * 4)
__global__ __launch_bounds__(256, 4) void k_att(const float* __restrict__ lt)
{
    extern __shared__ float sm[];
    float* sEL = sm;            // [128][51]
    float* sER = sm + 6528;     // [16][51]
    float* sZP = sm + 7344;     // [16][132]
    float* sT  = sm + 9456;     // [2][8][204]
    const unsigned sTb = smem_u32(sT);

    const int tile = blockIdx.x, b = blockIdx.y;
    const int t = threadIdx.x;
    const int lane = t & 31, w = t >> 5;   // 8 warps
    const int r0g = tile * 16;
    const float* ltb = lt + (size_t)b * L * D;

    auto issue = [&](int T) {
        const float* src = ltb + (size_t)(T * 8) * D;
        for (int idx = t; idx < 400; idx += 256) {
            const int l = idx / 50, q = idx - l * 50;
            cp_async16(sTb + (T & 1) * 6528 + l * 816 + q * 16,
                       src + (size_t)l * D + 4 * q);
        }
        cp_async_commit();
    };

    issue(0);
    issue(1);

    for (int idx = t; idx < L * ATT; idx += 256) {
        const int l = idx / 50, k = idx - l * 50;
        sEL[l * 51 + k] = g_e_lt[(size_t)b * L * ATT + idx];
    }
    for (int idx = t; idx < 16 * ATT; idx += 256) {
        const int j = idx / 50, k = idx - j * 50;
        sER[j * 51 + k] = g_e_rt[(size_t)(b * L + r0g) * ATT + idx];
    }
    __syncthreads();

    {
        const int c = t & 127, rr = t >> 7;
        float acc[8];
        #pragma unroll
        for (int j = 0; j < 8; j++) acc[j] = 0.f;
        #pragma unroll 2
        for (int a = 0; a < 50; a++) {
            const float x = sEL[c * 51 + a];
            #pragma unroll
            for (int j = 0; j < 8; j++)
                acc[j] = fmaf(sER[(rr + 2 * j) * 51 + a], x, acc[j]);
        }
        #pragma unroll
        for (int j = 0; j < 8; j++) sZP[(rr + 2 * j) * 132 + c] = acc[j];
    }
    __syncthreads();

    #pragma unroll
    for (int rr = 0; rr < 2; rr++) {
        const int r = 2 * w + rr;
        float zv[4];
        float zm = -FLT_MAX;
        #pragma unroll
        for (int q = 0; q < 4; q++) {
            zv[q] = sZP[r * 132 + lane + 32 * q];
            zm = fmaxf(zm, zv[q]);
        }
        #pragma unroll
        for (int o = 16; o > 0; o >>= 1)
            zm = fmaxf(zm, __shfl_xor_sync(0xffffffffu, zm, o));
        float s = 0.f;
        #pragma unroll
        for (int q = 0; q < 4; q++) { zv[q] = expf(zv[q] - zm); s += zv[q]; }
        #pragma unroll
        for (int o = 16; o > 0; o >>= 1)
            s += __shfl_xor_sync(0xffffffffu, s, o);
        const float inv = 1.0f / s;
        #pragma unroll
        for (int q = 0; q < 4; q++)
            sZP[r * 132 + lane + 32 * q] = zv[q] * inv;
    }
    __syncthreads();

    {
        const int rg = t >> 6, c = t & 63;
        const bool q3 = (c < 8);
        float acc[4][4];
        #pragma unroll
        for (int i = 0; i < 4; i++)
            #pragma unroll
            for (int q = 0; q < 4; q++) acc[i][q] = 0.f;

        #pragma unroll 1
        for (int T = 0; T < 16; T++) {
            if (T < 15) cp_async_wait<1>(); else cp_async_wait<0>();
            __syncthreads();
            const float* tb = &sT[(T & 1) * 1632];
            #pragma unroll
            for (int lo = 0; lo < 8; lo++) {
                const int l = T * 8 + lo;
                const float p0 = sZP[rg * 132 + l];
                const float p1 = sZP[(rg + 4) * 132 + l];
                const float p2 = sZP[(rg + 8) * 132 + l];
                const float p3 = sZP[(rg + 12) * 132 + l];
                const float* row = &tb[lo * 204 + c];
                const float v0 = row[0], v1 = row[64], v2 = row[128];
                acc[0][0] = fmaf(p0, v0, acc[0][0]); acc[1][0] = fmaf(p1, v0, acc[1][0]);
                acc[2][0] = fmaf(p2, v0, acc[2][0]); acc[3][0] = fmaf(p3, v0, acc[3][0]);
                acc[0][1] = fmaf(p0, v1, acc[0][1]); acc[1][1] = fmaf(p1, v1, acc[1][1]);
                acc[2][1] = fmaf(p2, v1, acc[2][1]); acc[3][1] = fmaf(p3, v1, acc[3][1]);
                acc[0][2] = fmaf(p0, v2, acc[0][2]); acc[1][2] = fmaf(p1, v2, acc[1][2]);
                acc[2][2] = fmaf(p2, v2, acc[2][2]); acc[3][2] = fmaf(p3, v2, acc[3][2]);
                if (q3) {
                    const float v3 = row[192];
                    acc[0][3] = fmaf(p0, v3, acc[0][3]); acc[1][3] = fmaf(p1, v3, acc[1][3]);
                    acc[2][3] = fmaf(p2, v3, acc[2][3]); acc[3][3] = fmaf(p3, v3, acc[3][3]);
                }
            }
            __syncthreads();
            if (T < 14) issue(T + 2);
        }

        #pragma unroll
        for (int i = 0; i < 4; i++) {
            float* dst = g_att + (size_t)(b * L + r0g + rg + 4 * i) * D;
            dst[c]       = acc[i][0];
            dst[c + 64]  = acc[i][1];
            dst[c + 128] = acc[i][2];
            if (q3) dst[c + 192] = acc[i][3];
        }
    }
}

// ---------------------------------------------------------------------------
// Kernel 3b: build gating vectors G (full/att/maxatt) + the 3 cosine columns.
// grid (8, B), 256 threads; warp j handles rows 2j, 2j+1.
// ---------------------------------------------------------------------------
__global__ __launch_bounds__(256) void k_gbuild(
    const float* __restrict__ lt, const float* __restrict__ rt,
    const float* __restrict__ fw, const float* __restrict__ bw,
    float* __restrict__ out)
{
    __shared__ float sH[204];
    __shared__ int sPOS[16];

    const int tile = blockIdx.x, b = blockIdx.y;
    const int t = threadIdx.x;
    const int lane = t & 31, w = t >> 5;   // 8 warps
    const int r0g = tile * 16;

    if (t < 204) { sH[t] = (t < 100) ? fw[b * 100 + t]
                         : (t < 200) ? bw[b * 100 + t - 100] : 0.f; }
    if (t < 16) sPOS[t] = g_pos[b * L + r0g + t];
    __syncthreads();

    #pragma unroll 1
    for (int rr = 0; rr < 2; rr++) {
        const int j = 2 * w + rr;
        const int grow = b * L + r0g + j;
        const int pos = sPOS[j];
        const float* ltrow  = lt + (size_t)grow * D;
        const float* rtrow  = rt + (size_t)grow * D;
        const float* atrow  = g_att + (size_t)grow * D;
        const float* posrow = lt + (size_t)(b * L + pos) * D;

        float s0 = 0.f, s1 = 0.f, s2 = 0.f;
        #pragma unroll
        for (int c = 0; c < 7; c++) {
            const int d = lane + 32 * c;
            const bool ok = (c < 6) || (lane < 8);
            if (ok) {
                const float xl = ltrow[d];
                const float xh = sH[d];
                const float xa = atrow[d];
                const float xr = rtrow[d];
                const float xp = posrow[d];
                const float gf = xl * xh;
                const float ga = xa * xr;
                const float gm = xr * xp;
                g_G[(size_t)grow * 200 + d]                 = gf;
                g_G[(size_t)(8192 + grow) * 200 + d]        = ga;
                g_G[(size_t)(16384 + grow) * 200 + d]       = gm;
                s0 += gf; s1 += ga; s2 += gm;
            }
        }
        #pragma unroll
        for (int o = 16; o > 0; o >>= 1) {
            s0 += __shfl_xor_sync(0xffffffffu, s0, o);
            s1 += __shfl_xor_sync(0xffffffffu, s1, o);
            s2 += __shfl_xor_sync(0xffffffffu, s2, o);
        }
        if (lane == 0) {
            float* outrow = out + (size_t)grow * OUTC;
            outrow[0]  = tanhf(s0);
            outrow[41] = tanhf(s1);
            outrow[62] = tanhf(s2);
        }
    }
}

// ---------------------------------------------------------------------------
// Kernel 3c: weight GEMM — out[row, colbase+m] = tanh(G[type][row] . W[m]).
// grid (512, 3): 16 rows x 1 type per block; 320 threads = (row r, col m).
// FFMA2 dot over 100 float2 pairs; sG stride 206 -> conflict-free LDS.64.
// ---------------------------------------------------------------------------
#define WG_SMEM ((16 * 206 + 20 * 206) * 4)   // 29664 B
__global__ __launch_bounds__(320) void k_wgemm(
    const float* __restrict__ w_full, const float* __restrict__ w_att,
    const float* __restrict__ w_maxatt, float* __restrict__ out)
{
    extern __shared__ float sm[];
    float* sG = sm;              // [16][206]
    float* sW = sm + 16 * 206;   // [20][206]

    const int tile = blockIdx.x;   // 0..511
    const int type = blockIdx.y;   // 0..2
    const int t = threadIdx.x;
    const float* wsrc = (type == 0) ? w_full : (type == 1) ? w_att : w_maxatt;

    for (int idx = t; idx < 20 * 200; idx += 320) {
        const int m = idx / 200, d = idx - m * 200;
        sW[m * 206 + d] = wsrc[idx];
    }
    const float* gsrc = g_G + ((size_t)type * 8192 + tile * 16) * 200;
    for (int idx = t; idx < 16 * 200; idx += 320) {
        const int r = idx / 200, d = idx - r * 200;
        sG[r * 206 + d] = gsrc[idx];
    }
    __syncthreads();

    const int r = t & 15, c = t >> 4;   // c 0..19
    const float* gr_ = &sG[r * 206];
    const float* wr_ = &sW[c * 206];
    unsigned long long acc2 = 0ull;
    #pragma unroll 4
    for (int d = 0; d < 200; d += 2) {
        const unsigned long long gv = *(const unsigned long long*)&gr_[d];
        const unsigned long long wv = *(const unsigned long long*)&wr_[d];
        asm("fma.rn.f32x2 %0, %1, %2, %0;" : "+l"(acc2) : "l"(gv), "l"(wv));
    }
    float lo, hi;
    asm("mov.b64 {%0, %1}, %2;" : "=f"(lo), "=f"(hi) : "l"(acc2));
    const int row = tile * 16 + r;
    const int colbase = (type == 0) ? 1 : (type == 1) ? 42 : 63;
    out[(size_t)row * OUTC + colbase + c] = tanhf(lo + hi);
}

// ---------------------------------------------------------------------------
// Launch topology (graph-capturable; identical every call):
//   default (L): k_s -> [es] -> k_prep -> k_mp_mma            (cols 21..40)
//   s1      (S): k_proj -> k_att -> (wait es) -> k_gbuild -> k_wgemm
//                                                (cols 0..20, 41..82)
//   default waits e1 (end of S).
// ---------------------------------------------------------------------------
extern "C" void kernel_launch(void* const* d_in, const int* in_sizes, int n_in,
                              void* d_out, int out_size)
{
    const float* reps_lt   = (const float*)d_in[0];
    const float* reps_rt   = (const float*)d_in[1];
    const float* fw_h_rt   = (const float*)d_in[2];
    const float* bw_h_rt   = (const float*)d_in[3];
    const float* w_full    = (const float*)d_in[4];
    const float* w_maxpool = (const float*)d_in[5];
    const float* w_att     = (const float*)d_in[6];
    const float* w_maxatt  = (const float*)d_in[7];
    const float* attn_w1   = (const float*)d_in[8];
    const float* attn_w2   = (const float*)d_in[9];
    const float* diag_w    = (const float*)d_in[10];
    float* out = (float*)d_out;

    cudaFuncSetAttribute(k_mp_mma, cudaFuncAttributeMaxDynamicSharedMemorySize, MMA_SMEM_BYTES);
    cudaFuncSetAttribute(k_att, cudaFuncAttributeMaxDynamicSharedMemorySize, ATT_SMEM_BYTES);
    cudaFuncSetAttribute(k_wgemm, cudaFuncAttributeMaxDynamicSharedMemorySize, WG_SMEM);

    cudaStream_t s1;
    cudaEvent_t e0, es, e1;
    cudaStreamCreateWithFlags(&s1, cudaStreamNonBlocking);
    cudaEventCreateWithFlags(&e0, cudaEventDisableTiming);
    cudaEventCreateWithFlags(&es, cudaEventDisableTiming);
    cudaEventCreateWithFlags(&e1, cudaEventDisableTiming);

    cudaEventRecord(e0, 0);
    cudaStreamWaitEvent(s1, e0, 0);

    // S chain (part 1)
    dim3 g1(8, B);
    k_proj<<<g1, 128, 0, s1>>>(reps_lt, reps_rt, attn_w1, attn_w2, diag_w);
    dim3 g3(8, B);
    k_att<<<g3, 256, ATT_SMEM_BYTES, s1>>>(reps_lt);

    // L chain
    k_s<<<B, 256>>>(reps_rt, reps_lt);
    cudaEventRecord(es, 0);
    dim3 gp(8, B);
    k_prep<<<gp, 256>>>(reps_lt);
    dim3 g2(MP, B);
    k_mp_mma<<<g2, 256, MMA_SMEM_BYTES>>>(reps_rt, w_maxpool, out);

    // S chain (part 2)
    cudaStreamWaitEvent(s1, es, 0);
    dim3 g4(8, B);
    k_gbuild<<<g4, 256, 0, s1>>>(reps_lt, reps_rt, fw_h_rt, bw_h_rt, out);
    dim3 g5(512, 3);
    k_wgemm<<<g5, 320, WG_SMEM, s1>>>(w_full, w_att, w_maxatt, out);
    cudaEventRecord(e1, s1);

    cudaStreamWaitEvent(0, e1, 0);
}